// round 1
// baseline (speedup 1.0000x reference)
#include <cuda_runtime.h>
#include <math.h>

#define N_VID 36000
#define DM    512
#define NWIN  50
#define WS    720
#define SEQ   784
#define TXTL  64

// ---------------- scratch (static device allocations; no cudaMalloc) ----------------
__device__ float g_qkv_v[N_VID * 1536];        // vid QKV
__device__ float g_qkv_t[TXTL * 1536];         // txt QKV
__device__ float g_Qw[NWIN * SEQ * DM];        // windowed Q (rope applied)
__device__ float g_Kw[NWIN * SEQ * DM];
__device__ float g_Vw[NWIN * SEQ * DM];
__device__ float g_preproj[N_VID * DM];        // attn out, token order
__device__ float g_txtacc[TXTL * DM];          // txt attn out, summed over windows

__device__ __forceinline__ int token_of(int w, int p) {
    // window index w = iw*10 + ih*2 + it  (nt=2, nh=5, nw=5; wt=5, wh=9, ww=16)
    int it = w & 1;
    int ih = (w >> 1) % 5;
    int iw = w / 10;
    int tl = p / 144;          // p over (5,9,16)
    int rem = p % 144;
    int hl = rem >> 4;
    int wl = rem & 15;
    return ((it * 5 + tl) * 45 + (ih * 9 + hl)) * 80 + (iw * 16 + wl);
}

// ---------------- generic SGEMM: C[M,N] = alpha * A[M,K] @ B[K,N] ----------------
// 128x64 tile, BK=16, 256 threads, 8x4 per thread. K%16==0, N%64==0 required.
__global__ void __launch_bounds__(256) sgemm_kernel(
    const float* __restrict__ A, const float* __restrict__ B, float* __restrict__ C,
    int M, int N, int K, float alpha)
{
    __shared__ float sA[16][132];   // [k][m], padded
    __shared__ float sB[16][64];    // [k][n]

    int tid = threadIdx.x;
    int tx = tid & 15, ty = tid >> 4;
    int rowBase = blockIdx.y * 128;
    int colBase = blockIdx.x * 64;

    float acc[8][4];
#pragma unroll
    for (int i = 0; i < 8; ++i)
#pragma unroll
        for (int j = 0; j < 4; ++j) acc[i][j] = 0.f;

    for (int k0 = 0; k0 < K; k0 += 16) {
        // load A tile: 128 rows x 16 cols = 512 float4
#pragma unroll
        for (int t = 0; t < 2; ++t) {
            int i4 = tid + t * 256;
            int m = i4 >> 2, c4 = i4 & 3;
            int row = rowBase + m;
            float4 v = make_float4(0.f, 0.f, 0.f, 0.f);
            if (row < M) v = *reinterpret_cast<const float4*>(&A[(long)row * K + k0 + c4 * 4]);
            sA[c4 * 4 + 0][m] = v.x;
            sA[c4 * 4 + 1][m] = v.y;
            sA[c4 * 4 + 2][m] = v.z;
            sA[c4 * 4 + 3][m] = v.w;
        }
        // load B tile: 16 x 64 = 256 float4
        {
            int r = tid >> 4, c4 = tid & 15;
            float4 v = *reinterpret_cast<const float4*>(&B[(long)(k0 + r) * N + colBase + c4 * 4]);
            *reinterpret_cast<float4*>(&sB[r][c4 * 4]) = v;
        }
        __syncthreads();
#pragma unroll
        for (int kk = 0; kk < 16; ++kk) {
            float4 a0 = *reinterpret_cast<const float4*>(&sA[kk][ty * 8]);
            float4 a1 = *reinterpret_cast<const float4*>(&sA[kk][ty * 8 + 4]);
            float4 b  = *reinterpret_cast<const float4*>(&sB[kk][tx * 4]);
            float av[8] = {a0.x, a0.y, a0.z, a0.w, a1.x, a1.y, a1.z, a1.w};
            float bv[4] = {b.x, b.y, b.z, b.w};
#pragma unroll
            for (int i = 0; i < 8; ++i)
#pragma unroll
                for (int j = 0; j < 4; ++j) acc[i][j] += av[i] * bv[j];
        }
        __syncthreads();
    }
#pragma unroll
    for (int i = 0; i < 8; ++i) {
        int row = rowBase + ty * 8 + i;
        if (row >= M) continue;
        float4 o = make_float4(acc[i][0] * alpha, acc[i][1] * alpha,
                               acc[i][2] * alpha, acc[i][3] * alpha);
        *reinterpret_cast<float4*>(&C[(long)row * N + colBase + tx * 4]) = o;
    }
}

// ---------------- zero the txt accumulator ----------------
__global__ void zero_txt_kernel() {
    int i = blockIdx.x * 256 + threadIdx.x;
    if (i < TXTL * DM) g_txtacc[i] = 0.f;
}

// ---------------- window gather + 3D RoPE ----------------
// grid = NWIN*SEQ blocks; 256 threads: h = tid>>6, pair = tid&63
__global__ void __launch_bounds__(256) build_windows_kernel() {
    int wp = blockIdx.x;
    int tid = threadIdx.x;
    int h = tid >> 6, pr = tid & 63;
    int p = wp % SEQ, w = wp / SEQ;
    int d0 = pr * 2;
    long ob = ((long)wp * 4 + h) * 128 + d0;

    float q0, q1, k0, k1, v0, v1;
    if (p < WS) {
        int token = token_of(w, p);
        const float* base = &g_qkv_v[(long)token * 1536 + h * 128];
        q0 = base[d0];        q1 = base[d0 + 1];
        k0 = base[512 + d0];  k1 = base[512 + d0 + 1];
        v0 = base[1024 + d0]; v1 = base[1024 + d0 + 1];
        int tt = token / 3600;
        int hh = (token / 80) % 45;
        int ww2 = token % 80;
        float pos; int dl, da;
        if (d0 < 32)      { pos = (float)tt;  dl = d0;      da = 32; }
        else if (d0 < 80) { pos = (float)hh;  dl = d0 - 32; da = 48; }
        else              { pos = (float)ww2; dl = d0 - 80; da = 48; }
        float inv = powf(10000.0f, -((float)dl) / (float)da);
        float ang = pos * inv;
        float s, c;
        sincosf(ang, &s, &c);
        float nq0 = q0 * c - q1 * s, nq1 = q1 * c + q0 * s;
        float nk0 = k0 * c - k1 * s, nk1 = k1 * c + k0 * s;
        q0 = nq0; q1 = nq1; k0 = nk0; k1 = nk1;
    } else {
        const float* base = &g_qkv_t[(long)(p - WS) * 1536 + h * 128];
        q0 = base[d0];        q1 = base[d0 + 1];
        k0 = base[512 + d0];  k1 = base[512 + d0 + 1];
        v0 = base[1024 + d0]; v1 = base[1024 + d0 + 1];
    }
    g_Qw[ob] = q0; g_Qw[ob + 1] = q1;
    g_Kw[ob] = k0; g_Kw[ob + 1] = k1;
    g_Vw[ob] = v0; g_Vw[ob + 1] = v1;
}

// ---------------- fused flash attention per (qtile, head, window) ----------------
#define QT   64
#define KT   64
#define PADD 132
#define SPAD 68
#define ATTN_SMEM_FLOATS (QT * PADD + KT * PADD + QT * SPAD + 3 * QT)
#define ATTN_SMEM_BYTES  (ATTN_SMEM_FLOATS * 4)

__global__ void __launch_bounds__(256) attn_kernel() {
    extern __shared__ float sm[];
    float* sQ   = sm;                    // [QT][PADD]
    float* sKV  = sQ + QT * PADD;        // [KT][PADD]  (K in phase1, V in phase2)
    float* sS   = sKV + KT * PADD;       // [QT][SPAD]
    float* rowM = sS + QT * SPAD;        // [QT]
    float* rowL = rowM + QT;
    float* rowA = rowL + QT;

    const float NEGINF = __int_as_float(0xff800000);
    int qt = blockIdx.x, h = blockIdx.y, w = blockIdx.z;
    int tid = threadIdx.x, tx = tid & 15, ty = tid >> 4;

    // load Q tile (zero-fill past SEQ)
#pragma unroll
    for (int t = 0; t < 8; ++t) {
        int i4 = tid + t * 256;
        int r = i4 >> 5, d4 = i4 & 31;
        int qg = qt * QT + r;
        float4 v = make_float4(0.f, 0.f, 0.f, 0.f);
        if (qg < SEQ) v = *reinterpret_cast<const float4*>(
            &g_Qw[((long)(w * SEQ + qg) * 4 + h) * 128 + d4 * 4]);
        *reinterpret_cast<float4*>(&sQ[r * PADD + d4 * 4]) = v;
    }
    if (tid < QT) { rowM[tid] = NEGINF; rowL[tid] = 0.f; }

    float acc[4][8];
#pragma unroll
    for (int i = 0; i < 4; ++i)
#pragma unroll
        for (int j = 0; j < 8; ++j) acc[i][j] = 0.f;

    const float scale = 0.08838834764831843f;  // 1/sqrt(128)

    for (int kt = 0; kt < 13; ++kt) {
        __syncthreads();  // protect prev phase2's sKV reads (and Q store on iter 0)
        // load K tile
#pragma unroll
        for (int t = 0; t < 8; ++t) {
            int i4 = tid + t * 256;
            int r = i4 >> 5, d4 = i4 & 31;
            int kg = kt * KT + r;
            float4 v = make_float4(0.f, 0.f, 0.f, 0.f);
            if (kg < SEQ) v = *reinterpret_cast<const float4*>(
                &g_Kw[((long)(w * SEQ + kg) * 4 + h) * 128 + d4 * 4]);
            *reinterpret_cast<float4*>(&sKV[r * PADD + d4 * 4]) = v;
        }
        __syncthreads();

        // phase 1: S = Q @ K^T  (thread: rows ty*4+i, cols j*16+tx)
        float sacc[4][4];
#pragma unroll
        for (int i = 0; i < 4; ++i)
#pragma unroll
            for (int j = 0; j < 4; ++j) sacc[i][j] = 0.f;
#pragma unroll 4
        for (int d4 = 0; d4 < 32; ++d4) {
            float4 qv[4], kv[4];
#pragma unroll
            for (int i = 0; i < 4; ++i)
                qv[i] = *reinterpret_cast<const float4*>(&sQ[(ty * 4 + i) * PADD + d4 * 4]);
#pragma unroll
            for (int j = 0; j < 4; ++j)
                kv[j] = *reinterpret_cast<const float4*>(&sKV[(j * 16 + tx) * PADD + d4 * 4]);
#pragma unroll
            for (int i = 0; i < 4; ++i)
#pragma unroll
                for (int j = 0; j < 4; ++j)
                    sacc[i][j] += qv[i].x * kv[j].x + qv[i].y * kv[j].y +
                                  qv[i].z * kv[j].z + qv[i].w * kv[j].w;
        }
#pragma unroll
        for (int i = 0; i < 4; ++i)
#pragma unroll
            for (int j = 0; j < 4; ++j) {
                int kg = kt * KT + j * 16 + tx;
                sS[(ty * 4 + i) * SPAD + j * 16 + tx] =
                    (kg < SEQ) ? sacc[i][j] * scale : NEGINF;
            }
        __syncthreads();

        // load V tile (into sKV) + online-softmax stats, same region
#pragma unroll
        for (int t = 0; t < 8; ++t) {
            int i4 = tid + t * 256;
            int r = i4 >> 5, d4 = i4 & 31;
            int kg = kt * KT + r;
            float4 v = make_float4(0.f, 0.f, 0.f, 0.f);
            if (kg < SEQ) v = *reinterpret_cast<const float4*>(
                &g_Vw[((long)(w * SEQ + kg) * 4 + h) * 128 + d4 * 4]);
            *reinterpret_cast<float4*>(&sKV[r * PADD + d4 * 4]) = v;
        }
        {
            int r = tid >> 2, l4 = tid & 3;
            float* row = &sS[r * SPAD + l4 * 16];
            float ml = NEGINF;
#pragma unroll
            for (int s2 = 0; s2 < 16; ++s2) ml = fmaxf(ml, row[s2]);
            ml = fmaxf(ml, __shfl_xor_sync(0xffffffffu, ml, 1));
            ml = fmaxf(ml, __shfl_xor_sync(0xffffffffu, ml, 2));
            float mOld = rowM[r];
            float mNew = fmaxf(mOld, ml);
            float sum = 0.f;
#pragma unroll
            for (int s2 = 0; s2 < 16; ++s2) {
                float pv = __expf(row[s2] - mNew);
                row[s2] = pv;
                sum += pv;
            }
            sum += __shfl_xor_sync(0xffffffffu, sum, 1);
            sum += __shfl_xor_sync(0xffffffffu, sum, 2);
            if (l4 == 0) {
                float a = __expf(mOld - mNew);
                rowA[r] = a;
                rowL[r] = rowL[r] * a + sum;
                rowM[r] = mNew;
            }
        }
        __syncthreads();

        // phase 2: O = O*alpha + P @ V  (thread: rows ty*4+i, dims tx*8+j)
#pragma unroll
        for (int i = 0; i < 4; ++i) {
            float a = rowA[ty * 4 + i];
#pragma unroll
            for (int j = 0; j < 8; ++j) acc[i][j] *= a;
        }
#pragma unroll 2
        for (int kk = 0; kk < KT; ++kk) {
            float4 v0 = *reinterpret_cast<const float4*>(&sKV[kk * PADD + tx * 8]);
            float4 v1 = *reinterpret_cast<const float4*>(&sKV[kk * PADD + tx * 8 + 4]);
#pragma unroll
            for (int i = 0; i < 4; ++i) {
                float pv = sS[(ty * 4 + i) * SPAD + kk];
                acc[i][0] += pv * v0.x; acc[i][1] += pv * v0.y;
                acc[i][2] += pv * v0.z; acc[i][3] += pv * v0.w;
                acc[i][4] += pv * v1.x; acc[i][5] += pv * v1.y;
                acc[i][6] += pv * v1.z; acc[i][7] += pv * v1.w;
            }
        }
    }

    // epilogue: normalize, scatter vid rows to token order, atomic-accumulate txt rows
#pragma unroll
    for (int i = 0; i < 4; ++i) {
        int ql = ty * 4 + i;
        int qg = qt * QT + ql;
        if (qg >= SEQ) continue;
        float inv = 1.f / rowL[ql];
        if (qg < WS) {
            int token = token_of(w, qg);
            float* dst = &g_preproj[(long)token * DM + h * 128 + tx * 8];
            float4 o0 = make_float4(acc[i][0] * inv, acc[i][1] * inv,
                                    acc[i][2] * inv, acc[i][3] * inv);
            float4 o1 = make_float4(acc[i][4] * inv, acc[i][5] * inv,
                                    acc[i][6] * inv, acc[i][7] * inv);
            *reinterpret_cast<float4*>(dst) = o0;
            *reinterpret_cast<float4*>(dst + 4) = o1;
        } else {
            int tr = qg - WS;
            float* dst = &g_txtacc[(long)tr * DM + h * 128 + tx * 8];
#pragma unroll
            for (int j = 0; j < 8; ++j) atomicAdd(&dst[j], acc[i][j] * inv);
        }
    }
}

// ---------------- launch ----------------
extern "C" void kernel_launch(void* const* d_in, const int* in_sizes, int n_in,
                              void* d_out, int out_size) {
    const float* vid       = (const float*)d_in[0];
    const float* txt       = (const float*)d_in[1];
    const float* w_qkv_vid = (const float*)d_in[2];
    const float* w_qkv_txt = (const float*)d_in[3];
    const float* w_out_vid = (const float*)d_in[4];
    const float* w_out_txt = (const float*)d_in[5];
    float* out = (float*)d_out;

    cudaFuncSetAttribute(attn_kernel, cudaFuncAttributeMaxDynamicSharedMemorySize,
                         ATTN_SMEM_BYTES);

    float *p_qkv_v, *p_qkv_t, *p_pre, *p_txt;
    cudaGetSymbolAddress((void**)&p_qkv_v, g_qkv_v);
    cudaGetSymbolAddress((void**)&p_qkv_t, g_qkv_t);
    cudaGetSymbolAddress((void**)&p_pre,   g_preproj);
    cudaGetSymbolAddress((void**)&p_txt,   g_txtacc);

    zero_txt_kernel<<<(TXTL * DM + 255) / 256, 256>>>();

    // QKV projections
    sgemm_kernel<<<dim3(1536 / 64, (N_VID + 127) / 128), 256>>>(
        vid, w_qkv_vid, p_qkv_v, N_VID, 1536, DM, 1.f);
    sgemm_kernel<<<dim3(1536 / 64, 1), 256>>>(
        txt, w_qkv_txt, p_qkv_t, TXTL, 1536, DM, 1.f);

    // window gather + rope
    build_windows_kernel<<<NWIN * SEQ, 256>>>();

    // attention
    attn_kernel<<<dim3(13, 4, NWIN), 256, ATTN_SMEM_BYTES>>>();

    // output projections (txt mean over 50 windows folded into alpha)
    sgemm_kernel<<<dim3(DM / 64, (N_VID + 127) / 128), 256>>>(
        p_pre, w_out_vid, out, N_VID, DM, DM, 1.f);
    sgemm_kernel<<<dim3(DM / 64, 1), 256>>>(
        p_txt, w_out_txt, out + (long)N_VID * DM, TXTL, DM, DM, 1.f / 50.f);
}

// round 2
// speedup vs baseline: 1.3444x; 1.3444x over previous
#include <cuda_runtime.h>
#include <math.h>

#define N_VID 36000
#define DM    512
#define NWIN  50
#define WS    720
#define SEQ   784
#define TXTL  64

// ---------------- scratch (static device allocations; no cudaMalloc) ----------------
__device__ float g_qkv_v[N_VID * 1536];        // vid QKV
__device__ float g_qkv_t[TXTL * 1536];         // txt QKV
__device__ float g_Qw[NWIN * SEQ * DM];        // windowed Q (rope applied)
__device__ float g_Kw[NWIN * SEQ * DM];
__device__ float g_Vw[NWIN * SEQ * DM];
__device__ float g_preproj[N_VID * DM];        // attn out, token order
__device__ float g_txtacc[TXTL * DM];          // txt attn out, summed over windows

__device__ __forceinline__ int token_of(int w, int p) {
    // window index w = iw*10 + ih*2 + it  (nt=2, nh=5, nw=5; wt=5, wh=9, ww=16)
    int it = w & 1;
    int ih = (w >> 1) % 5;
    int iw = w / 10;
    int tl = p / 144;          // p over (5,9,16)
    int rem = p % 144;
    int hl = rem >> 4;
    int wl = rem & 15;
    return ((it * 5 + tl) * 45 + (ih * 9 + hl)) * 80 + (iw * 16 + wl);
}

__device__ __forceinline__ float to_tf32(float x) {
    float r;
    asm("cvt.rna.tf32.f32 %0, %1;" : "=f"(r) : "f"(x));
    return r;
}

// ---------------- tf32 tensor-core GEMM: C[M,N] = alpha * A[M,K] @ B[K,N] ----------------
// CTA tile 128x128x32, 256 threads (8 warps of 64x32), mma.sync.m16n8k8 tf32.
// Requires N%128==0, K%32==0. M guarded.
#define SA_STRIDE 36    // 32 + 4 pad
#define SB_STRIDE 136   // 128 + 8 pad
__global__ void __launch_bounds__(256) tf32_gemm_kernel(
    const float* __restrict__ A, const float* __restrict__ B, float* __restrict__ C,
    int M, int N, int K, float alpha)
{
    __shared__ float sA[128 * SA_STRIDE];
    __shared__ float sB[32 * SB_STRIDE];

    const int tid  = threadIdx.x;
    const int warp = tid >> 5, lane = tid & 31;
    const int g = lane >> 2, tig = lane & 3;
    const int wm = (warp & 1) * 64;        // warp row offset in tile
    const int wn = (warp >> 1) * 32;       // warp col offset in tile
    const int rowBase = blockIdx.y * 128;
    const int colBase = blockIdx.x * 128;

    float c[4][4][4];
#pragma unroll
    for (int mt = 0; mt < 4; ++mt)
#pragma unroll
        for (int nt = 0; nt < 4; ++nt)
#pragma unroll
            for (int i = 0; i < 4; ++i) c[mt][nt][i] = 0.f;

    // per-thread global load coords
    const int arow = tid >> 1;              // A: idx = tid + i*256 -> row=idx>>3 wait: computed per i below
    (void)arow;

    float4 pa[4], pb[4];

    // prologue: load tile 0 into regs
#pragma unroll
    for (int i = 0; i < 4; ++i) {
        int idx = tid + i * 256;
        int r = idx >> 3, c4 = idx & 7;
        int grow = rowBase + r;
        pa[i] = (grow < M) ? *reinterpret_cast<const float4*>(&A[(long)grow * K + c4 * 4])
                           : make_float4(0.f, 0.f, 0.f, 0.f);
        int rb = idx >> 5, cb4 = idx & 31;
        pb[i] = *reinterpret_cast<const float4*>(&B[(long)rb * N + colBase + cb4 * 4]);
    }

    const int nIter = K / 32;
    for (int it = 0; it < nIter; ++it) {
        // store prefetched tile to smem (with tf32 rounding)
#pragma unroll
        for (int i = 0; i < 4; ++i) {
            int idx = tid + i * 256;
            int r = idx >> 3, c4 = idx & 7;
            float* d = &sA[r * SA_STRIDE + c4 * 4];
            d[0] = to_tf32(pa[i].x); d[1] = to_tf32(pa[i].y);
            d[2] = to_tf32(pa[i].z); d[3] = to_tf32(pa[i].w);
            int rb = idx >> 5, cb4 = idx & 31;
            float* db = &sB[rb * SB_STRIDE + cb4 * 4];
            db[0] = to_tf32(pb[i].x); db[1] = to_tf32(pb[i].y);
            db[2] = to_tf32(pb[i].z); db[3] = to_tf32(pb[i].w);
        }
        __syncthreads();

        // prefetch next tile
        if (it + 1 < nIter) {
            int k0 = (it + 1) * 32;
#pragma unroll
            for (int i = 0; i < 4; ++i) {
                int idx = tid + i * 256;
                int r = idx >> 3, c4 = idx & 7;
                int grow = rowBase + r;
                pa[i] = (grow < M) ? *reinterpret_cast<const float4*>(&A[(long)grow * K + k0 + c4 * 4])
                                   : make_float4(0.f, 0.f, 0.f, 0.f);
                int rb = idx >> 5, cb4 = idx & 31;
                pb[i] = *reinterpret_cast<const float4*>(&B[(long)(k0 + rb) * N + colBase + cb4 * 4]);
            }
        }

        // compute: 4 k-steps of 8
#pragma unroll
        for (int kk = 0; kk < 4; ++kk) {
            unsigned int af[4][4], bf[4][2];
#pragma unroll
            for (int mt = 0; mt < 4; ++mt) {
                int r0 = wm + mt * 16 + g;
                af[mt][0] = __float_as_uint(sA[r0 * SA_STRIDE + kk * 8 + tig]);
                af[mt][1] = __float_as_uint(sA[(r0 + 8) * SA_STRIDE + kk * 8 + tig]);
                af[mt][2] = __float_as_uint(sA[r0 * SA_STRIDE + kk * 8 + tig + 4]);
                af[mt][3] = __float_as_uint(sA[(r0 + 8) * SA_STRIDE + kk * 8 + tig + 4]);
            }
#pragma unroll
            for (int nt = 0; nt < 4; ++nt) {
                int cn = wn + nt * 8 + g;
                bf[nt][0] = __float_as_uint(sB[(kk * 8 + tig) * SB_STRIDE + cn]);
                bf[nt][1] = __float_as_uint(sB[(kk * 8 + tig + 4) * SB_STRIDE + cn]);
            }
#pragma unroll
            for (int mt = 0; mt < 4; ++mt)
#pragma unroll
                for (int nt = 0; nt < 4; ++nt) {
                    asm volatile(
                        "mma.sync.aligned.m16n8k8.row.col.f32.tf32.tf32.f32 "
                        "{%0,%1,%2,%3}, {%4,%5,%6,%7}, {%8,%9}, {%0,%1,%2,%3};"
                        : "+f"(c[mt][nt][0]), "+f"(c[mt][nt][1]),
                          "+f"(c[mt][nt][2]), "+f"(c[mt][nt][3])
                        : "r"(af[mt][0]), "r"(af[mt][1]), "r"(af[mt][2]), "r"(af[mt][3]),
                          "r"(bf[nt][0]), "r"(bf[nt][1]));
                }
        }
        __syncthreads();
    }

    // epilogue
#pragma unroll
    for (int mt = 0; mt < 4; ++mt) {
#pragma unroll
        for (int nt = 0; nt < 4; ++nt) {
            int row0 = rowBase + wm + mt * 16 + g;
            int col = colBase + wn + nt * 8 + 2 * tig;
            if (row0 < M) {
                float2 o = make_float2(c[mt][nt][0] * alpha, c[mt][nt][1] * alpha);
                *reinterpret_cast<float2*>(&C[(long)row0 * N + col]) = o;
            }
            int row1 = row0 + 8;
            if (row1 < M) {
                float2 o = make_float2(c[mt][nt][2] * alpha, c[mt][nt][3] * alpha);
                *reinterpret_cast<float2*>(&C[(long)row1 * N + col]) = o;
            }
        }
    }
}

// ---------------- zero the txt accumulator ----------------
__global__ void zero_txt_kernel() {
    int i = blockIdx.x * 256 + threadIdx.x;
    if (i < TXTL * DM) g_txtacc[i] = 0.f;
}

// ---------------- window gather + 3D RoPE ----------------
// grid = NWIN*SEQ blocks; 256 threads: h = tid>>6, pair = tid&63
__global__ void __launch_bounds__(256) build_windows_kernel() {
    int wp = blockIdx.x;
    int tid = threadIdx.x;
    int h = tid >> 6, pr = tid & 63;
    int p = wp % SEQ, w = wp / SEQ;
    int d0 = pr * 2;
    long ob = ((long)wp * 4 + h) * 128 + d0;

    float q0, q1, k0, k1, v0, v1;
    if (p < WS) {
        int token = token_of(w, p);
        const float* base = &g_qkv_v[(long)token * 1536 + h * 128];
        q0 = base[d0];        q1 = base[d0 + 1];
        k0 = base[512 + d0];  k1 = base[512 + d0 + 1];
        v0 = base[1024 + d0]; v1 = base[1024 + d0 + 1];
        int tt = token / 3600;
        int hh = (token / 80) % 45;
        int ww2 = token % 80;
        float pos; int dl, da;
        if (d0 < 32)      { pos = (float)tt;  dl = d0;      da = 32; }
        else if (d0 < 80) { pos = (float)hh;  dl = d0 - 32; da = 48; }
        else              { pos = (float)ww2; dl = d0 - 80; da = 48; }
        float inv = powf(10000.0f, -((float)dl) / (float)da);
        float ang = pos * inv;
        float s, c;
        sincosf(ang, &s, &c);
        float nq0 = q0 * c - q1 * s, nq1 = q1 * c + q0 * s;
        float nk0 = k0 * c - k1 * s, nk1 = k1 * c + k0 * s;
        q0 = nq0; q1 = nq1; k0 = nk0; k1 = nk1;
    } else {
        const float* base = &g_qkv_t[(long)(p - WS) * 1536 + h * 128];
        q0 = base[d0];        q1 = base[d0 + 1];
        k0 = base[512 + d0];  k1 = base[512 + d0 + 1];
        v0 = base[1024 + d0]; v1 = base[1024 + d0 + 1];
    }
    g_Qw[ob] = q0; g_Qw[ob + 1] = q1;
    g_Kw[ob] = k0; g_Kw[ob + 1] = k1;
    g_Vw[ob] = v0; g_Vw[ob + 1] = v1;
}

// ---------------- fused flash attention per (qtile, head, window) ----------------
#define QT   64
#define KT   64
#define PADD 132
#define SPAD 68
#define ATTN_SMEM_FLOATS (QT * PADD + KT * PADD + QT * SPAD + 3 * QT)
#define ATTN_SMEM_BYTES  (ATTN_SMEM_FLOATS * 4)

__global__ void __launch_bounds__(256) attn_kernel() {
    extern __shared__ float sm[];
    float* sQ   = sm;                    // [QT][PADD]
    float* sKV  = sQ + QT * PADD;        // [KT][PADD]  (K in phase1, V in phase2)
    float* sS   = sKV + KT * PADD;       // [QT][SPAD]
    float* rowM = sS + QT * SPAD;        // [QT]
    float* rowL = rowM + QT;
    float* rowA = rowL + QT;

    const float NEGINF = __int_as_float(0xff800000);
    int qt = blockIdx.x, h = blockIdx.y, w = blockIdx.z;
    int tid = threadIdx.x, tx = tid & 15, ty = tid >> 4;

    // load Q tile (zero-fill past SEQ)
#pragma unroll
    for (int t = 0; t < 8; ++t) {
        int i4 = tid + t * 256;
        int r = i4 >> 5, d4 = i4 & 31;
        int qg = qt * QT + r;
        float4 v = make_float4(0.f, 0.f, 0.f, 0.f);
        if (qg < SEQ) v = *reinterpret_cast<const float4*>(
            &g_Qw[((long)(w * SEQ + qg) * 4 + h) * 128 + d4 * 4]);
        *reinterpret_cast<float4*>(&sQ[r * PADD + d4 * 4]) = v;
    }
    if (tid < QT) { rowM[tid] = NEGINF; rowL[tid] = 0.f; }

    float acc[4][8];
#pragma unroll
    for (int i = 0; i < 4; ++i)
#pragma unroll
        for (int j = 0; j < 8; ++j) acc[i][j] = 0.f;

    const float scale = 0.08838834764831843f;  // 1/sqrt(128)

    for (int kt = 0; kt < 13; ++kt) {
        __syncthreads();  // protect prev phase2's sKV reads (and Q store on iter 0)
        // load K tile
#pragma unroll
        for (int t = 0; t < 8; ++t) {
            int i4 = tid + t * 256;
            int r = i4 >> 5, d4 = i4 & 31;
            int kg = kt * KT + r;
            float4 v = make_float4(0.f, 0.f, 0.f, 0.f);
            if (kg < SEQ) v = *reinterpret_cast<const float4*>(
                &g_Kw[((long)(w * SEQ + kg) * 4 + h) * 128 + d4 * 4]);
            *reinterpret_cast<float4*>(&sKV[r * PADD + d4 * 4]) = v;
        }
        __syncthreads();

        // phase 1: S = Q @ K^T  (thread: rows ty*4+i, cols j*16+tx)
        float sacc[4][4];
#pragma unroll
        for (int i = 0; i < 4; ++i)
#pragma unroll
            for (int j = 0; j < 4; ++j) sacc[i][j] = 0.f;
#pragma unroll 4
        for (int d4 = 0; d4 < 32; ++d4) {
            float4 qv[4], kv[4];
#pragma unroll
            for (int i = 0; i < 4; ++i)
                qv[i] = *reinterpret_cast<const float4*>(&sQ[(ty * 4 + i) * PADD + d4 * 4]);
#pragma unroll
            for (int j = 0; j < 4; ++j)
                kv[j] = *reinterpret_cast<const float4*>(&sKV[(j * 16 + tx) * PADD + d4 * 4]);
#pragma unroll
            for (int i = 0; i < 4; ++i)
#pragma unroll
                for (int j = 0; j < 4; ++j)
                    sacc[i][j] += qv[i].x * kv[j].x + qv[i].y * kv[j].y +
                                  qv[i].z * kv[j].z + qv[i].w * kv[j].w;
        }
#pragma unroll
        for (int i = 0; i < 4; ++i)
#pragma unroll
            for (int j = 0; j < 4; ++j) {
                int kg = kt * KT + j * 16 + tx;
                sS[(ty * 4 + i) * SPAD + j * 16 + tx] =
                    (kg < SEQ) ? sacc[i][j] * scale : NEGINF;
            }
        __syncthreads();

        // load V tile (into sKV) + online-softmax stats, same region
#pragma unroll
        for (int t = 0; t < 8; ++t) {
            int i4 = tid + t * 256;
            int r = i4 >> 5, d4 = i4 & 31;
            int kg = kt * KT + r;
            float4 v = make_float4(0.f, 0.f, 0.f, 0.f);
            if (kg < SEQ) v = *reinterpret_cast<const float4*>(
                &g_Vw[((long)(w * SEQ + kg) * 4 + h) * 128 + d4 * 4]);
            *reinterpret_cast<float4*>(&sKV[r * PADD + d4 * 4]) = v;
        }
        {
            int r = tid >> 2, l4 = tid & 3;
            float* row = &sS[r * SPAD + l4 * 16];
            float ml = NEGINF;
#pragma unroll
            for (int s2 = 0; s2 < 16; ++s2) ml = fmaxf(ml, row[s2]);
            ml = fmaxf(ml, __shfl_xor_sync(0xffffffffu, ml, 1));
            ml = fmaxf(ml, __shfl_xor_sync(0xffffffffu, ml, 2));
            float mOld = rowM[r];
            float mNew = fmaxf(mOld, ml);
            float sum = 0.f;
#pragma unroll
            for (int s2 = 0; s2 < 16; ++s2) {
                float pv = __expf(row[s2] - mNew);
                row[s2] = pv;
                sum += pv;
            }
            sum += __shfl_xor_sync(0xffffffffu, sum, 1);
            sum += __shfl_xor_sync(0xffffffffu, sum, 2);
            if (l4 == 0) {
                float a = __expf(mOld - mNew);
                rowA[r] = a;
                rowL[r] = rowL[r] * a + sum;
                rowM[r] = mNew;
            }
        }
        __syncthreads();

        // phase 2: O = O*alpha + P @ V  (thread: rows ty*4+i, dims tx*8+j)
#pragma unroll
        for (int i = 0; i < 4; ++i) {
            float a = rowA[ty * 4 + i];
#pragma unroll
            for (int j = 0; j < 8; ++j) acc[i][j] *= a;
        }
#pragma unroll 2
        for (int kk = 0; kk < KT; ++kk) {
            float4 v0 = *reinterpret_cast<const float4*>(&sKV[kk * PADD + tx * 8]);
            float4 v1 = *reinterpret_cast<const float4*>(&sKV[kk * PADD + tx * 8 + 4]);
#pragma unroll
            for (int i = 0; i < 4; ++i) {
                float pv = sS[(ty * 4 + i) * SPAD + kk];
                acc[i][0] += pv * v0.x; acc[i][1] += pv * v0.y;
                acc[i][2] += pv * v0.z; acc[i][3] += pv * v0.w;
                acc[i][4] += pv * v1.x; acc[i][5] += pv * v1.y;
                acc[i][6] += pv * v1.z; acc[i][7] += pv * v1.w;
            }
        }
    }

    // epilogue: normalize, scatter vid rows to token order, atomic-accumulate txt rows
#pragma unroll
    for (int i = 0; i < 4; ++i) {
        int ql = ty * 4 + i;
        int qg = qt * QT + ql;
        if (qg >= SEQ) continue;
        float inv = 1.f / rowL[ql];
        if (qg < WS) {
            int token = token_of(w, qg);
            float* dst = &g_preproj[(long)token * DM + h * 128 + tx * 8];
            float4 o0 = make_float4(acc[i][0] * inv, acc[i][1] * inv,
                                    acc[i][2] * inv, acc[i][3] * inv);
            float4 o1 = make_float4(acc[i][4] * inv, acc[i][5] * inv,
                                    acc[i][6] * inv, acc[i][7] * inv);
            *reinterpret_cast<float4*>(dst) = o0;
            *reinterpret_cast<float4*>(dst + 4) = o1;
        } else {
            int tr = qg - WS;
            float* dst = &g_txtacc[(long)tr * DM + h * 128 + tx * 8];
#pragma unroll
            for (int j = 0; j < 8; ++j) atomicAdd(&dst[j], acc[i][j] * inv);
        }
    }
}

// ---------------- launch ----------------
extern "C" void kernel_launch(void* const* d_in, const int* in_sizes, int n_in,
                              void* d_out, int out_size) {
    const float* vid       = (const float*)d_in[0];
    const float* txt       = (const float*)d_in[1];
    const float* w_qkv_vid = (const float*)d_in[2];
    const float* w_qkv_txt = (const float*)d_in[3];
    const float* w_out_vid = (const float*)d_in[4];
    const float* w_out_txt = (const float*)d_in[5];
    float* out = (float*)d_out;

    cudaFuncSetAttribute(attn_kernel, cudaFuncAttributeMaxDynamicSharedMemorySize,
                         ATTN_SMEM_BYTES);

    float *p_qkv_v, *p_qkv_t, *p_pre, *p_txt;
    cudaGetSymbolAddress((void**)&p_qkv_v, g_qkv_v);
    cudaGetSymbolAddress((void**)&p_qkv_t, g_qkv_t);
    cudaGetSymbolAddress((void**)&p_pre,   g_preproj);
    cudaGetSymbolAddress((void**)&p_txt,   g_txtacc);

    zero_txt_kernel<<<(TXTL * DM + 255) / 256, 256>>>();

    // QKV projections (tf32 tensor cores)
    tf32_gemm_kernel<<<dim3(1536 / 128, (N_VID + 127) / 128), 256>>>(
        vid, w_qkv_vid, p_qkv_v, N_VID, 1536, DM, 1.f);
    tf32_gemm_kernel<<<dim3(1536 / 128, 1), 256>>>(
        txt, w_qkv_txt, p_qkv_t, TXTL, 1536, DM, 1.f);

    // window gather + rope
    build_windows_kernel<<<NWIN * SEQ, 256>>>();

    // attention
    attn_kernel<<<dim3(13, 4, NWIN), 256, ATTN_SMEM_BYTES>>>();

    // output projections (txt mean over 50 windows folded into alpha)
    tf32_gemm_kernel<<<dim3(DM / 128, (N_VID + 127) / 128), 256>>>(
        p_pre, w_out_vid, out, N_VID, DM, DM, 1.f);
    tf32_gemm_kernel<<<dim3(DM / 128, 1), 256>>>(
        p_txt, w_out_txt, out + (long)N_VID * DM, TXTL, DM, DM, 1.f / 50.f);
}

// round 3
// speedup vs baseline: 2.2490x; 1.6728x over previous
#include <cuda_runtime.h>
#include <math.h>

#define N_VID 36000
#define DM    512
#define NWIN  50
#define WS    720
#define SEQ   784
#define TXTL  64

// ---------------- scratch (static device allocations; no cudaMalloc) ----------------
__device__ float g_qkv_v[N_VID * 1536];        // vid QKV
__device__ float g_qkv_t[TXTL * 1536];         // txt QKV
__device__ float g_Qw[NWIN * SEQ * DM];        // windowed Q (rope applied, tf32-rounded)
__device__ float g_Kw[NWIN * SEQ * DM];        // tf32-rounded
__device__ float g_Vw[NWIN * SEQ * DM];        // full fp32
__device__ float g_preproj[N_VID * DM];        // attn out, token order
__device__ float g_txtacc[TXTL * DM];          // txt attn out, summed over windows

__device__ __forceinline__ int token_of(int w, int p) {
    int it = w & 1;
    int ih = (w >> 1) % 5;
    int iw = w / 10;
    int tl = p / 144;
    int rem = p % 144;
    int hl = rem >> 4;
    int wl = rem & 15;
    return ((it * 5 + tl) * 45 + (ih * 9 + hl)) * 80 + (iw * 16 + wl);
}

__device__ __forceinline__ float to_tf32(float x) {
    float r;
    asm("cvt.rna.tf32.f32 %0, %1;" : "=f"(r) : "f"(x));
    return r;
}

__device__ __forceinline__ void mma_tf32(float* c, unsigned a0, unsigned a1,
                                         unsigned a2, unsigned a3,
                                         unsigned b0, unsigned b1) {
    asm volatile(
        "mma.sync.aligned.m16n8k8.row.col.f32.tf32.tf32.f32 "
        "{%0,%1,%2,%3}, {%4,%5,%6,%7}, {%8,%9}, {%0,%1,%2,%3};"
        : "+f"(c[0]), "+f"(c[1]), "+f"(c[2]), "+f"(c[3])
        : "r"(a0), "r"(a1), "r"(a2), "r"(a3), "r"(b0), "r"(b1));
}

// ---------------- tf32 tensor-core GEMM: C[M,N] = alpha * A[M,K] @ B[K,N] ----------------
#define SA_STRIDE 36
#define SB_STRIDE 136
__global__ void __launch_bounds__(256) tf32_gemm_kernel(
    const float* __restrict__ A, const float* __restrict__ B, float* __restrict__ C,
    int M, int N, int K, float alpha)
{
    __shared__ float sA[128 * SA_STRIDE];
    __shared__ float sB[32 * SB_STRIDE];

    const int tid  = threadIdx.x;
    const int warp = tid >> 5, lane = tid & 31;
    const int g = lane >> 2, tig = lane & 3;
    const int wm = (warp & 1) * 64;
    const int wn = (warp >> 1) * 32;
    const int rowBase = blockIdx.y * 128;
    const int colBase = blockIdx.x * 128;

    float c[4][4][4];
#pragma unroll
    for (int mt = 0; mt < 4; ++mt)
#pragma unroll
        for (int nt = 0; nt < 4; ++nt)
#pragma unroll
            for (int i = 0; i < 4; ++i) c[mt][nt][i] = 0.f;

    float4 pa[4], pb[4];
#pragma unroll
    for (int i = 0; i < 4; ++i) {
        int idx = tid + i * 256;
        int r = idx >> 3, c4 = idx & 7;
        int grow = rowBase + r;
        pa[i] = (grow < M) ? *reinterpret_cast<const float4*>(&A[(long)grow * K + c4 * 4])
                           : make_float4(0.f, 0.f, 0.f, 0.f);
        int rb = idx >> 5, cb4 = idx & 31;
        pb[i] = *reinterpret_cast<const float4*>(&B[(long)rb * N + colBase + cb4 * 4]);
    }

    const int nIter = K / 32;
    for (int it = 0; it < nIter; ++it) {
#pragma unroll
        for (int i = 0; i < 4; ++i) {
            int idx = tid + i * 256;
            int r = idx >> 3, c4 = idx & 7;
            float* d = &sA[r * SA_STRIDE + c4 * 4];
            d[0] = to_tf32(pa[i].x); d[1] = to_tf32(pa[i].y);
            d[2] = to_tf32(pa[i].z); d[3] = to_tf32(pa[i].w);
            int rb = idx >> 5, cb4 = idx & 31;
            float* db = &sB[rb * SB_STRIDE + cb4 * 4];
            db[0] = to_tf32(pb[i].x); db[1] = to_tf32(pb[i].y);
            db[2] = to_tf32(pb[i].z); db[3] = to_tf32(pb[i].w);
        }
        __syncthreads();

        if (it + 1 < nIter) {
            int k0 = (it + 1) * 32;
#pragma unroll
            for (int i = 0; i < 4; ++i) {
                int idx = tid + i * 256;
                int r = idx >> 3, c4 = idx & 7;
                int grow = rowBase + r;
                pa[i] = (grow < M) ? *reinterpret_cast<const float4*>(&A[(long)grow * K + k0 + c4 * 4])
                                   : make_float4(0.f, 0.f, 0.f, 0.f);
                int rb = idx >> 5, cb4 = idx & 31;
                pb[i] = *reinterpret_cast<const float4*>(&B[(long)(k0 + rb) * N + colBase + cb4 * 4]);
            }
        }

#pragma unroll
        for (int kk = 0; kk < 4; ++kk) {
            unsigned int af[4][4], bf[4][2];
#pragma unroll
            for (int mt = 0; mt < 4; ++mt) {
                int r0 = wm + mt * 16 + g;
                af[mt][0] = __float_as_uint(sA[r0 * SA_STRIDE + kk * 8 + tig]);
                af[mt][1] = __float_as_uint(sA[(r0 + 8) * SA_STRIDE + kk * 8 + tig]);
                af[mt][2] = __float_as_uint(sA[r0 * SA_STRIDE + kk * 8 + tig + 4]);
                af[mt][3] = __float_as_uint(sA[(r0 + 8) * SA_STRIDE + kk * 8 + tig + 4]);
            }
#pragma unroll
            for (int nt = 0; nt < 4; ++nt) {
                int cn = wn + nt * 8 + g;
                bf[nt][0] = __float_as_uint(sB[(kk * 8 + tig) * SB_STRIDE + cn]);
                bf[nt][1] = __float_as_uint(sB[(kk * 8 + tig + 4) * SB_STRIDE + cn]);
            }
#pragma unroll
            for (int mt = 0; mt < 4; ++mt)
#pragma unroll
                for (int nt = 0; nt < 4; ++nt)
                    mma_tf32(c[mt][nt], af[mt][0], af[mt][1], af[mt][2], af[mt][3],
                             bf[nt][0], bf[nt][1]);
        }
        __syncthreads();
    }

#pragma unroll
    for (int mt = 0; mt < 4; ++mt) {
#pragma unroll
        for (int nt = 0; nt < 4; ++nt) {
            int row0 = rowBase + wm + mt * 16 + g;
            int col = colBase + wn + nt * 8 + 2 * tig;
            if (row0 < M) {
                float2 o = make_float2(c[mt][nt][0] * alpha, c[mt][nt][1] * alpha);
                *reinterpret_cast<float2*>(&C[(long)row0 * N + col]) = o;
            }
            int row1 = row0 + 8;
            if (row1 < M) {
                float2 o = make_float2(c[mt][nt][2] * alpha, c[mt][nt][3] * alpha);
                *reinterpret_cast<float2*>(&C[(long)row1 * N + col]) = o;
            }
        }
    }
}

// ---------------- zero the txt accumulator ----------------
__global__ void zero_txt_kernel() {
    int i = blockIdx.x * 256 + threadIdx.x;
    if (i < TXTL * DM) g_txtacc[i] = 0.f;
}

// ---------------- window gather + 3D RoPE (Q/K tf32-rounded) ----------------
__global__ void __launch_bounds__(256) build_windows_kernel() {
    int wp = blockIdx.x;
    int tid = threadIdx.x;
    int h = tid >> 6, pr = tid & 63;
    int p = wp % SEQ, w = wp / SEQ;
    int d0 = pr * 2;
    long ob = ((long)wp * 4 + h) * 128 + d0;

    float q0, q1, k0, k1, v0, v1;
    if (p < WS) {
        int token = token_of(w, p);
        const float* base = &g_qkv_v[(long)token * 1536 + h * 128];
        q0 = base[d0];        q1 = base[d0 + 1];
        k0 = base[512 + d0];  k1 = base[512 + d0 + 1];
        v0 = base[1024 + d0]; v1 = base[1024 + d0 + 1];
        int tt = token / 3600;
        int hh = (token / 80) % 45;
        int ww2 = token % 80;
        float pos; int dl, da;
        if (d0 < 32)      { pos = (float)tt;  dl = d0;      da = 32; }
        else if (d0 < 80) { pos = (float)hh;  dl = d0 - 32; da = 48; }
        else              { pos = (float)ww2; dl = d0 - 80; da = 48; }
        float inv = powf(10000.0f, -((float)dl) / (float)da);
        float ang = pos * inv;
        float s, c;
        sincosf(ang, &s, &c);
        float nq0 = q0 * c - q1 * s, nq1 = q1 * c + q0 * s;
        float nk0 = k0 * c - k1 * s, nk1 = k1 * c + k0 * s;
        q0 = nq0; q1 = nq1; k0 = nk0; k1 = nk1;
    } else {
        const float* base = &g_qkv_t[(long)(p - WS) * 1536 + h * 128];
        q0 = base[d0];        q1 = base[d0 + 1];
        k0 = base[512 + d0];  k1 = base[512 + d0 + 1];
        v0 = base[1024 + d0]; v1 = base[1024 + d0 + 1];
    }
    g_Qw[ob] = to_tf32(q0); g_Qw[ob + 1] = to_tf32(q1);
    g_Kw[ob] = to_tf32(k0); g_Kw[ob + 1] = to_tf32(k1);
    g_Vw[ob] = v0; g_Vw[ob + 1] = v1;
}

// ---------------- fused flash attention, tensor-core tf32 ----------------
#define QT   64
#define KT   64
#define PADD 132
#define SPAD 68
#define ATTN_SMEM_FLOATS (QT * PADD + KT * PADD + QT * SPAD + 3 * QT)
#define ATTN_SMEM_BYTES  (ATTN_SMEM_FLOATS * 4)

__global__ void __launch_bounds__(256) attn_kernel() {
    extern __shared__ float sm[];
    float* sQ   = sm;                    // [QT][PADD] (tf32 values)
    float* sKV  = sQ + QT * PADD;        // [KT][PADD] (K tf32 in phase1, V fp32 in phase2)
    float* sS   = sKV + KT * PADD;       // [QT][SPAD] scores / probs (tf32-rounded)
    float* rowM = sS + QT * SPAD;        // [QT]
    float* rowL = rowM + QT;
    float* rowA = rowL + QT;

    const float NEGINF = __int_as_float(0xff800000);
    int qt = blockIdx.x, h = blockIdx.y, w = blockIdx.z;
    int tid = threadIdx.x;
    const int warp = tid >> 5, lane = tid & 31;
    const int g = lane >> 2, tig = lane & 3;
    // phase-1 partition: S[64x64], warps 4m x 2n (warp tile 16x32)
    const int wm1 = (warp & 3) * 16, wn1 = (warp >> 2) * 32;
    // phase-2 partition: O[64x128], warps 4m x 2n (warp tile 16x64)
    const int wm2 = (warp & 3) * 16, wn2 = (warp >> 2) * 64;

    // load Q tile (zero-fill past SEQ)
#pragma unroll
    for (int t = 0; t < 8; ++t) {
        int i4 = tid + t * 256;
        int r = i4 >> 5, d4 = i4 & 31;
        int qg = qt * QT + r;
        float4 v = make_float4(0.f, 0.f, 0.f, 0.f);
        if (qg < SEQ) v = *reinterpret_cast<const float4*>(
            &g_Qw[((long)(w * SEQ + qg) * 4 + h) * 128 + d4 * 4]);
        *reinterpret_cast<float4*>(&sQ[r * PADD + d4 * 4]) = v;
    }
    if (tid < QT) { rowM[tid] = NEGINF; rowL[tid] = 0.f; }

    float oacc[8][4];   // 8 n-frags (cols wn2+nf*8), rows wm2+g / wm2+g+8
#pragma unroll
    for (int nf = 0; nf < 8; ++nf)
#pragma unroll
        for (int i = 0; i < 4; ++i) oacc[nf][i] = 0.f;

    const float scale = 0.08838834764831843f;  // 1/sqrt(128)

    for (int kt = 0; kt < 13; ++kt) {
        __syncthreads();
        // load K tile (tf32 values)
#pragma unroll
        for (int t = 0; t < 8; ++t) {
            int i4 = tid + t * 256;
            int r = i4 >> 5, d4 = i4 & 31;
            int kg = kt * KT + r;
            float4 v = make_float4(0.f, 0.f, 0.f, 0.f);
            if (kg < SEQ) v = *reinterpret_cast<const float4*>(
                &g_Kw[((long)(w * SEQ + kg) * 4 + h) * 128 + d4 * 4]);
            *reinterpret_cast<float4*>(&sKV[r * PADD + d4 * 4]) = v;
        }
        __syncthreads();

        // ---- phase 1: S = Q @ K^T via mma (k over d=128, 16 steps of 8) ----
        {
            float sacc[4][4];
#pragma unroll
            for (int nf = 0; nf < 4; ++nf)
#pragma unroll
                for (int i = 0; i < 4; ++i) sacc[nf][i] = 0.f;
#pragma unroll
            for (int kk = 0; kk < 16; ++kk) {
                unsigned a0 = __float_as_uint(sQ[(wm1 + g) * PADD + kk * 8 + tig]);
                unsigned a1 = __float_as_uint(sQ[(wm1 + g + 8) * PADD + kk * 8 + tig]);
                unsigned a2 = __float_as_uint(sQ[(wm1 + g) * PADD + kk * 8 + tig + 4]);
                unsigned a3 = __float_as_uint(sQ[(wm1 + g + 8) * PADD + kk * 8 + tig + 4]);
#pragma unroll
                for (int nf = 0; nf < 4; ++nf) {
                    int kr = wn1 + nf * 8 + g;   // K-token row
                    unsigned b0 = __float_as_uint(sKV[kr * PADD + kk * 8 + tig]);
                    unsigned b1 = __float_as_uint(sKV[kr * PADD + kk * 8 + tig + 4]);
                    mma_tf32(sacc[nf], a0, a1, a2, a3, b0, b1);
                }
            }
            // write scores to sS (scaled, masked)
#pragma unroll
            for (int nf = 0; nf < 4; ++nf) {
                int col = wn1 + nf * 8 + 2 * tig;
                int kg0 = kt * KT + col, kg1 = kg0 + 1;
                float s00 = (kg0 < SEQ) ? sacc[nf][0] * scale : NEGINF;
                float s01 = (kg1 < SEQ) ? sacc[nf][1] * scale : NEGINF;
                float s10 = (kg0 < SEQ) ? sacc[nf][2] * scale : NEGINF;
                float s11 = (kg1 < SEQ) ? sacc[nf][3] * scale : NEGINF;
                sS[(wm1 + g) * SPAD + col]     = s00;
                sS[(wm1 + g) * SPAD + col + 1] = s01;
                sS[(wm1 + g + 8) * SPAD + col]     = s10;
                sS[(wm1 + g + 8) * SPAD + col + 1] = s11;
            }
        }
        __syncthreads();

        // load V tile (fp32) into sKV + online-softmax stats on sS
#pragma unroll
        for (int t = 0; t < 8; ++t) {
            int i4 = tid + t * 256;
            int r = i4 >> 5, d4 = i4 & 31;
            int kg = kt * KT + r;
            float4 v = make_float4(0.f, 0.f, 0.f, 0.f);
            if (kg < SEQ) v = *reinterpret_cast<const float4*>(
                &g_Vw[((long)(w * SEQ + kg) * 4 + h) * 128 + d4 * 4]);
            *reinterpret_cast<float4*>(&sKV[r * PADD + d4 * 4]) = v;
        }
        {
            int r = tid >> 2, l4 = tid & 3;
            float* row = &sS[r * SPAD + l4 * 16];
            float ml = NEGINF;
#pragma unroll
            for (int s2 = 0; s2 < 16; ++s2) ml = fmaxf(ml, row[s2]);
            ml = fmaxf(ml, __shfl_xor_sync(0xffffffffu, ml, 1));
            ml = fmaxf(ml, __shfl_xor_sync(0xffffffffu, ml, 2));
            float mOld = rowM[r];
            float mNew = fmaxf(mOld, ml);
            float sum = 0.f;
#pragma unroll
            for (int s2 = 0; s2 < 16; ++s2) {
                float pv = to_tf32(__expf(row[s2] - mNew));
                row[s2] = pv;
                sum += pv;
            }
            sum += __shfl_xor_sync(0xffffffffu, sum, 1);
            sum += __shfl_xor_sync(0xffffffffu, sum, 2);
            if (l4 == 0) {
                float a = __expf(mOld - mNew);
                rowA[r] = a;
                rowL[r] = rowL[r] * a + sum;
                rowM[r] = mNew;
            }
        }
        __syncthreads();

        // ---- phase 2: O = O*alpha + P @ V via mma (V hi/lo split) ----
        {
            float a0 = rowA[wm2 + g];
            float a1 = rowA[wm2 + g + 8];
#pragma unroll
            for (int nf = 0; nf < 8; ++nf) {
                oacc[nf][0] *= a0; oacc[nf][1] *= a0;
                oacc[nf][2] *= a1; oacc[nf][3] *= a1;
            }
#pragma unroll
            for (int kk = 0; kk < 8; ++kk) {
                unsigned p0 = __float_as_uint(sS[(wm2 + g) * SPAD + kk * 8 + tig]);
                unsigned p1 = __float_as_uint(sS[(wm2 + g + 8) * SPAD + kk * 8 + tig]);
                unsigned p2 = __float_as_uint(sS[(wm2 + g) * SPAD + kk * 8 + tig + 4]);
                unsigned p3 = __float_as_uint(sS[(wm2 + g + 8) * SPAD + kk * 8 + tig + 4]);
#pragma unroll
                for (int nf = 0; nf < 8; ++nf) {
                    int d = wn2 + nf * 8 + g;
                    float v0r = sKV[(kk * 8 + tig) * PADD + d];
                    float v1r = sKV[(kk * 8 + tig + 4) * PADD + d];
                    float v0h = to_tf32(v0r), v1h = to_tf32(v1r);
                    float v0l = to_tf32(v0r - v0h), v1l = to_tf32(v1r - v1h);
                    mma_tf32(oacc[nf], p0, p1, p2, p3,
                             __float_as_uint(v0h), __float_as_uint(v1h));
                    mma_tf32(oacc[nf], p0, p1, p2, p3,
                             __float_as_uint(v0l), __float_as_uint(v1l));
                }
            }
        }
    }

    // epilogue: normalize, scatter vid rows, atomic-accumulate txt rows
#pragma unroll
    for (int half = 0; half < 2; ++half) {
        int ql = wm2 + g + half * 8;
        int qg = qt * QT + ql;
        if (qg >= SEQ) continue;
        float inv = 1.f / rowL[ql];
        if (qg < WS) {
            int token = token_of(w, qg);
            float* dst = &g_preproj[(long)token * DM + h * 128];
#pragma unroll
            for (int nf = 0; nf < 8; ++nf) {
                int col = wn2 + nf * 8 + 2 * tig;
                float2 o = make_float2(oacc[nf][half * 2] * inv,
                                       oacc[nf][half * 2 + 1] * inv);
                *reinterpret_cast<float2*>(&dst[col]) = o;
            }
        } else {
            int tr = qg - WS;
            float* dst = &g_txtacc[(long)tr * DM + h * 128];
#pragma unroll
            for (int nf = 0; nf < 8; ++nf) {
                int col = wn2 + nf * 8 + 2 * tig;
                atomicAdd(&dst[col],     oacc[nf][half * 2] * inv);
                atomicAdd(&dst[col + 1], oacc[nf][half * 2 + 1] * inv);
            }
        }
    }
}

// ---------------- launch ----------------
extern "C" void kernel_launch(void* const* d_in, const int* in_sizes, int n_in,
                              void* d_out, int out_size) {
    const float* vid       = (const float*)d_in[0];
    const float* txt       = (const float*)d_in[1];
    const float* w_qkv_vid = (const float*)d_in[2];
    const float* w_qkv_txt = (const float*)d_in[3];
    const float* w_out_vid = (const float*)d_in[4];
    const float* w_out_txt = (const float*)d_in[5];
    float* out = (float*)d_out;

    cudaFuncSetAttribute(attn_kernel, cudaFuncAttributeMaxDynamicSharedMemorySize,
                         ATTN_SMEM_BYTES);

    float *p_qkv_v, *p_qkv_t, *p_pre, *p_txt;
    cudaGetSymbolAddress((void**)&p_qkv_v, g_qkv_v);
    cudaGetSymbolAddress((void**)&p_qkv_t, g_qkv_t);
    cudaGetSymbolAddress((void**)&p_pre,   g_preproj);
    cudaGetSymbolAddress((void**)&p_txt,   g_txtacc);

    zero_txt_kernel<<<(TXTL * DM + 255) / 256, 256>>>();

    // QKV projections (tf32 tensor cores)
    tf32_gemm_kernel<<<dim3(1536 / 128, (N_VID + 127) / 128), 256>>>(
        vid, w_qkv_vid, p_qkv_v, N_VID, 1536, DM, 1.f);
    tf32_gemm_kernel<<<dim3(1536 / 128, 1), 256>>>(
        txt, w_qkv_txt, p_qkv_t, TXTL, 1536, DM, 1.f);

    // window gather + rope
    build_windows_kernel<<<NWIN * SEQ, 256>>>();

    // attention (tensor-core flash)
    attn_kernel<<<dim3(13, 4, NWIN), 256, ATTN_SMEM_BYTES>>>();

    // output projections (txt mean over 50 windows folded into alpha)
    tf32_gemm_kernel<<<dim3(DM / 128, (N_VID + 127) / 128), 256>>>(
        p_pre, w_out_vid, out, N_VID, DM, DM, 1.f);
    tf32_gemm_kernel<<<dim3(DM / 128, 1), 256>>>(
        p_txt, w_out_txt, out + (long)N_VID * DM, TXTL, DM, DM, 1.f / 50.f);
}

// round 5
// speedup vs baseline: 2.4705x; 1.0985x over previous
#include <cuda_runtime.h>
#include <math.h>

#define N_VID 36000
#define DM    512
#define NWIN  50
#define WS    720
#define SEQ   784
#define TXTL  64

// ---------------- scratch (static device allocations; no cudaMalloc) ----------------
__device__ float g_qkv_v[N_VID * 1536];        // vid QKV
__device__ float g_qkv_t[TXTL * 1536];         // txt QKV
__device__ float g_Qw[NWIN * SEQ * DM];        // windowed Q (rope, tf32-rounded)
__device__ float g_Kw[NWIN * SEQ * DM];        // tf32-rounded
__device__ float g_Vhi[NWIN * SEQ * DM];       // V hi part (tf32)
__device__ float g_Vlo[NWIN * SEQ * DM];       // V lo part (tf32)
__device__ float g_preproj[N_VID * DM];        // attn out, token order (tf32-rounded)
__device__ float g_txtacc[TXTL * DM];          // txt attn out, summed over windows
__device__ float g_vid_r[N_VID * DM];          // tf32-rounded vid
__device__ float g_wqkv_r[DM * 1536];          // tf32-rounded w_qkv_vid
__device__ float g_wout_r[DM * DM];            // tf32-rounded w_out_vid

__device__ __forceinline__ int token_of(int w, int p) {
    int it = w & 1;
    int ih = (w >> 1) % 5;
    int iw = w / 10;
    int tl = p / 144;
    int rem = p % 144;
    int hl = rem >> 4;
    int wl = rem & 15;
    return ((it * 5 + tl) * 45 + (ih * 9 + hl)) * 80 + (iw * 16 + wl);
}

__device__ __forceinline__ float to_tf32(float x) {
    float r;
    asm("cvt.rna.tf32.f32 %0, %1;" : "=f"(r) : "f"(x));
    return r;
}

__device__ __forceinline__ void mma_tf32(float* c, unsigned a0, unsigned a1,
                                         unsigned a2, unsigned a3,
                                         unsigned b0, unsigned b1) {
    asm volatile(
        "mma.sync.aligned.m16n8k8.row.col.f32.tf32.tf32.f32 "
        "{%0,%1,%2,%3}, {%4,%5,%6,%7}, {%8,%9}, {%0,%1,%2,%3};"
        : "+f"(c[0]), "+f"(c[1]), "+f"(c[2]), "+f"(c[3])
        : "r"(a0), "r"(a1), "r"(a2), "r"(a3), "r"(b0), "r"(b1));
}

// cp.async helpers
__device__ __forceinline__ void cp_async16(float* smem_dst, const float* gsrc, bool valid) {
    unsigned saddr = (unsigned)__cvta_generic_to_shared(smem_dst);
    int sz = valid ? 16 : 0;
    asm volatile("cp.async.cg.shared.global [%0], [%1], 16, %2;\n"
                 :: "r"(saddr), "l"(gsrc), "r"(sz));
}
__device__ __forceinline__ void cp_commit() {
    asm volatile("cp.async.commit_group;\n" ::);
}
template <int N>
__device__ __forceinline__ void cp_wait() {
    asm volatile("cp.async.wait_group %0;\n" :: "n"(N));
}

// ---------------- round to tf32 (rna), elementwise copy ----------------
__global__ void round_tf32_kernel(const float* __restrict__ src, float* __restrict__ dst, int n4) {
    int i = blockIdx.x * 256 + threadIdx.x;
    if (i < n4) {
        float4 v = reinterpret_cast<const float4*>(src)[i];
        v.x = to_tf32(v.x); v.y = to_tf32(v.y); v.z = to_tf32(v.z); v.w = to_tf32(v.w);
        reinterpret_cast<float4*>(dst)[i] = v;
    }
}

// ---------------- old tf32 GEMM (conversion in-kernel) — used for small txt GEMMs --------
#define SA_STRIDE 36
#define SB_STRIDE 136
__global__ void __launch_bounds__(256) tf32_gemm_kernel(
    const float* __restrict__ A, const float* __restrict__ B, float* __restrict__ C,
    int M, int N, int K, float alpha)
{
    __shared__ float sA[128 * SA_STRIDE];
    __shared__ float sB[32 * SB_STRIDE];

    const int tid  = threadIdx.x;
    const int warp = tid >> 5, lane = tid & 31;
    const int g = lane >> 2, tig = lane & 3;
    const int wm = (warp & 1) * 64;
    const int wn = (warp >> 1) * 32;
    const int rowBase = blockIdx.y * 128;
    const int colBase = blockIdx.x * 128;

    float c[4][4][4];
#pragma unroll
    for (int mt = 0; mt < 4; ++mt)
#pragma unroll
        for (int nt = 0; nt < 4; ++nt)
#pragma unroll
            for (int i = 0; i < 4; ++i) c[mt][nt][i] = 0.f;

    float4 pa[4], pb[4];
#pragma unroll
    for (int i = 0; i < 4; ++i) {
        int idx = tid + i * 256;
        int r = idx >> 3, c4 = idx & 7;
        int grow = rowBase + r;
        pa[i] = (grow < M) ? *reinterpret_cast<const float4*>(&A[(long)grow * K + c4 * 4])
                           : make_float4(0.f, 0.f, 0.f, 0.f);
        int rb = idx >> 5, cb4 = idx & 31;
        pb[i] = *reinterpret_cast<const float4*>(&B[(long)rb * N + colBase + cb4 * 4]);
    }

    const int nIter = K / 32;
    for (int it = 0; it < nIter; ++it) {
#pragma unroll
        for (int i = 0; i < 4; ++i) {
            int idx = tid + i * 256;
            int r = idx >> 3, c4 = idx & 7;
            float* d = &sA[r * SA_STRIDE + c4 * 4];
            d[0] = to_tf32(pa[i].x); d[1] = to_tf32(pa[i].y);
            d[2] = to_tf32(pa[i].z); d[3] = to_tf32(pa[i].w);
            int rb = idx >> 5, cb4 = idx & 31;
            float* db = &sB[rb * SB_STRIDE + cb4 * 4];
            db[0] = to_tf32(pb[i].x); db[1] = to_tf32(pb[i].y);
            db[2] = to_tf32(pb[i].z); db[3] = to_tf32(pb[i].w);
        }
        __syncthreads();

        if (it + 1 < nIter) {
            int k0 = (it + 1) * 32;
#pragma unroll
            for (int i = 0; i < 4; ++i) {
                int idx = tid + i * 256;
                int r = idx >> 3, c4 = idx & 7;
                int grow = rowBase + r;
                pa[i] = (grow < M) ? *reinterpret_cast<const float4*>(&A[(long)grow * K + k0 + c4 * 4])
                                   : make_float4(0.f, 0.f, 0.f, 0.f);
                int rb = idx >> 5, cb4 = idx & 31;
                pb[i] = *reinterpret_cast<const float4*>(&B[(long)(k0 + rb) * N + colBase + cb4 * 4]);
            }
        }

#pragma unroll
        for (int kk = 0; kk < 4; ++kk) {
            unsigned int af[4][4], bf[4][2];
#pragma unroll
            for (int mt = 0; mt < 4; ++mt) {
                int r0 = wm + mt * 16 + g;
                af[mt][0] = __float_as_uint(sA[r0 * SA_STRIDE + kk * 8 + tig]);
                af[mt][1] = __float_as_uint(sA[(r0 + 8) * SA_STRIDE + kk * 8 + tig]);
                af[mt][2] = __float_as_uint(sA[r0 * SA_STRIDE + kk * 8 + tig + 4]);
                af[mt][3] = __float_as_uint(sA[(r0 + 8) * SA_STRIDE + kk * 8 + tig + 4]);
            }
#pragma unroll
            for (int nt = 0; nt < 4; ++nt) {
                int cn = wn + nt * 8 + g;
                bf[nt][0] = __float_as_uint(sB[(kk * 8 + tig) * SB_STRIDE + cn]);
                bf[nt][1] = __float_as_uint(sB[(kk * 8 + tig + 4) * SB_STRIDE + cn]);
            }
#pragma unroll
            for (int mt = 0; mt < 4; ++mt)
#pragma unroll
                for (int nt = 0; nt < 4; ++nt)
                    mma_tf32(c[mt][nt], af[mt][0], af[mt][1], af[mt][2], af[mt][3],
                             bf[nt][0], bf[nt][1]);
        }
        __syncthreads();
    }

#pragma unroll
    for (int mt = 0; mt < 4; ++mt) {
#pragma unroll
        for (int nt = 0; nt < 4; ++nt) {
            int row0 = rowBase + wm + mt * 16 + g;
            int col = colBase + wn + nt * 8 + 2 * tig;
            if (row0 < M) {
                float2 o = make_float2(c[mt][nt][0] * alpha, c[mt][nt][1] * alpha);
                *reinterpret_cast<float2*>(&C[(long)row0 * N + col]) = o;
            }
            int row1 = row0 + 8;
            if (row1 < M) {
                float2 o = make_float2(c[mt][nt][2] * alpha, c[mt][nt][3] * alpha);
                *reinterpret_cast<float2*>(&C[(long)row1 * N + col]) = o;
            }
        }
    }
}

// ---------------- GEMM v2: pre-rounded inputs, cp.async 2-stage pipeline ----------------
// C[M,N] = A[M,K] @ B[K,N]. Inputs must be tf32-pre-rounded. N%128==0, K%32==0.
__global__ void __launch_bounds__(256) tf32_gemm_async_kernel(
    const float* __restrict__ A, const float* __restrict__ B, float* __restrict__ C,
    int M, int N, int K)
{
    __shared__ float sA[2][128 * SA_STRIDE];
    __shared__ float sB[2][32 * SB_STRIDE];

    const int tid  = threadIdx.x;
    const int warp = tid >> 5, lane = tid & 31;
    const int g = lane >> 2, tig = lane & 3;
    const int wm = (warp & 1) * 64;
    const int wn = (warp >> 1) * 32;
    const int rowBase = blockIdx.y * 128;
    const int colBase = blockIdx.x * 128;
    const int nIter = K / 32;

    float c[4][4][4];
#pragma unroll
    for (int mt = 0; mt < 4; ++mt)
#pragma unroll
        for (int nt = 0; nt < 4; ++nt)
#pragma unroll
            for (int i = 0; i < 4; ++i) c[mt][nt][i] = 0.f;

    // load coords (float4 granularity)
    const int ar = tid >> 1;                 // unused helper
    (void)ar;

    // prologue: stage 0
    {
#pragma unroll
        for (int i = 0; i < 4; ++i) {
            int idx = tid + i * 256;
            int r = idx >> 3, c4 = idx & 7;
            int grow = rowBase + r;
            cp_async16(&sA[0][r * SA_STRIDE + c4 * 4], &A[(long)grow * K + c4 * 4], grow < M);
            int rb = idx >> 5, cb4 = idx & 31;
            cp_async16(&sB[0][rb * SB_STRIDE + cb4 * 4], &B[(long)rb * N + colBase + cb4 * 4], true);
        }
        cp_commit();
    }

    for (int it = 0; it < nIter; ++it) {
        int b = it & 1;
        if (it + 1 < nIter) {
            int k0 = (it + 1) * 32;
            int bn = (it + 1) & 1;
#pragma unroll
            for (int i = 0; i < 4; ++i) {
                int idx = tid + i * 256;
                int r = idx >> 3, c4 = idx & 7;
                int grow = rowBase + r;
                cp_async16(&sA[bn][r * SA_STRIDE + c4 * 4], &A[(long)grow * K + k0 + c4 * 4], grow < M);
                int rb = idx >> 5, cb4 = idx & 31;
                cp_async16(&sB[bn][rb * SB_STRIDE + cb4 * 4],
                           &B[(long)(k0 + rb) * N + colBase + cb4 * 4], true);
            }
            cp_commit();
            cp_wait<1>();
        } else {
            cp_wait<0>();
        }
        __syncthreads();

#pragma unroll
        for (int kk = 0; kk < 4; ++kk) {
            unsigned int af[4][4], bf[4][2];
#pragma unroll
            for (int mt = 0; mt < 4; ++mt) {
                int r0 = wm + mt * 16 + g;
                af[mt][0] = __float_as_uint(sA[b][r0 * SA_STRIDE + kk * 8 + tig]);
                af[mt][1] = __float_as_uint(sA[b][(r0 + 8) * SA_STRIDE + kk * 8 + tig]);
                af[mt][2] = __float_as_uint(sA[b][r0 * SA_STRIDE + kk * 8 + tig + 4]);
                af[mt][3] = __float_as_uint(sA[b][(r0 + 8) * SA_STRIDE + kk * 8 + tig + 4]);
            }
#pragma unroll
            for (int nt = 0; nt < 4; ++nt) {
                int cn = wn + nt * 8 + g;
                bf[nt][0] = __float_as_uint(sB[b][(kk * 8 + tig) * SB_STRIDE + cn]);
                bf[nt][1] = __float_as_uint(sB[b][(kk * 8 + tig + 4) * SB_STRIDE + cn]);
            }
#pragma unroll
            for (int mt = 0; mt < 4; ++mt)
#pragma unroll
                for (int nt = 0; nt < 4; ++nt)
                    mma_tf32(c[mt][nt], af[mt][0], af[mt][1], af[mt][2], af[mt][3],
                             bf[nt][0], bf[nt][1]);
        }
        __syncthreads();
    }

#pragma unroll
    for (int mt = 0; mt < 4; ++mt) {
#pragma unroll
        for (int nt = 0; nt < 4; ++nt) {
            int row0 = rowBase + wm + mt * 16 + g;
            int col = colBase + wn + nt * 8 + 2 * tig;
            if (row0 < M) {
                float2 o = make_float2(c[mt][nt][0], c[mt][nt][1]);
                *reinterpret_cast<float2*>(&C[(long)row0 * N + col]) = o;
            }
            int row1 = row0 + 8;
            if (row1 < M) {
                float2 o = make_float2(c[mt][nt][2], c[mt][nt][3]);
                *reinterpret_cast<float2*>(&C[(long)row1 * N + col]) = o;
            }
        }
    }
}

// ---------------- zero the txt accumulator ----------------
__global__ void zero_txt_kernel() {
    int i = blockIdx.x * 256 + threadIdx.x;
    if (i < TXTL * DM) g_txtacc[i] = 0.f;
}

// ---------------- window gather + 3D RoPE (Q/K tf32, V hi/lo split) ----------------
__global__ void __launch_bounds__(256) build_windows_kernel() {
    int wp = blockIdx.x;
    int tid = threadIdx.x;
    int h = tid >> 6, pr = tid & 63;
    int p = wp % SEQ, w = wp / SEQ;
    int d0 = pr * 2;
    long ob = ((long)wp * 4 + h) * 128 + d0;

    float q0, q1, k0, k1, v0, v1;
    if (p < WS) {
        int token = token_of(w, p);
        const float* base = &g_qkv_v[(long)token * 1536 + h * 128];
        q0 = base[d0];        q1 = base[d0 + 1];
        k0 = base[512 + d0];  k1 = base[512 + d0 + 1];
        v0 = base[1024 + d0]; v1 = base[1024 + d0 + 1];
        int tt = token / 3600;
        int hh = (token / 80) % 45;
        int ww2 = token % 80;
        float pos; int dl, da;
        if (d0 < 32)      { pos = (float)tt;  dl = d0;      da = 32; }
        else if (d0 < 80) { pos = (float)hh;  dl = d0 - 32; da = 48; }
        else              { pos = (float)ww2; dl = d0 - 80; da = 48; }
        float inv = powf(10000.0f, -((float)dl) / (float)da);
        float ang = pos * inv;
        float s, c;
        sincosf(ang, &s, &c);
        float nq0 = q0 * c - q1 * s, nq1 = q1 * c + q0 * s;
        float nk0 = k0 * c - k1 * s, nk1 = k1 * c + k0 * s;
        q0 = nq0; q1 = nq1; k0 = nk0; k1 = nk1;
    } else {
        const float* base = &g_qkv_t[(long)(p - WS) * 1536 + h * 128];
        q0 = base[d0];        q1 = base[d0 + 1];
        k0 = base[512 + d0];  k1 = base[512 + d0 + 1];
        v0 = base[1024 + d0]; v1 = base[1024 + d0 + 1];
    }
    g_Qw[ob] = to_tf32(q0); g_Qw[ob + 1] = to_tf32(q1);
    g_Kw[ob] = to_tf32(k0); g_Kw[ob + 1] = to_tf32(k1);
    float v0h = to_tf32(v0), v1h = to_tf32(v1);
    g_Vhi[ob] = v0h;               g_Vhi[ob + 1] = v1h;
    g_Vlo[ob] = to_tf32(v0 - v0h); g_Vlo[ob + 1] = to_tf32(v1 - v1h);
}

// ---------------- fused flash attention v2: QT=128, cp.async, register softmax ---------
#define QT2   128
#define KT2   64
#define PADD2 132
#define SPADP 66
#define NKT   13
// smem (floats): sQ 128*132=16896 | sK 2*64*132=16896 | sV(hi+lo) 2*64*132=16896 |
//                sPart 256 | sSum 256  => 51200 floats = 204800 bytes
#define ATTN2_SMEM_BYTES (51200 * 4)

__global__ void __launch_bounds__(256) attn2_kernel() {
    extern __shared__ float sm[];
    float* sQ    = sm;                       // [128][132]
    float* sK    = sm + 16896;               // 2 bufs [64][132]
    float* sV    = sm + 33792;               // hi [64][132] then lo [64][132]
    float* sPart = sm + 50688;               // [128][2]
    float* sSum  = sm + 50944;               // [128][2]

    const float NEGINF = __int_as_float(0xff800000);
    const float scale = 0.08838834764831843f;  // 1/sqrt(128)

    int qt = blockIdx.x, h = blockIdx.y, w = blockIdx.z;
    int tid = threadIdx.x;
    const int warp = tid >> 5, lane = tid & 31;
    const int g = lane >> 2, tig = lane & 3;
    const int wm = (warp & 3) * 32;          // m-group: rows wm..wm+31 (phase1 & phase2)
    const int ng = warp >> 2;                // n-group (0/1)
    const int wn1 = ng * 32;                 // phase1 col offset (S cols)
    const int wn2 = ng * 64;                 // phase2 col offset (O dims)

    const long gbase = ((long)(w * SEQ) * 4 + h) * 128;
    const int qrow0 = qt * QT2;

    // prologue: Q + K0 (one commit group), V0 (second group)
#pragma unroll
    for (int i = 0; i < 16; ++i) {
        int idx = tid + i * 256;
        int r = idx >> 5, c4 = idx & 31;
        cp_async16(&sQ[r * PADD2 + c4 * 4],
                   &g_Qw[gbase + (long)(qrow0 + r) * 512 + c4 * 4], qrow0 + r < SEQ);
    }
#pragma unroll
    for (int i = 0; i < 8; ++i) {
        int idx = tid + i * 256;
        int r = idx >> 5, c4 = idx & 31;
        cp_async16(&sK[r * PADD2 + c4 * 4],
                   &g_Kw[gbase + (long)r * 512 + c4 * 4], r < SEQ);
    }
    cp_commit();

    float oacc[2][8][4];
#pragma unroll
    for (int mt = 0; mt < 2; ++mt)
#pragma unroll
        for (int nf = 0; nf < 8; ++nf)
#pragma unroll
            for (int i = 0; i < 4; ++i) oacc[mt][nf][i] = 0.f;

    float mOld[2][2], lAcc[2][2];
#pragma unroll
    for (int mt = 0; mt < 2; ++mt)
#pragma unroll
        for (int hf = 0; hf < 2; ++hf) { mOld[mt][hf] = NEGINF; lAcc[mt][hf] = 0.f; }

    for (int kt = 0; kt < NKT; ++kt) {
        const int b = kt & 1;
        float* sKb = sK + b * (64 * PADD2);
        float* sP  = sKb;                    // overlay after K is consumed (stride 66)

        __syncthreads();   // phase2(kt-1) done: sV free; prior K buf free

        // issue V[kt] (kt>0; V0 already... actually issue V0 here too but it wasn't
        // issued in prologue — issue uniformly for all kt)
        {
            int kb = kt * KT2;
#pragma unroll
            for (int i = 0; i < 8; ++i) {
                int idx = tid + i * 256;
                int r = idx >> 5, c4 = idx & 31;
                bool v = kb + r < SEQ;
                cp_async16(&sV[r * PADD2 + c4 * 4],
                           &g_Vhi[gbase + (long)(kb + r) * 512 + c4 * 4], v);
                cp_async16(&sV[(64 + r) * PADD2 + c4 * 4],
                           &g_Vlo[gbase + (long)(kb + r) * 512 + c4 * 4], v);
            }
            cp_commit();
        }
        // issue K[kt+1]
        if (kt + 1 < NKT) {
            int kb = (kt + 1) * KT2;
            float* sKn = sK + ((kt + 1) & 1) * (64 * PADD2);
#pragma unroll
            for (int i = 0; i < 8; ++i) {
                int idx = tid + i * 256;
                int r = idx >> 5, c4 = idx & 31;
                cp_async16(&sKn[r * PADD2 + c4 * 4],
                           &g_Kw[gbase + (long)(kb + r) * 512 + c4 * 4], kb + r < SEQ);
            }
            cp_commit();
            cp_wait<2>();   // K[kt] (and everything older) complete
        } else {
            cp_wait<1>();   // only V[kt] may pend
        }
        __syncthreads();   // K[kt] visible to all

        // ---- phase 1: S = Q @ K^T (warp tile 32x32) ----
        float sacc[2][4][4];
#pragma unroll
        for (int mt = 0; mt < 2; ++mt)
#pragma unroll
            for (int nf = 0; nf < 4; ++nf)
#pragma unroll
                for (int i = 0; i < 4; ++i) sacc[mt][nf][i] = 0.f;
#pragma unroll
        for (int kk = 0; kk < 16; ++kk) {
            unsigned af[2][4];
#pragma unroll
            for (int mt = 0; mt < 2; ++mt) {
                int r0 = wm + mt * 16 + g;
                af[mt][0] = __float_as_uint(sQ[r0 * PADD2 + kk * 8 + tig]);
                af[mt][1] = __float_as_uint(sQ[(r0 + 8) * PADD2 + kk * 8 + tig]);
                af[mt][2] = __float_as_uint(sQ[r0 * PADD2 + kk * 8 + tig + 4]);
                af[mt][3] = __float_as_uint(sQ[(r0 + 8) * PADD2 + kk * 8 + tig + 4]);
            }
#pragma unroll
            for (int nf = 0; nf < 4; ++nf) {
                int kr = wn1 + nf * 8 + g;
                unsigned b0 = __float_as_uint(sKb[kr * PADD2 + kk * 8 + tig]);
                unsigned b1 = __float_as_uint(sKb[kr * PADD2 + kk * 8 + tig + 4]);
#pragma unroll
                for (int mt = 0; mt < 2; ++mt)
                    mma_tf32(sacc[mt][nf], af[mt][0], af[mt][1], af[mt][2], af[mt][3], b0, b1);
            }
        }

        // ---- mask + per-thread partial row max ----
        bool cval[4][2];
#pragma unroll
        for (int nf = 0; nf < 4; ++nf) {
            int c0 = kt * KT2 + wn1 + nf * 8 + 2 * tig;
            cval[nf][0] = (c0 < SEQ);
            cval[nf][1] = (c0 + 1 < SEQ);
        }
        float mp[2][2];
#pragma unroll
        for (int mt = 0; mt < 2; ++mt)
#pragma unroll
            for (int hf = 0; hf < 2; ++hf) {
                float m = NEGINF;
#pragma unroll
                for (int nf = 0; nf < 4; ++nf)
#pragma unroll
                    for (int pr = 0; pr < 2; ++pr) {
                        float s = cval[nf][pr] ? sacc[mt][nf][hf * 2 + pr] * scale : NEGINF;
                        sacc[mt][nf][hf * 2 + pr] = s;
                        m = fmaxf(m, s);
                    }
                m = fmaxf(m, __shfl_xor_sync(0xffffffffu, m, 1));
                m = fmaxf(m, __shfl_xor_sync(0xffffffffu, m, 2));
                mp[mt][hf] = m;
            }
        if (tig == 0) {
#pragma unroll
            for (int mt = 0; mt < 2; ++mt)
#pragma unroll
                for (int hf = 0; hf < 2; ++hf)
                    sPart[(wm + mt * 16 + g + hf * 8) * 2 + ng] = mp[mt][hf];
        }
        __syncthreads();   // sPart visible; K buf now dead (phase1 reads complete)

        // ---- exp + P write + partial sums ----
        float mNew[2][2], aF[2][2], psum[2][2];
#pragma unroll
        for (int mt = 0; mt < 2; ++mt)
#pragma unroll
            for (int hf = 0; hf < 2; ++hf) {
                int row = wm + mt * 16 + g + hf * 8;
                float mn = fmaxf(mOld[mt][hf], fmaxf(sPart[row * 2], sPart[row * 2 + 1]));
                aF[mt][hf] = __expf(mOld[mt][hf] - mn);
                mOld[mt][hf] = mn;
                mNew[mt][hf] = mn;
                psum[mt][hf] = 0.f;
            }
#pragma unroll
        for (int mt = 0; mt < 2; ++mt)
#pragma unroll
            for (int hf = 0; hf < 2; ++hf) {
                int row = wm + mt * 16 + g + hf * 8;
#pragma unroll
                for (int nf = 0; nf < 4; ++nf) {
                    float p0 = to_tf32(__expf(sacc[mt][nf][hf * 2]     - mNew[mt][hf]));
                    float p1 = to_tf32(__expf(sacc[mt][nf][hf * 2 + 1] - mNew[mt][hf]));
                    psum[mt][hf] += p0 + p1;
                    int col = wn1 + nf * 8 + 2 * tig;
                    *reinterpret_cast<float2*>(&sP[row * SPADP + col]) = make_float2(p0, p1);
                }
            }
#pragma unroll
        for (int mt = 0; mt < 2; ++mt)
#pragma unroll
            for (int hf = 0; hf < 2; ++hf) {
                float s = psum[mt][hf];
                s += __shfl_xor_sync(0xffffffffu, s, 1);
                s += __shfl_xor_sync(0xffffffffu, s, 2);
                psum[mt][hf] = s;
            }
        if (tig == 0) {
#pragma unroll
            for (int mt = 0; mt < 2; ++mt)
#pragma unroll
                for (int hf = 0; hf < 2; ++hf)
                    sSum[(wm + mt * 16 + g + hf * 8) * 2 + ng] = psum[mt][hf];
        }
        if (kt + 1 < NKT) cp_wait<1>(); else cp_wait<0>();   // V[kt] arrived
        __syncthreads();   // P + sSum visible; V visible

        // ---- l update + rescale O ----
#pragma unroll
        for (int mt = 0; mt < 2; ++mt)
#pragma unroll
            for (int hf = 0; hf < 2; ++hf) {
                int row = wm + mt * 16 + g + hf * 8;
                lAcc[mt][hf] = lAcc[mt][hf] * aF[mt][hf] + sSum[row * 2] + sSum[row * 2 + 1];
            }
#pragma unroll
        for (int mt = 0; mt < 2; ++mt)
#pragma unroll
            for (int nf = 0; nf < 8; ++nf) {
                oacc[mt][nf][0] *= aF[mt][0]; oacc[mt][nf][1] *= aF[mt][0];
                oacc[mt][nf][2] *= aF[mt][1]; oacc[mt][nf][3] *= aF[mt][1];
            }

        // ---- phase 2: O += P @ V (hi + lo), warp tile 32x64 ----
        float* sVlo = sV + 64 * PADD2;
#pragma unroll
        for (int kk = 0; kk < 8; ++kk) {
            unsigned pf[2][4];
#pragma unroll
            for (int mt = 0; mt < 2; ++mt) {
                int r0 = wm + mt * 16 + g;
                pf[mt][0] = __float_as_uint(sP[r0 * SPADP + kk * 8 + tig]);
                pf[mt][1] = __float_as_uint(sP[(r0 + 8) * SPADP + kk * 8 + tig]);
                pf[mt][2] = __float_as_uint(sP[r0 * SPADP + kk * 8 + tig + 4]);
                pf[mt][3] = __float_as_uint(sP[(r0 + 8) * SPADP + kk * 8 + tig + 4]);
            }
#pragma unroll
            for (int nf = 0; nf < 8; ++nf) {
                int d = wn2 + nf * 8 + g;
                unsigned bh0 = __float_as_uint(sV[(kk * 8 + tig) * PADD2 + d]);
                unsigned bh1 = __float_as_uint(sV[(kk * 8 + tig + 4) * PADD2 + d]);
                unsigned bl0 = __float_as_uint(sVlo[(kk * 8 + tig) * PADD2 + d]);
                unsigned bl1 = __float_as_uint(sVlo[(kk * 8 + tig + 4) * PADD2 + d]);
#pragma unroll
                for (int mt = 0; mt < 2; ++mt) {
                    mma_tf32(oacc[mt][nf], pf[mt][0], pf[mt][1], pf[mt][2], pf[mt][3], bh0, bh1);
                    mma_tf32(oacc[mt][nf], pf[mt][0], pf[mt][1], pf[mt][2], pf[mt][3], bl0, bl1);
                }
            }
        }
    }

    // epilogue
#pragma unroll
    for (int mt = 0; mt < 2; ++mt)
#pragma unroll
        for (int hf = 0; hf < 2; ++hf) {
            int ql = wm + mt * 16 + g + hf * 8;
            int qg = qrow0 + ql;
            if (qg >= SEQ) continue;
            float inv = 1.f / lAcc[mt][hf];
            if (qg < WS) {
                int token = token_of(w, qg);
                float* dst = &g_preproj[(long)token * DM + h * 128];
#pragma unroll
                for (int nf = 0; nf < 8; ++nf) {
                    int col = wn2 + nf * 8 + 2 * tig;
                    float2 o = make_float2(to_tf32(oacc[mt][nf][hf * 2] * inv),
                                           to_tf32(oacc[mt][nf][hf * 2 + 1] * inv));
                    *reinterpret_cast<float2*>(&dst[col]) = o;
                }
            } else {
                int tr = qg - WS;
                float* dst = &g_txtacc[(long)tr * DM + h * 128];
#pragma unroll
                for (int nf = 0; nf < 8; ++nf) {
                    int col = wn2 + nf * 8 + 2 * tig;
                    atomicAdd(&dst[col],     oacc[mt][nf][hf * 2] * inv);
                    atomicAdd(&dst[col + 1], oacc[mt][nf][hf * 2 + 1] * inv);
                }
            }
        }
}

// ---------------- launch ----------------
extern "C" void kernel_launch(void* const* d_in, const int* in_sizes, int n_in,
                              void* d_out, int out_size) {
    const float* vid       = (const float*)d_in[0];
    const float* txt       = (const float*)d_in[1];
    const float* w_qkv_vid = (const float*)d_in[2];
    const float* w_qkv_txt = (const float*)d_in[3];
    const float* w_out_vid = (const float*)d_in[4];
    const float* w_out_txt = (const float*)d_in[5];
    float* out = (float*)d_out;

    cudaFuncSetAttribute(attn2_kernel, cudaFuncAttributeMaxDynamicSharedMemorySize,
                         ATTN2_SMEM_BYTES);

    float *p_qkv_v, *p_qkv_t, *p_pre, *p_txt, *p_vid_r, *p_wqkv_r, *p_wout_r;
    cudaGetSymbolAddress((void**)&p_qkv_v,  g_qkv_v);
    cudaGetSymbolAddress((void**)&p_qkv_t,  g_qkv_t);
    cudaGetSymbolAddress((void**)&p_pre,    g_preproj);
    cudaGetSymbolAddress((void**)&p_txt,    g_txtacc);
    cudaGetSymbolAddress((void**)&p_vid_r,  g_vid_r);
    cudaGetSymbolAddress((void**)&p_wqkv_r, g_wqkv_r);
    cudaGetSymbolAddress((void**)&p_wout_r, g_wout_r);

    zero_txt_kernel<<<(TXTL * DM + 255) / 256, 256>>>();

    // pre-round big GEMM inputs to tf32 (rna)
    round_tf32_kernel<<<(N_VID * DM / 4 + 255) / 256, 256>>>(vid, p_vid_r, N_VID * DM / 4);
    round_tf32_kernel<<<(DM * 1536 / 4 + 255) / 256, 256>>>(w_qkv_vid, p_wqkv_r, DM * 1536 / 4);
    round_tf32_kernel<<<(DM * DM / 4 + 255) / 256, 256>>>(w_out_vid, p_wout_r, DM * DM / 4);

    // QKV projections
    tf32_gemm_async_kernel<<<dim3(1536 / 128, (N_VID + 127) / 128), 256>>>(
        p_vid_r, p_wqkv_r, p_qkv_v, N_VID, 1536, DM);
    tf32_gemm_kernel<<<dim3(1536 / 128, 1), 256>>>(
        txt, w_qkv_txt, p_qkv_t, TXTL, 1536, DM, 1.f);

    // window gather + rope + V split
    build_windows_kernel<<<NWIN * SEQ, 256>>>();

    // attention
    attn2_kernel<<<dim3(7, 4, NWIN), 256, ATTN2_SMEM_BYTES>>>();

    // output projections
    tf32_gemm_async_kernel<<<dim3(DM / 128, (N_VID + 127) / 128), 256>>>(
        p_pre, p_wout_r, out, N_VID, DM, DM);
    tf32_gemm_kernel<<<dim3(DM / 128, 1), 256>>>(
        p_txt, w_out_txt, out + (long)N_VID * DM, TXTL, DM, DM, 1.f / 50.f);
}

// round 7
// speedup vs baseline: 2.9325x; 1.1870x over previous
#include <cuda_runtime.h>
#include <cuda_fp16.h>
#include <math.h>
#include <stdint.h>

#define N_VID 36000
#define DM    512
#define NWIN  50
#define WS    720
#define SEQ   784
#define TXTL  64

// ---------------- scratch (static device allocations; no cudaMalloc) ----------------
__device__ float  g_qkv_v[N_VID * 1536];        // vid QKV (fp32)
__device__ float  g_qkv_t[TXTL * 1536];         // txt QKV (fp32)
__device__ __half g_Qw_h[NWIN * SEQ * DM];      // windowed Q (rope, fp16)
__device__ __half g_Kw_h[NWIN * SEQ * DM];
__device__ __half g_Vhi_h[NWIN * SEQ * DM];
__device__ __half g_Vlo_h[NWIN * SEQ * DM];
__device__ __half g_preproj_h[N_VID * DM];      // attn out, token order (fp16)
__device__ float  g_txtacc[TXTL * DM];          // txt attn out (fp32)
__device__ __half g_vid_h[N_VID * DM];          // fp16 vid
__device__ __half g_wqkvT_h[1536 * DM];         // w_qkv_vid^T [N][K] fp16
__device__ __half g_woutT_h[DM * DM];           // w_out_vid^T [N][K] fp16

__device__ __forceinline__ int token_of(int w, int p) {
    int it = w & 1;
    int ih = (w >> 1) % 5;
    int iw = w / 10;
    int tl = p / 144;
    int rem = p % 144;
    int hl = rem >> 4;
    int wl = rem & 15;
    return ((it * 5 + tl) * 45 + (ih * 9 + hl)) * 80 + (iw * 16 + wl);
}

__device__ __forceinline__ float to_tf32(float x) {
    float r;
    asm("cvt.rna.tf32.f32 %0, %1;" : "=f"(r) : "f"(x));
    return r;
}

// tf32 mma (kept for small txt GEMMs)
__device__ __forceinline__ void mma_tf32(float* c, unsigned a0, unsigned a1,
                                         unsigned a2, unsigned a3,
                                         unsigned b0, unsigned b1) {
    asm volatile(
        "mma.sync.aligned.m16n8k8.row.col.f32.tf32.tf32.f32 "
        "{%0,%1,%2,%3}, {%4,%5,%6,%7}, {%8,%9}, {%0,%1,%2,%3};"
        : "+f"(c[0]), "+f"(c[1]), "+f"(c[2]), "+f"(c[3])
        : "r"(a0), "r"(a1), "r"(a2), "r"(a3), "r"(b0), "r"(b1));
}

// fp16 mma, fp32 accum
__device__ __forceinline__ void mma_f16(float* c, const uint32_t* a,
                                        uint32_t b0, uint32_t b1) {
    asm volatile(
        "mma.sync.aligned.m16n8k16.row.col.f32.f16.f16.f32 "
        "{%0,%1,%2,%3}, {%4,%5,%6,%7}, {%8,%9}, {%0,%1,%2,%3};"
        : "+f"(c[0]), "+f"(c[1]), "+f"(c[2]), "+f"(c[3])
        : "r"(a[0]), "r"(a[1]), "r"(a[2]), "r"(a[3]), "r"(b0), "r"(b1));
}

__device__ __forceinline__ void ldsm_x4(uint32_t* r, uint32_t addr) {
    asm volatile("ldmatrix.sync.aligned.m8n8.x4.shared.b16 {%0,%1,%2,%3}, [%4];"
                 : "=r"(r[0]), "=r"(r[1]), "=r"(r[2]), "=r"(r[3]) : "r"(addr));
}
__device__ __forceinline__ void ldsm_x4_t(uint32_t* r, uint32_t addr) {
    asm volatile("ldmatrix.sync.aligned.m8n8.x4.trans.shared.b16 {%0,%1,%2,%3}, [%4];"
                 : "=r"(r[0]), "=r"(r[1]), "=r"(r[2]), "=r"(r[3]) : "r"(addr));
}

__device__ __forceinline__ uint32_t smem_u32(const void* p) {
    return (uint32_t)__cvta_generic_to_shared(p);
}

// cp.async helpers (16B; invalid -> zero-fill)
__device__ __forceinline__ void cp_async16(void* smem_dst, const void* gsrc, bool valid) {
    unsigned saddr = (unsigned)__cvta_generic_to_shared(smem_dst);
    int sz = valid ? 16 : 0;
    asm volatile("cp.async.cg.shared.global [%0], [%1], 16, %2;\n"
                 :: "r"(saddr), "l"(gsrc), "r"(sz));
}
__device__ __forceinline__ void cp_commit() {
    asm volatile("cp.async.commit_group;\n" ::);
}
template <int N>
__device__ __forceinline__ void cp_wait() {
    asm volatile("cp.async.wait_group %0;\n" :: "n"(N));
}

// ---------------- round fp32 -> fp16, elementwise ----------------
__global__ void round_half_kernel(const float* __restrict__ src, __half* __restrict__ dst, int n4) {
    int i = blockIdx.x * 256 + threadIdx.x;
    if (i < n4) {
        float4 v = reinterpret_cast<const float4*>(src)[i];
        reinterpret_cast<__half2*>(dst)[2 * i]     = __floats2half2_rn(v.x, v.y);
        reinterpret_cast<__half2*>(dst)[2 * i + 1] = __floats2half2_rn(v.z, v.w);
    }
}

// ---------------- transpose + round weights: w[K][N] fp32 -> wt[N][K] fp16 ----------------
__global__ void transpose_round_h_kernel(const float* __restrict__ w, __half* __restrict__ wt,
                                         int K, int N) {
    __shared__ float t[32][33];
    int nb = blockIdx.x * 32, kb = blockIdx.y * 32;
    int tx = threadIdx.x, ty = threadIdx.y;   // 32 x 8
#pragma unroll
    for (int j = 0; j < 4; ++j)
        t[ty + j * 8][tx] = w[(long)(kb + ty + j * 8) * N + nb + tx];
    __syncthreads();
#pragma unroll
    for (int j = 0; j < 4; ++j)
        wt[(long)(nb + ty + j * 8) * K + kb + tx] = __float2half_rn(t[tx][ty + j * 8]);
}

// ============= fp16 tensor-core GEMM: C[M,N] = A[M,K] @ Bt[N,K]^T (fp32 out) =============
// 128x128 CTA tile, BK=32, 256 threads, 8 warps 64x32, m16n8k16, ldmatrix, cp.async 2-stage.
#define GH_STRIDE 40   // halves per row (32 + 8 pad); 80B, conflict-free for ldmatrix
__global__ void __launch_bounds__(256) h16_gemm_kernel(
    const __half* __restrict__ A, const __half* __restrict__ Bt, float* __restrict__ C,
    int M, int N, int K)
{
    __shared__ __half sA[2][128 * GH_STRIDE];
    __shared__ __half sB[2][128 * GH_STRIDE];

    const int tid  = threadIdx.x;
    const int warp = tid >> 5, lane = tid & 31;
    const int g = lane >> 2, tig = lane & 3;
    const int lr = lane & 15, lk = (lane >> 4) * 8;
    const int wm = (warp & 1) * 64;
    const int wn = (warp >> 1) * 32;
    const int rowBase = blockIdx.y * 128;
    const int colBase = blockIdx.x * 128;
    const int nIter = K / 32;

    float c[4][4][4];
#pragma unroll
    for (int mt = 0; mt < 4; ++mt)
#pragma unroll
        for (int nt = 0; nt < 4; ++nt)
#pragma unroll
            for (int i = 0; i < 4; ++i) c[mt][nt][i] = 0.f;

    // prologue: stage 0 (A,B tiles: 128 rows x 32 halves = 4 chunks of 8 halves per row)
#pragma unroll
    for (int i = 0; i < 2; ++i) {
        int idx = tid + i * 256;
        int r = idx >> 2, o = idx & 3;
        int grow = rowBase + r;
        cp_async16(&sA[0][r * GH_STRIDE + o * 8], &A[(long)grow * K + o * 8], grow < M);
        cp_async16(&sB[0][r * GH_STRIDE + o * 8], &Bt[(long)(colBase + r) * K + o * 8], true);
    }
    cp_commit();

    for (int it = 0; it < nIter; ++it) {
        int b = it & 1;
        if (it + 1 < nIter) {
            int k0 = (it + 1) * 32;
            int bn = (it + 1) & 1;
#pragma unroll
            for (int i = 0; i < 2; ++i) {
                int idx = tid + i * 256;
                int r = idx >> 2, o = idx & 3;
                int grow = rowBase + r;
                cp_async16(&sA[bn][r * GH_STRIDE + o * 8], &A[(long)grow * K + k0 + o * 8], grow < M);
                cp_async16(&sB[bn][r * GH_STRIDE + o * 8], &Bt[(long)(colBase + r) * K + k0 + o * 8], true);
            }
            cp_commit();
            cp_wait<1>();
        } else {
            cp_wait<0>();
        }
        __syncthreads();

        uint32_t aBase = smem_u32(&sA[b][0]) + ((wm + lr) * GH_STRIDE + lk) * 2;
        uint32_t bBase = smem_u32(&sB[b][0]) + ((wn + lr) * GH_STRIDE + lk) * 2;
#pragma unroll
        for (int s = 0; s < 2; ++s) {
            uint32_t af[4][4];
#pragma unroll
            for (int mt = 0; mt < 4; ++mt)
                ldsm_x4(af[mt], aBase + mt * (16 * GH_STRIDE * 2) + s * 32);
#pragma unroll
            for (int np = 0; np < 2; ++np) {
                uint32_t bf[4];
                ldsm_x4(bf, bBase + np * (16 * GH_STRIDE * 2) + s * 32);
#pragma unroll
                for (int mt = 0; mt < 4; ++mt) {
                    mma_f16(c[mt][np * 2],     af[mt], bf[0], bf[2]);
                    mma_f16(c[mt][np * 2 + 1], af[mt], bf[1], bf[3]);
                }
            }
        }
        __syncthreads();
    }

#pragma unroll
    for (int mt = 0; mt < 4; ++mt) {
#pragma unroll
        for (int nt = 0; nt < 4; ++nt) {
            int row0 = rowBase + wm + mt * 16 + g;
            int col = colBase + wn + nt * 8 + 2 * tig;
            if (row0 < M) {
                float2 o = make_float2(c[mt][nt][0], c[mt][nt][1]);
                *reinterpret_cast<float2*>(&C[(long)row0 * N + col]) = o;
            }
            int row1 = row0 + 8;
            if (row1 < M) {
                float2 o = make_float2(c[mt][nt][2], c[mt][nt][3]);
                *reinterpret_cast<float2*>(&C[(long)row1 * N + col]) = o;
            }
        }
    }
}

// ---------------- old tf32 GEMM — small txt GEMMs only ----------------
#define SA_STRIDE 36
#define SB_STRIDE 136
__global__ void __launch_bounds__(256) tf32_gemm_kernel(
    const float* __restrict__ A, const float* __restrict__ B, float* __restrict__ C,
    int M, int N, int K, float alpha)
{
    __shared__ float sA[128 * SA_STRIDE];
    __shared__ float sB[32 * SB_STRIDE];

    const int tid  = threadIdx.x;
    const int warp = tid >> 5, lane = tid & 31;
    const int g = lane >> 2, tig = lane & 3;
    const int wm = (warp & 1) * 64;
    const int wn = (warp >> 1) * 32;
    const int rowBase = blockIdx.y * 128;
    const int colBase = blockIdx.x * 128;

    float c[4][4][4];
#pragma unroll
    for (int mt = 0; mt < 4; ++mt)
#pragma unroll
        for (int nt = 0; nt < 4; ++nt)
#pragma unroll
            for (int i = 0; i < 4; ++i) c[mt][nt][i] = 0.f;

    float4 pa[4], pb[4];
#pragma unroll
    for (int i = 0; i < 4; ++i) {
        int idx = tid + i * 256;
        int r = idx >> 3, c4 = idx & 7;
        int grow = rowBase + r;
        pa[i] = (grow < M) ? *reinterpret_cast<const float4*>(&A[(long)grow * K + c4 * 4])
                           : make_float4(0.f, 0.f, 0.f, 0.f);
        int rb = idx >> 5, cb4 = idx & 31;
        pb[i] = *reinterpret_cast<const float4*>(&B[(long)rb * N + colBase + cb4 * 4]);
    }

    const int nIter = K / 32;
    for (int it = 0; it < nIter; ++it) {
#pragma unroll
        for (int i = 0; i < 4; ++i) {
            int idx = tid + i * 256;
            int r = idx >> 3, c4 = idx & 7;
            float* d = &sA[r * SA_STRIDE + c4 * 4];
            d[0] = to_tf32(pa[i].x); d[1] = to_tf32(pa[i].y);
            d[2] = to_tf32(pa[i].z); d[3] = to_tf32(pa[i].w);
            int rb = idx >> 5, cb4 = idx & 31;
            float* db = &sB[rb * SB_STRIDE + cb4 * 4];
            db[0] = to_tf32(pb[i].x); db[1] = to_tf32(pb[i].y);
            db[2] = to_tf32(pb[i].z); db[3] = to_tf32(pb[i].w);
        }
        __syncthreads();

        if (it + 1 < nIter) {
            int k0 = (it + 1) * 32;
#pragma unroll
            for (int i = 0; i < 4; ++i) {
                int idx = tid + i * 256;
                int r = idx >> 3, c4 = idx & 7;
                int grow = rowBase + r;
                pa[i] = (grow < M) ? *reinterpret_cast<const float4*>(&A[(long)grow * K + k0 + c4 * 4])
                                   : make_float4(0.f, 0.f, 0.f, 0.f);
                int rb = idx >> 5, cb4 = idx & 31;
                pb[i] = *reinterpret_cast<const float4*>(&B[(long)(k0 + rb) * N + colBase + cb4 * 4]);
            }
        }

#pragma unroll
        for (int kk = 0; kk < 4; ++kk) {
            unsigned int af[4][4], bf[4][2];
#pragma unroll
            for (int mt = 0; mt < 4; ++mt) {
                int r0 = wm + mt * 16 + g;
                af[mt][0] = __float_as_uint(sA[r0 * SA_STRIDE + kk * 8 + tig]);
                af[mt][1] = __float_as_uint(sA[(r0 + 8) * SA_STRIDE + kk * 8 + tig]);
                af[mt][2] = __float_as_uint(sA[r0 * SA_STRIDE + kk * 8 + tig + 4]);
                af[mt][3] = __float_as_uint(sA[(r0 + 8) * SA_STRIDE + kk * 8 + tig + 4]);
            }
#pragma unroll
            for (int nt = 0; nt < 4; ++nt) {
                int cn = wn + nt * 8 + g;
                bf[nt][0] = __float_as_uint(sB[(kk * 8 + tig) * SB_STRIDE + cn]);
                bf[nt][1] = __float_as_uint(sB[(kk * 8 + tig + 4) * SB_STRIDE + cn]);
            }
#pragma unroll
            for (int mt = 0; mt < 4; ++mt)
#pragma unroll
                for (int nt = 0; nt < 4; ++nt)
                    mma_tf32(c[mt][nt], af[mt][0], af[mt][1], af[mt][2], af[mt][3],
                             bf[nt][0], bf[nt][1]);
        }
        __syncthreads();
    }

#pragma unroll
    for (int mt = 0; mt < 4; ++mt) {
#pragma unroll
        for (int nt = 0; nt < 4; ++nt) {
            int row0 = rowBase + wm + mt * 16 + g;
            int col = colBase + wn + nt * 8 + 2 * tig;
            if (row0 < M) {
                float2 o = make_float2(c[mt][nt][0] * alpha, c[mt][nt][1] * alpha);
                *reinterpret_cast<float2*>(&C[(long)row0 * N + col]) = o;
            }
            int row1 = row0 + 8;
            if (row1 < M) {
                float2 o = make_float2(c[mt][nt][2] * alpha, c[mt][nt][3] * alpha);
                *reinterpret_cast<float2*>(&C[(long)row1 * N + col]) = o;
            }
        }
    }
}

// ---------------- zero the txt accumulator ----------------
__global__ void zero_txt_kernel() {
    int i = blockIdx.x * 256 + threadIdx.x;
    if (i < TXTL * DM) g_txtacc[i] = 0.f;
}

// ---------------- window gather + 3D RoPE -> fp16 Q/K, V hi/lo ----------------
__global__ void __launch_bounds__(256) build_windows_kernel() {
    int wp = blockIdx.x;
    int tid = threadIdx.x;
    int h = tid >> 6, pr = tid & 63;
    int p = wp % SEQ, w = wp / SEQ;
    int d0 = pr * 2;
    long ob = ((long)wp * 4 + h) * 128 + d0;

    float q0, q1, k0, k1, v0, v1;
    if (p < WS) {
        int token = token_of(w, p);
        const float* base = &g_qkv_v[(long)token * 1536 + h * 128];
        q0 = base[d0];        q1 = base[d0 + 1];
        k0 = base[512 + d0];  k1 = base[512 + d0 + 1];
        v0 = base[1024 + d0]; v1 = base[1024 + d0 + 1];
        int tt = token / 3600;
        int hh = (token / 80) % 45;
        int ww2 = token % 80;
        float pos; int dl, da;
        if (d0 < 32)      { pos = (float)tt;  dl = d0;      da = 32; }
        else if (d0 < 80) { pos = (float)hh;  dl = d0 - 32; da = 48; }
        else              { pos = (float)ww2; dl = d0 - 80; da = 48; }
        float inv = powf(10000.0f, -((float)dl) / (float)da);
        float ang = pos * inv;
        float s, c;
        sincosf(ang, &s, &c);
        float nq0 = q0 * c - q1 * s, nq1 = q1 * c + q0 * s;
        float nk0 = k0 * c - k1 * s, nk1 = k1 * c + k0 * s;
        q0 = nq0; q1 = nq1; k0 = nk0; k1 = nk1;
    } else {
        const float* base = &g_qkv_t[(long)(p - WS) * 1536 + h * 128];
        q0 = base[d0];        q1 = base[d0 + 1];
        k0 = base[512 + d0];  k1 = base[512 + d0 + 1];
        v0 = base[1024 + d0]; v1 = base[1024 + d0 + 1];
    }
    *reinterpret_cast<__half2*>(&g_Qw_h[ob]) = __floats2half2_rn(q0, q1);
    *reinterpret_cast<__half2*>(&g_Kw_h[ob]) = __floats2half2_rn(k0, k1);
    __half v0h = __float2half_rn(v0), v1h = __float2half_rn(v1);
    *reinterpret_cast<__half2*>(&g_Vhi_h[ob]) = __halves2half2(v0h, v1h);
    *reinterpret_cast<__half2*>(&g_Vlo_h[ob]) =
        __floats2half2_rn(v0 - __half2float(v0h), v1 - __half2float(v1h));
}

// ---------------- fp16 flash attention: QT=128, KT=64, ldmatrix, cp.async ----------------
#define QT2   128
#define KT2   64
#define PADDH 136   // halves stride for Q/K/V rows (128+8); 272B
#define PSTR  72    // halves stride for P rows (64+8); 144B
#define NKT   13
// smem halves: sQ 128*136=17408 @0 | sK 2 bufs of 9216 @17408 (K uses 64*136, P overlay 128*72)
//              sV hi+lo 2*64*136=17408 @35840 | total halves 53248 = 106496B
// floats: sPart 256 @106496B, sSum 256 @107520B => total 108544B
#define SMEM_K0   17408
#define SMEM_KBUF 9216
#define SMEM_V    35840
#define ATTN3_SMEM_BYTES 108544

__global__ void __launch_bounds__(256) attn3_kernel() {
    extern __shared__ char smraw[];
    __half* sh = (__half*)smraw;
    float* sPart = (float*)(smraw + 106496);
    float* sSum  = (float*)(smraw + 107520);
    const uint32_t sbase = smem_u32(sh);

    const float NEGINF = __int_as_float(0xff800000);
    const float scale = 0.08838834764831843f;  // 1/sqrt(128)

    int qt = blockIdx.x, h = blockIdx.y, w = blockIdx.z;
    int tid = threadIdx.x;
    const int warp = tid >> 5, lane = tid & 31;
    const int g = lane >> 2, tig = lane & 3;
    const int lr = lane & 15, lk = (lane >> 4) * 8;
    const int wm = (warp & 3) * 32;
    const int ng = warp >> 2;
    const int wn1 = ng * 32;
    const int wn2 = ng * 64;

    const long gbase = ((long)(w * SEQ) * 4 + h) * 128;
    const int qrow0 = qt * QT2;

    // prologue: Q (8 chunks/thread) + K0 (4 chunks/thread), one commit group
#pragma unroll
    for (int i = 0; i < 8; ++i) {
        int idx = tid + i * 256;
        int r = idx >> 4, o = idx & 15;
        cp_async16(&sh[r * PADDH + o * 8],
                   &g_Qw_h[gbase + (long)(qrow0 + r) * 512 + o * 8], qrow0 + r < SEQ);
    }
#pragma unroll
    for (int i = 0; i < 4; ++i) {
        int idx = tid + i * 256;
        int r = idx >> 4, o = idx & 15;
        cp_async16(&sh[SMEM_K0 + r * PADDH + o * 8],
                   &g_Kw_h[gbase + (long)r * 512 + o * 8], r < SEQ);
    }
    cp_commit();

    float oacc[2][8][4];
#pragma unroll
    for (int mt = 0; mt < 2; ++mt)
#pragma unroll
        for (int nf = 0; nf < 8; ++nf)
#pragma unroll
            for (int i = 0; i < 4; ++i) oacc[mt][nf][i] = 0.f;

    float mOld[2][2], lAcc[2][2];
#pragma unroll
    for (int mt = 0; mt < 2; ++mt)
#pragma unroll
        for (int hf = 0; hf < 2; ++hf) { mOld[mt][hf] = NEGINF; lAcc[mt][hf] = 0.f; }

    for (int kt = 0; kt < NKT; ++kt) {
        const int b = kt & 1;
        __half* sKb = sh + SMEM_K0 + b * SMEM_KBUF;
        __half* sP  = sKb;   // overlay after K consumed

        __syncthreads();   // phase2(kt-1) done: sV free; prior K buf free

        // issue V[kt] hi+lo (8 chunks/thread)
        {
            int kb = kt * KT2;
#pragma unroll
            for (int i = 0; i < 4; ++i) {
                int idx = tid + i * 256;
                int r = idx >> 4, o = idx & 15;
                bool v = kb + r < SEQ;
                cp_async16(&sh[SMEM_V + r * PADDH + o * 8],
                           &g_Vhi_h[gbase + (long)(kb + r) * 512 + o * 8], v);
                cp_async16(&sh[SMEM_V + 8704 + r * PADDH + o * 8],
                           &g_Vlo_h[gbase + (long)(kb + r) * 512 + o * 8], v);
            }
            cp_commit();
        }
        // issue K[kt+1]
        if (kt + 1 < NKT) {
            int kb = (kt + 1) * KT2;
            __half* sKn = sh + SMEM_K0 + ((kt + 1) & 1) * SMEM_KBUF;
#pragma unroll
            for (int i = 0; i < 4; ++i) {
                int idx = tid + i * 256;
                int r = idx >> 4, o = idx & 15;
                cp_async16(&sKn[r * PADDH + o * 8],
                           &g_Kw_h[gbase + (long)(kb + r) * 512 + o * 8], kb + r < SEQ);
            }
            cp_commit();
            cp_wait<2>();   // K[kt] complete
        } else {
            cp_wait<1>();
        }
        __syncthreads();

        // ---- phase 1: S = Q @ K^T (warp tile 32x32, 8 k16-steps) ----
        float sacc[2][4][4];
#pragma unroll
        for (int mt = 0; mt < 2; ++mt)
#pragma unroll
            for (int nf = 0; nf < 4; ++nf)
#pragma unroll
                for (int i = 0; i < 4; ++i) sacc[mt][nf][i] = 0.f;

        {
            uint32_t qa0 = sbase + ((wm + lr) * PADDH + lk) * 2;
            uint32_t ka0 = smem_u32(sKb) + ((wn1 + lr) * PADDH + lk) * 2;
#pragma unroll
            for (int kk = 0; kk < 8; ++kk) {
                uint32_t aQ[2][4];
#pragma unroll
                for (int mt = 0; mt < 2; ++mt)
                    ldsm_x4(aQ[mt], qa0 + mt * (16 * PADDH * 2) + kk * 32);
#pragma unroll
                for (int np = 0; np < 2; ++np) {
                    uint32_t bK[4];
                    ldsm_x4(bK, ka0 + np * (16 * PADDH * 2) + kk * 32);
#pragma unroll
                    for (int mt = 0; mt < 2; ++mt) {
                        mma_f16(sacc[mt][np * 2],     aQ[mt], bK[0], bK[2]);
                        mma_f16(sacc[mt][np * 2 + 1], aQ[mt], bK[1], bK[3]);
                    }
                }
            }
        }

        // ---- mask + per-thread partial row max ----
        bool cval[4][2];
#pragma unroll
        for (int nf = 0; nf < 4; ++nf) {
            int c0 = kt * KT2 + wn1 + nf * 8 + 2 * tig;
            cval[nf][0] = (c0 < SEQ);
            cval[nf][1] = (c0 + 1 < SEQ);
        }
        float mp[2][2];
#pragma unroll
        for (int mt = 0; mt < 2; ++mt)
#pragma unroll
            for (int hf = 0; hf < 2; ++hf) {
                float m = NEGINF;
#pragma unroll
                for (int nf = 0; nf < 4; ++nf)
#pragma unroll
                    for (int pr = 0; pr < 2; ++pr) {
                        float s = cval[nf][pr] ? sacc[mt][nf][hf * 2 + pr] * scale : NEGINF;
                        sacc[mt][nf][hf * 2 + pr] = s;
                        m = fmaxf(m, s);
                    }
                m = fmaxf(m, __shfl_xor_sync(0xffffffffu, m, 1));
                m = fmaxf(m, __shfl_xor_sync(0xffffffffu, m, 2));
                mp[mt][hf] = m;
            }
        if (tig == 0) {
#pragma unroll
            for (int mt = 0; mt < 2; ++mt)
#pragma unroll
                for (int hf = 0; hf < 2; ++hf)
                    sPart[(wm + mt * 16 + g + hf * 8) * 2 + ng] = mp[mt][hf];
        }
        __syncthreads();   // sPart visible; K buf dead -> P overlay safe

        // ---- exp + P(half) write + partial sums ----
        float aF[2][2], psum[2][2];
#pragma unroll
        for (int mt = 0; mt < 2; ++mt)
#pragma unroll
            for (int hf = 0; hf < 2; ++hf) {
                int row = wm + mt * 16 + g + hf * 8;
                float mn = fmaxf(mOld[mt][hf], fmaxf(sPart[row * 2], sPart[row * 2 + 1]));
                aF[mt][hf] = __expf(mOld[mt][hf] - mn);
                mOld[mt][hf] = mn;
                psum[mt][hf] = 0.f;
            }
#pragma unroll
        for (int mt = 0; mt < 2; ++mt)
#pragma unroll
            for (int hf = 0; hf < 2; ++hf) {
                int row = wm + mt * 16 + g + hf * 8;
                float mn = mOld[mt][hf];
#pragma unroll
                for (int nf = 0; nf < 4; ++nf) {
                    __half p0h = __float2half_rn(__expf(sacc[mt][nf][hf * 2]     - mn));
                    __half p1h = __float2half_rn(__expf(sacc[mt][nf][hf * 2 + 1] - mn));
                    psum[mt][hf] += __half2float(p0h) + __half2float(p1h);
                    int col = wn1 + nf * 8 + 2 * tig;
                    *reinterpret_cast<__half2*>(&sP[row * PSTR + col]) = __halves2half2(p0h, p1h);
                }
            }
#pragma unroll
        for (int mt = 0; mt < 2; ++mt)
#pragma unroll
            for (int hf = 0; hf < 2; ++hf) {
                float s = psum[mt][hf];
                s += __shfl_xor_sync(0xffffffffu, s, 1);
                s += __shfl_xor_sync(0xffffffffu, s, 2);
                psum[mt][hf] = s;
            }
        if (tig == 0) {
#pragma unroll
            for (int mt = 0; mt < 2; ++mt)
#pragma unroll
                for (int hf = 0; hf < 2; ++hf)
                    sSum[(wm + mt * 16 + g + hf * 8) * 2 + ng] = psum[mt][hf];
        }
        if (kt + 1 < NKT) cp_wait<1>(); else cp_wait<0>();   // V[kt] arrived
        __syncthreads();   // P + sSum + V visible

        // ---- l update + rescale O ----
#pragma unroll
        for (int mt = 0; mt < 2; ++mt)
#pragma unroll
            for (int hf = 0; hf < 2; ++hf) {
                int row = wm + mt * 16 + g + hf * 8;
                lAcc[mt][hf] = lAcc[mt][hf] * aF[mt][hf] + sSum[row * 2] + sSum[row * 2 + 1];
            }
#pragma unroll
        for (int mt = 0; mt < 2; ++mt)
#pragma unroll
            for (int nf = 0; nf < 8; ++nf) {
                oacc[mt][nf][0] *= aF[mt][0]; oacc[mt][nf][1] *= aF[mt][0];
                oacc[mt][nf][2] *= aF[mt][1]; oacc[mt][nf][3] *= aF[mt][1];
            }

        // ---- phase 2: O += P @ V (hi + lo), warp tile 32x64, 4 k16-steps ----
        {
            uint32_t pa0 = smem_u32(sP) + ((wm + lr) * PSTR + lk) * 2;
            int vkr = ((lane >> 3) & 1) * 8 + (lane & 7);
            int vnc = (lane >> 4) * 8;
            uint32_t va0 = sbase + (SMEM_V + vkr * PADDH + wn2 + vnc) * 2;
#pragma unroll
            for (int kk2 = 0; kk2 < 4; ++kk2) {
                uint32_t aP[2][4];
#pragma unroll
                for (int mt = 0; mt < 2; ++mt)
                    ldsm_x4(aP[mt], pa0 + mt * (16 * PSTR * 2) + kk2 * 32);
#pragma unroll
                for (int ng2 = 0; ng2 < 4; ++ng2) {
                    uint32_t bh[4], bl[4];
                    uint32_t va = va0 + kk2 * (16 * PADDH * 2) + ng2 * 32;
                    ldsm_x4_t(bh, va);
                    ldsm_x4_t(bl, va + 8704 * 2);
#pragma unroll
                    for (int mt = 0; mt < 2; ++mt) {
                        mma_f16(oacc[mt][ng2 * 2],     aP[mt], bh[0], bh[1]);
                        mma_f16(oacc[mt][ng2 * 2 + 1], aP[mt], bh[2], bh[3]);
                        mma_f16(oacc[mt][ng2 * 2],     aP[mt], bl[0], bl[1]);
                        mma_f16(oacc[mt][ng2 * 2 + 1], aP[mt], bl[2], bl[3]);
                    }
                }
            }
        }
    }

    // epilogue: normalize; vid rows -> fp16 preproj (token order); txt rows -> fp32 atomics
#pragma unroll
    for (int mt = 0; mt < 2; ++mt)
#pragma unroll
        for (int hf = 0; hf < 2; ++hf) {
            int ql = wm + mt * 16 + g + hf * 8;
            int qg = qrow0 + ql;
            if (qg >= SEQ) continue;
            float inv = 1.f / lAcc[mt][hf];
            if (qg < WS) {
                int token = token_of(w, qg);
                __half* dst = &g_preproj_h[(long)token * DM + h * 128];
#pragma unroll
                for (int nf = 0; nf < 8; ++nf) {
                    int col = wn2 + nf * 8 + 2 * tig;
                    *reinterpret_cast<__half2*>(&dst[col]) =
                        __floats2half2_rn(oacc[mt][nf][hf * 2] * inv,
                                          oacc[mt][nf][hf * 2 + 1] * inv);
                }
            } else {
                int tr = qg - WS;
                float* dst = &g_txtacc[(long)tr * DM + h * 128];
#pragma unroll
                for (int nf = 0; nf < 8; ++nf) {
                    int col = wn2 + nf * 8 + 2 * tig;
                    atomicAdd(&dst[col],     oacc[mt][nf][hf * 2] * inv);
                    atomicAdd(&dst[col + 1], oacc[mt][nf][hf * 2 + 1] * inv);
                }
            }
        }
}

// ---------------- launch ----------------
extern "C" void kernel_launch(void* const* d_in, const int* in_sizes, int n_in,
                              void* d_out, int out_size) {
    const float* vid       = (const float*)d_in[0];
    const float* txt       = (const float*)d_in[1];
    const float* w_qkv_vid = (const float*)d_in[2];
    const float* w_qkv_txt = (const float*)d_in[3];
    const float* w_out_vid = (const float*)d_in[4];
    const float* w_out_txt = (const float*)d_in[5];
    float* out = (float*)d_out;

    cudaFuncSetAttribute(attn3_kernel, cudaFuncAttributeMaxDynamicSharedMemorySize,
                         ATTN3_SMEM_BYTES);

    float *p_qkv_v, *p_qkv_t, *p_txt;
    __half *p_pre_h, *p_vid_h, *p_wqkvT_h, *p_woutT_h;
    cudaGetSymbolAddress((void**)&p_qkv_v,   g_qkv_v);
    cudaGetSymbolAddress((void**)&p_qkv_t,   g_qkv_t);
    cudaGetSymbolAddress((void**)&p_txt,     g_txtacc);
    cudaGetSymbolAddress((void**)&p_pre_h,   g_preproj_h);
    cudaGetSymbolAddress((void**)&p_vid_h,   g_vid_h);
    cudaGetSymbolAddress((void**)&p_wqkvT_h, g_wqkvT_h);
    cudaGetSymbolAddress((void**)&p_woutT_h, g_woutT_h);

    zero_txt_kernel<<<(TXTL * DM + 255) / 256, 256>>>();

    // fp16 conversions (same rounding points as the tf32 pipeline)
    round_half_kernel<<<(N_VID * DM / 4 + 255) / 256, 256>>>(vid, p_vid_h, N_VID * DM / 4);
    transpose_round_h_kernel<<<dim3(1536 / 32, DM / 32), dim3(32, 8)>>>(w_qkv_vid, p_wqkvT_h, DM, 1536);
    transpose_round_h_kernel<<<dim3(DM / 32, DM / 32), dim3(32, 8)>>>(w_out_vid, p_woutT_h, DM, DM);

    // QKV projection (fp16 tensor cores)
    h16_gemm_kernel<<<dim3(1536 / 128, (N_VID + 127) / 128), 256>>>(
        p_vid_h, p_wqkvT_h, p_qkv_v, N_VID, 1536, DM);
    tf32_gemm_kernel<<<dim3(1536 / 128, 1), 256>>>(
        txt, w_qkv_txt, p_qkv_t, TXTL, 1536, DM, 1.f);

    // window gather + rope + V split (fp16 out)
    build_windows_kernel<<<NWIN * SEQ, 256>>>();

    // attention (fp16)
    attn3_kernel<<<dim3(7, 4, NWIN), 256, ATTN3_SMEM_BYTES>>>();

    // output projections
    h16_gemm_kernel<<<dim3(DM / 128, (N_VID + 127) / 128), 256>>>(
        p_pre_h, p_woutT_h, out, N_VID, DM, DM);
    tf32_gemm_kernel<<<dim3(DM / 128, 1), 256>>>(
        p_txt, w_out_txt, out + (long)N_VID * DM, TXTL, DM, DM, 1.f / 50.f);
}

// round 8
// speedup vs baseline: 5.3644x; 1.8293x over previous
#include <cuda_runtime.h>
#include <cuda_fp16.h>
#include <math.h>
#include <stdint.h>

#define N_VID 36000
#define DM    512
#define NWIN  50
#define WS    720
#define SEQ   784
#define TXTL  64

// ---------------- scratch (static device allocations; no cudaMalloc) ----------------
__device__ float  g_qkv_t[TXTL * 1536];         // txt QKV (fp32)
__device__ __half g_Qw_h[NWIN * SEQ * DM];      // windowed Q (rope, fp16)
__device__ __half g_Kw_h[NWIN * SEQ * DM];
__device__ __half g_Vhi_h[NWIN * SEQ * DM];     // V (fp16, single rounding)
__device__ __half g_preproj_h[N_VID * DM];      // attn out, token order (fp16)
__device__ float  g_txtacc[TXTL * DM];          // txt attn out (fp32)
__device__ __half g_vid_h[N_VID * DM];          // fp16 vid
__device__ __half g_wqkvT_h[1536 * DM];         // w_qkv_vid^T [N][K] fp16
__device__ __half g_woutT_h[DM * DM];           // w_out_vid^T [N][K] fp16
__device__ float  g_invfreq[64];                // rope inverse frequencies per d-pair

__device__ __forceinline__ int token_of(int w, int p) {
    int it = w & 1;
    int ih = (w >> 1) % 5;
    int iw = w / 10;
    int tl = p / 144;
    int rem = p % 144;
    int hl = rem >> 4;
    int wl = rem & 15;
    return ((it * 5 + tl) * 45 + (ih * 9 + hl)) * 80 + (iw * 16 + wl);
}

__device__ __forceinline__ float to_tf32(float x) {
    float r;
    asm("cvt.rna.tf32.f32 %0, %1;" : "=f"(r) : "f"(x));
    return r;
}

// tf32 mma (kept for small txt GEMMs)
__device__ __forceinline__ void mma_tf32(float* c, unsigned a0, unsigned a1,
                                         unsigned a2, unsigned a3,
                                         unsigned b0, unsigned b1) {
    asm volatile(
        "mma.sync.aligned.m16n8k8.row.col.f32.tf32.tf32.f32 "
        "{%0,%1,%2,%3}, {%4,%5,%6,%7}, {%8,%9}, {%0,%1,%2,%3};"
        : "+f"(c[0]), "+f"(c[1]), "+f"(c[2]), "+f"(c[3])
        : "r"(a0), "r"(a1), "r"(a2), "r"(a3), "r"(b0), "r"(b1));
}

// fp16 mma, fp32 accum
__device__ __forceinline__ void mma_f16(float* c, const uint32_t* a,
                                        uint32_t b0, uint32_t b1) {
    asm volatile(
        "mma.sync.aligned.m16n8k16.row.col.f32.f16.f16.f32 "
        "{%0,%1,%2,%3}, {%4,%5,%6,%7}, {%8,%9}, {%0,%1,%2,%3};"
        : "+f"(c[0]), "+f"(c[1]), "+f"(c[2]), "+f"(c[3])
        : "r"(a[0]), "r"(a[1]), "r"(a[2]), "r"(a[3]), "r"(b0), "r"(b1));
}

__device__ __forceinline__ void ldsm_x4(uint32_t* r, uint32_t addr) {
    asm volatile("ldmatrix.sync.aligned.m8n8.x4.shared.b16 {%0,%1,%2,%3}, [%4];"
                 : "=r"(r[0]), "=r"(r[1]), "=r"(r[2]), "=r"(r[3]) : "r"(addr));
}
__device__ __forceinline__ void ldsm_x4_t(uint32_t* r, uint32_t addr) {
    asm volatile("ldmatrix.sync.aligned.m8n8.x4.trans.shared.b16 {%0,%1,%2,%3}, [%4];"
                 : "=r"(r[0]), "=r"(r[1]), "=r"(r[2]), "=r"(r[3]) : "r"(addr));
}

__device__ __forceinline__ uint32_t smem_u32(const void* p) {
    return (uint32_t)__cvta_generic_to_shared(p);
}

// cp.async helpers (16B; invalid -> zero-fill)
__device__ __forceinline__ void cp_async16(void* smem_dst, const void* gsrc, bool valid) {
    unsigned saddr = (unsigned)__cvta_generic_to_shared(smem_dst);
    int sz = valid ? 16 : 0;
    asm volatile("cp.async.cg.shared.global [%0], [%1], 16, %2;\n"
                 :: "r"(saddr), "l"(gsrc), "r"(sz));
}
__device__ __forceinline__ void cp_commit() {
    asm volatile("cp.async.commit_group;\n" ::);
}
template <int N>
__device__ __forceinline__ void cp_wait() {
    asm volatile("cp.async.wait_group %0;\n" :: "n"(N));
}

// ---------------- rope inverse-frequency table ----------------
__global__ void init_invfreq_kernel() {
    int i = threadIdx.x;   // 64
    int d0 = 2 * i;
    int dl, da;
    if (d0 < 32)      { dl = d0;      da = 32; }
    else if (d0 < 80) { dl = d0 - 32; da = 48; }
    else              { dl = d0 - 80; da = 48; }
    g_invfreq[i] = powf(10000.0f, -((float)dl) / (float)da);
}

// ---------------- round fp32 -> fp16, elementwise ----------------
__global__ void round_half_kernel(const float* __restrict__ src, __half* __restrict__ dst, int n4) {
    int i = blockIdx.x * 256 + threadIdx.x;
    if (i < n4) {
        float4 v = reinterpret_cast<const float4*>(src)[i];
        reinterpret_cast<__half2*>(dst)[2 * i]     = __floats2half2_rn(v.x, v.y);
        reinterpret_cast<__half2*>(dst)[2 * i + 1] = __floats2half2_rn(v.z, v.w);
    }
}

// ---------------- transpose + round weights: w[K][N] fp32 -> wt[N][K] fp16 ----------------
__global__ void transpose_round_h_kernel(const float* __restrict__ w, __half* __restrict__ wt,
                                         int K, int N) {
    __shared__ float t[32][33];
    int nb = blockIdx.x * 32, kb = blockIdx.y * 32;
    int tx = threadIdx.x, ty = threadIdx.y;   // 32 x 8
#pragma unroll
    for (int j = 0; j < 4; ++j)
        t[ty + j * 8][tx] = w[(long)(kb + ty + j * 8) * N + nb + tx];
    __syncthreads();
#pragma unroll
    for (int j = 0; j < 4; ++j)
        wt[(long)(nb + ty + j * 8) * K + kb + tx] = __float2half_rn(t[tx][ty + j * 8]);
}

// ============= fp16 tensor-core GEMM: C[M,N] = A[M,K] @ Bt[N,K]^T =============
// 128x128 CTA tile, BK=32, 256 threads, 8 warps 64x32, m16n8k16, ldmatrix, cp.async 2-stage.
// FUSED=true: QKV projection — epilogue applies 3D RoPE and scatters directly into the
// windowed fp16 Q/K/V arrays (identical math/rounding to the former build_windows path).
#define GH_STRIDE 40   // halves per row (32 + 8 pad); 80B, conflict-free for ldmatrix
template <bool FUSED>
__global__ void __launch_bounds__(256) h16_gemm_t(
    const __half* __restrict__ A, const __half* __restrict__ Bt, float* __restrict__ C,
    int M, int N, int K)
{
    __shared__ __half sA[2][128 * GH_STRIDE];
    __shared__ __half sB[2][128 * GH_STRIDE];

    const int tid  = threadIdx.x;
    const int warp = tid >> 5, lane = tid & 31;
    const int g = lane >> 2, tig = lane & 3;
    const int lr = lane & 15, lk = (lane >> 4) * 8;
    const int wm = (warp & 1) * 64;
    const int wn = (warp >> 1) * 32;
    const int rowBase = blockIdx.y * 128;
    const int colBase = blockIdx.x * 128;
    const int nIter = K / 32;

    float c[4][4][4];
#pragma unroll
    for (int mt = 0; mt < 4; ++mt)
#pragma unroll
        for (int nt = 0; nt < 4; ++nt)
#pragma unroll
            for (int i = 0; i < 4; ++i) c[mt][nt][i] = 0.f;

    // prologue: stage 0
#pragma unroll
    for (int i = 0; i < 2; ++i) {
        int idx = tid + i * 256;
        int r = idx >> 2, o = idx & 3;
        int grow = rowBase + r;
        cp_async16(&sA[0][r * GH_STRIDE + o * 8], &A[(long)grow * K + o * 8], grow < M);
        cp_async16(&sB[0][r * GH_STRIDE + o * 8], &Bt[(long)(colBase + r) * K + o * 8], true);
    }
    cp_commit();

    for (int it = 0; it < nIter; ++it) {
        int b = it & 1;
        if (it + 1 < nIter) {
            int k0 = (it + 1) * 32;
            int bn = (it + 1) & 1;
#pragma unroll
            for (int i = 0; i < 2; ++i) {
                int idx = tid + i * 256;
                int r = idx >> 2, o = idx & 3;
                int grow = rowBase + r;
                cp_async16(&sA[bn][r * GH_STRIDE + o * 8], &A[(long)grow * K + k0 + o * 8], grow < M);
                cp_async16(&sB[bn][r * GH_STRIDE + o * 8], &Bt[(long)(colBase + r) * K + k0 + o * 8], true);
            }
            cp_commit();
            cp_wait<1>();
        } else {
            cp_wait<0>();
        }
        __syncthreads();

        uint32_t aBase = smem_u32(&sA[b][0]) + ((wm + lr) * GH_STRIDE + lk) * 2;
        uint32_t bBase = smem_u32(&sB[b][0]) + ((wn + lr) * GH_STRIDE + lk) * 2;
#pragma unroll
        for (int s = 0; s < 2; ++s) {
            uint32_t af[4][4];
#pragma unroll
            for (int mt = 0; mt < 4; ++mt)
                ldsm_x4(af[mt], aBase + mt * (16 * GH_STRIDE * 2) + s * 32);
#pragma unroll
            for (int np = 0; np < 2; ++np) {
                uint32_t bf[4];
                ldsm_x4(bf, bBase + np * (16 * GH_STRIDE * 2) + s * 32);
#pragma unroll
                for (int mt = 0; mt < 4; ++mt) {
                    mma_f16(c[mt][np * 2],     af[mt], bf[0], bf[2]);
                    mma_f16(c[mt][np * 2 + 1], af[mt], bf[1], bf[3]);
                }
            }
        }
        __syncthreads();
    }

    if (!FUSED) {
        // standard epilogue: fp32 C
#pragma unroll
        for (int mt = 0; mt < 4; ++mt) {
#pragma unroll
            for (int nt = 0; nt < 4; ++nt) {
                int row0 = rowBase + wm + mt * 16 + g;
                int col = colBase + wn + nt * 8 + 2 * tig;
                if (row0 < M) {
                    float2 o = make_float2(c[mt][nt][0], c[mt][nt][1]);
                    *reinterpret_cast<float2*>(&C[(long)row0 * N + col]) = o;
                }
                int row1 = row0 + 8;
                if (row1 < M) {
                    float2 o = make_float2(c[mt][nt][2], c[mt][nt][3]);
                    *reinterpret_cast<float2*>(&C[(long)row1 * N + col]) = o;
                }
            }
        }
    } else {
        // fused QKV epilogue: rope + window scatter, fp16 out
#pragma unroll
        for (int mt = 0; mt < 4; ++mt) {
#pragma unroll
            for (int hr = 0; hr < 2; ++hr) {
                int token = rowBase + wm + mt * 16 + g + hr * 8;
                if (token >= M) continue;
                int t = token / 3600, rem = token % 3600;
                int hh = rem / 80, ww2 = rem % 80;
                int it2 = t / 5, tl = t % 5;
                int ih = hh / 9, hl = hh % 9;
                int iw = ww2 >> 4, wl = ww2 & 15;
                int wwin = iw * 10 + ih * 2 + it2;
                int p = tl * 144 + hl * 16 + wl;
                long rowout = ((long)(wwin * SEQ + p)) * 4;
#pragma unroll
                for (int nt = 0; nt < 4; ++nt) {
                    int col = colBase + wn + nt * 8 + 2 * tig;
                    int section = col >> 9;          // uniform per block
                    int head = (col >> 7) & 3;       // uniform per block
                    int d = col & 127;
                    float x0 = c[mt][nt][hr * 2], x1 = c[mt][nt][hr * 2 + 1];
                    long ob = (rowout + head) * 128 + d;
                    if (section == 2) {
                        *reinterpret_cast<__half2*>(&g_Vhi_h[ob]) = __floats2half2_rn(x0, x1);
                    } else {
                        float pos;
                        if (d < 32)      pos = (float)t;
                        else if (d < 80) pos = (float)hh;
                        else             pos = (float)ww2;
                        float ang = pos * g_invfreq[d >> 1];
                        float s = __sinf(ang), cc = __cosf(ang);
                        __half2 o = __floats2half2_rn(x0 * cc - x1 * s, x1 * cc + x0 * s);
                        if (section == 0)
                            *reinterpret_cast<__half2*>(&g_Qw_h[ob]) = o;
                        else
                            *reinterpret_cast<__half2*>(&g_Kw_h[ob]) = o;
                    }
                }
            }
        }
    }
}

// ---------------- old tf32 GEMM — small txt GEMMs only ----------------
#define SA_STRIDE 36
#define SB_STRIDE 136
__global__ void __launch_bounds__(256) tf32_gemm_kernel(
    const float* __restrict__ A, const float* __restrict__ B, float* __restrict__ C,
    int M, int N, int K, float alpha)
{
    __shared__ float sA[128 * SA_STRIDE];
    __shared__ float sB[32 * SB_STRIDE];

    const int tid  = threadIdx.x;
    const int warp = tid >> 5, lane = tid & 31;
    const int g = lane >> 2, tig = lane & 3;
    const int wm = (warp & 1) * 64;
    const int wn = (warp >> 1) * 32;
    const int rowBase = blockIdx.y * 128;
    const int colBase = blockIdx.x * 128;

    float c[4][4][4];
#pragma unroll
    for (int mt = 0; mt < 4; ++mt)
#pragma unroll
        for (int nt = 0; nt < 4; ++nt)
#pragma unroll
            for (int i = 0; i < 4; ++i) c[mt][nt][i] = 0.f;

    float4 pa[4], pb[4];
#pragma unroll
    for (int i = 0; i < 4; ++i) {
        int idx = tid + i * 256;
        int r = idx >> 3, c4 = idx & 7;
        int grow = rowBase + r;
        pa[i] = (grow < M) ? *reinterpret_cast<const float4*>(&A[(long)grow * K + c4 * 4])
                           : make_float4(0.f, 0.f, 0.f, 0.f);
        int rb = idx >> 5, cb4 = idx & 31;
        pb[i] = *reinterpret_cast<const float4*>(&B[(long)rb * N + colBase + cb4 * 4]);
    }

    const int nIter = K / 32;
    for (int it = 0; it < nIter; ++it) {
#pragma unroll
        for (int i = 0; i < 4; ++i) {
            int idx = tid + i * 256;
            int r = idx >> 3, c4 = idx & 7;
            float* d = &sA[r * SA_STRIDE + c4 * 4];
            d[0] = to_tf32(pa[i].x); d[1] = to_tf32(pa[i].y);
            d[2] = to_tf32(pa[i].z); d[3] = to_tf32(pa[i].w);
            int rb = idx >> 5, cb4 = idx & 31;
            float* db = &sB[rb * SB_STRIDE + cb4 * 4];
            db[0] = to_tf32(pb[i].x); db[1] = to_tf32(pb[i].y);
            db[2] = to_tf32(pb[i].z); db[3] = to_tf32(pb[i].w);
        }
        __syncthreads();

        if (it + 1 < nIter) {
            int k0 = (it + 1) * 32;
#pragma unroll
            for (int i = 0; i < 4; ++i) {
                int idx = tid + i * 256;
                int r = idx >> 3, c4 = idx & 7;
                int grow = rowBase + r;
                pa[i] = (grow < M) ? *reinterpret_cast<const float4*>(&A[(long)grow * K + k0 + c4 * 4])
                                   : make_float4(0.f, 0.f, 0.f, 0.f);
                int rb = idx >> 5, cb4 = idx & 31;
                pb[i] = *reinterpret_cast<const float4*>(&B[(long)(k0 + rb) * N + colBase + cb4 * 4]);
            }
        }

#pragma unroll
        for (int kk = 0; kk < 4; ++kk) {
            unsigned int af[4][4], bf[4][2];
#pragma unroll
            for (int mt = 0; mt < 4; ++mt) {
                int r0 = wm + mt * 16 + g;
                af[mt][0] = __float_as_uint(sA[r0 * SA_STRIDE + kk * 8 + tig]);
                af[mt][1] = __float_as_uint(sA[(r0 + 8) * SA_STRIDE + kk * 8 + tig]);
                af[mt][2] = __float_as_uint(sA[r0 * SA_STRIDE + kk * 8 + tig + 4]);
                af[mt][3] = __float_as_uint(sA[(r0 + 8) * SA_STRIDE + kk * 8 + tig + 4]);
            }
#pragma unroll
            for (int nt = 0; nt < 4; ++nt) {
                int cn = wn + nt * 8 + g;
                bf[nt][0] = __float_as_uint(sB[(kk * 8 + tig) * SB_STRIDE + cn]);
                bf[nt][1] = __float_as_uint(sB[(kk * 8 + tig + 4) * SB_STRIDE + cn]);
            }
#pragma unroll
            for (int mt = 0; mt < 4; ++mt)
#pragma unroll
                for (int nt = 0; nt < 4; ++nt)
                    mma_tf32(c[mt][nt], af[mt][0], af[mt][1], af[mt][2], af[mt][3],
                             bf[nt][0], bf[nt][1]);
        }
        __syncthreads();
    }

#pragma unroll
    for (int mt = 0; mt < 4; ++mt) {
#pragma unroll
        for (int nt = 0; nt < 4; ++nt) {
            int row0 = rowBase + wm + mt * 16 + g;
            int col = colBase + wn + nt * 8 + 2 * tig;
            if (row0 < M) {
                float2 o = make_float2(c[mt][nt][0] * alpha, c[mt][nt][1] * alpha);
                *reinterpret_cast<float2*>(&C[(long)row0 * N + col]) = o;
            }
            int row1 = row0 + 8;
            if (row1 < M) {
                float2 o = make_float2(c[mt][nt][2] * alpha, c[mt][nt][3] * alpha);
                *reinterpret_cast<float2*>(&C[(long)row1 * N + col]) = o;
            }
        }
    }
}

// ---------------- zero the txt accumulator ----------------
__global__ void zero_txt_kernel() {
    int i = blockIdx.x * 256 + threadIdx.x;
    if (i < TXTL * DM) g_txtacc[i] = 0.f;
}

// ---------------- broadcast txt qkv rows into all windows (no rope) ----------------
__global__ void __launch_bounds__(256) txt_broadcast_kernel() {
    int w = blockIdx.x, tr = blockIdx.y;
    int tid = threadIdx.x;
    int h = tid >> 6, pr = tid & 63;
    int d0 = pr * 2;
    const float* base = &g_qkv_t[(long)tr * 1536 + h * 128];
    float q0 = base[d0],        q1 = base[d0 + 1];
    float k0 = base[512 + d0],  k1 = base[512 + d0 + 1];
    float v0 = base[1024 + d0], v1 = base[1024 + d0 + 1];
    long ob = ((long)(w * SEQ + WS + tr) * 4 + h) * 128 + d0;
    *reinterpret_cast<__half2*>(&g_Qw_h[ob])  = __floats2half2_rn(q0, q1);
    *reinterpret_cast<__half2*>(&g_Kw_h[ob])  = __floats2half2_rn(k0, k1);
    *reinterpret_cast<__half2*>(&g_Vhi_h[ob]) = __floats2half2_rn(v0, v1);
}

// ---------------- fp16 flash attention: QT=128, KT=64, ldmatrix, cp.async ----------------
#define QT2   128
#define KT2   64
#define PADDH 136   // halves stride for Q/K/V rows (128+8); 272B
#define PSTR  72    // halves stride for P rows (64+8); 144B
#define NKT   13
// smem halves: sQ 128*136=17408 @0 | sK 2 bufs of 9216 @17408 | sV 64*136=8704 @35840
// => 44544 halves = 89088 B; floats: sPart @89088, sSum @90112 => total 91136 B
#define SMEM_K0   17408
#define SMEM_KBUF 9216
#define SMEM_V    35840
#define ATTN3_SMEM_BYTES 91136

__global__ void __launch_bounds__(256) attn3_kernel() {
    extern __shared__ char smraw[];
    __half* sh = (__half*)smraw;
    float* sPart = (float*)(smraw + 89088);
    float* sSum  = (float*)(smraw + 90112);
    const uint32_t sbase = smem_u32(sh);

    const float NEGINF = __int_as_float(0xff800000);
    const float scale = 0.08838834764831843f;  // 1/sqrt(128)

    int qt = blockIdx.x, h = blockIdx.y, w = blockIdx.z;
    int tid = threadIdx.x;
    const int warp = tid >> 5, lane = tid & 31;
    const int g = lane >> 2, tig = lane & 3;
    const int lr = lane & 15, lk = (lane >> 4) * 8;
    const int wm = (warp & 3) * 32;
    const int ng = warp >> 2;
    const int wn1 = ng * 32;
    const int wn2 = ng * 64;

    const long gbase = ((long)(w * SEQ) * 4 + h) * 128;
    const int qrow0 = qt * QT2;

    // prologue: Q + K0, one commit group
#pragma unroll
    for (int i = 0; i < 8; ++i) {
        int idx = tid + i * 256;
        int r = idx >> 4, o = idx & 15;
        cp_async16(&sh[r * PADDH + o * 8],
                   &g_Qw_h[gbase + (long)(qrow0 + r) * 512 + o * 8], qrow0 + r < SEQ);
    }
#pragma unroll
    for (int i = 0; i < 4; ++i) {
        int idx = tid + i * 256;
        int r = idx >> 4, o = idx & 15;
        cp_async16(&sh[SMEM_K0 + r * PADDH + o * 8],
                   &g_Kw_h[gbase + (long)r * 512 + o * 8], r < SEQ);
    }
    cp_commit();

    float oacc[2][8][4];
#pragma unroll
    for (int mt = 0; mt < 2; ++mt)
#pragma unroll
        for (int nf = 0; nf < 8; ++nf)
#pragma unroll
            for (int i = 0; i < 4; ++i) oacc[mt][nf][i] = 0.f;

    float mOld[2][2], lAcc[2][2];
#pragma unroll
    for (int mt = 0; mt < 2; ++mt)
#pragma unroll
        for (int hf = 0; hf < 2; ++hf) { mOld[mt][hf] = NEGINF; lAcc[mt][hf] = 0.f; }

    for (int kt = 0; kt < NKT; ++kt) {
        const int b = kt & 1;
        __half* sKb = sh + SMEM_K0 + b * SMEM_KBUF;
        __half* sP  = sKb;   // overlay after K consumed

        __syncthreads();   // phase2(kt-1) done: sV free; prior K buf free

        // issue V[kt]
        {
            int kb = kt * KT2;
#pragma unroll
            for (int i = 0; i < 4; ++i) {
                int idx = tid + i * 256;
                int r = idx >> 4, o = idx & 15;
                cp_async16(&sh[SMEM_V + r * PADDH + o * 8],
                           &g_Vhi_h[gbase + (long)(kb + r) * 512 + o * 8], kb + r < SEQ);
            }
            cp_commit();
        }
        // issue K[kt+1]
        if (kt + 1 < NKT) {
            int kb = (kt + 1) * KT2;
            __half* sKn = sh + SMEM_K0 + ((kt + 1) & 1) * SMEM_KBUF;
#pragma unroll
            for (int i = 0; i < 4; ++i) {
                int idx = tid + i * 256;
                int r = idx >> 4, o = idx & 15;
                cp_async16(&sKn[r * PADDH + o * 8],
                           &g_Kw_h[gbase + (long)(kb + r) * 512 + o * 8], kb + r < SEQ);
            }
            cp_commit();
            cp_wait<2>();   // K[kt] complete
        } else {
            cp_wait<1>();
        }
        __syncthreads();

        // ---- phase 1: S = Q @ K^T (warp tile 32x32, 8 k16-steps) ----
        float sacc[2][4][4];
#pragma unroll
        for (int mt = 0; mt < 2; ++mt)
#pragma unroll
            for (int nf = 0; nf < 4; ++nf)
#pragma unroll
                for (int i = 0; i < 4; ++i) sacc[mt][nf][i] = 0.f;

        {
            uint32_t qa0 = sbase + ((wm + lr) * PADDH + lk) * 2;
            uint32_t ka0 = smem_u32(sKb) + ((wn1 + lr) * PADDH + lk) * 2;
#pragma unroll
            for (int kk = 0; kk < 8; ++kk) {
                uint32_t aQ[2][4];
#pragma unroll
                for (int mt = 0; mt < 2; ++mt)
                    ldsm_x4(aQ[mt], qa0 + mt * (16 * PADDH * 2) + kk * 32);
#pragma unroll
                for (int np = 0; np < 2; ++np) {
                    uint32_t bK[4];
                    ldsm_x4(bK, ka0 + np * (16 * PADDH * 2) + kk * 32);
#pragma unroll
                    for (int mt = 0; mt < 2; ++mt) {
                        mma_f16(sacc[mt][np * 2],     aQ[mt], bK[0], bK[2]);
                        mma_f16(sacc[mt][np * 2 + 1], aQ[mt], bK[1], bK[3]);
                    }
                }
            }
        }

        // ---- mask + per-thread partial row max ----
        bool cval[4][2];
#pragma unroll
        for (int nf = 0; nf < 4; ++nf) {
            int c0 = kt * KT2 + wn1 + nf * 8 + 2 * tig;
            cval[nf][0] = (c0 < SEQ);
            cval[nf][1] = (c0 + 1 < SEQ);
        }
        float mp[2][2];
#pragma unroll
        for (int mt = 0; mt < 2; ++mt)
#pragma unroll
            for (int hf = 0; hf < 2; ++hf) {
                float m = NEGINF;
#pragma unroll
                for (int nf = 0; nf < 4; ++nf)
#pragma unroll
                    for (int pr = 0; pr < 2; ++pr) {
                        float s = cval[nf][pr] ? sacc[mt][nf][hf * 2 + pr] * scale : NEGINF;
                        sacc[mt][nf][hf * 2 + pr] = s;
                        m = fmaxf(m, s);
                    }
                m = fmaxf(m, __shfl_xor_sync(0xffffffffu, m, 1));
                m = fmaxf(m, __shfl_xor_sync(0xffffffffu, m, 2));
                mp[mt][hf] = m;
            }
        if (tig == 0) {
#pragma unroll
            for (int mt = 0; mt < 2; ++mt)
#pragma unroll
                for (int hf = 0; hf < 2; ++hf)
                    sPart[(wm + mt * 16 + g + hf * 8) * 2 + ng] = mp[mt][hf];
        }
        __syncthreads();   // sPart visible; K buf dead -> P overlay safe

        // ---- exp + P(half) write + partial sums ----
        float aF[2][2], psum[2][2];
#pragma unroll
        for (int mt = 0; mt < 2; ++mt)
#pragma unroll
            for (int hf = 0; hf < 2; ++hf) {
                int row = wm + mt * 16 + g + hf * 8;
                float mn = fmaxf(mOld[mt][hf], fmaxf(sPart[row * 2], sPart[row * 2 + 1]));
                aF[mt][hf] = __expf(mOld[mt][hf] - mn);
                mOld[mt][hf] = mn;
                psum[mt][hf] = 0.f;
            }
#pragma unroll
        for (int mt = 0; mt < 2; ++mt)
#pragma unroll
            for (int hf = 0; hf < 2; ++hf) {
                int row = wm + mt * 16 + g + hf * 8;
                float mn = mOld[mt][hf];
#pragma unroll
                for (int nf = 0; nf < 4; ++nf) {
                    __half p0h = __float2half_rn(__expf(sacc[mt][nf][hf * 2]     - mn));
                    __half p1h = __float2half_rn(__expf(sacc[mt][nf][hf * 2 + 1] - mn));
                    psum[mt][hf] += __half2float(p0h) + __half2float(p1h);
                    int col = wn1 + nf * 8 + 2 * tig;
                    *reinterpret_cast<__half2*>(&sP[row * PSTR + col]) = __halves2half2(p0h, p1h);
                }
            }
#pragma unroll
        for (int mt = 0; mt < 2; ++mt)
#pragma unroll
            for (int hf = 0; hf < 2; ++hf) {
                float s = psum[mt][hf];
                s += __shfl_xor_sync(0xffffffffu, s, 1);
                s += __shfl_xor_sync(0xffffffffu, s, 2);
                psum[mt][hf] = s;
            }
        if (tig == 0) {
#pragma unroll
            for (int mt = 0; mt < 2; ++mt)
#pragma unroll
                for (int hf = 0; hf < 2; ++hf)
                    sSum[(wm + mt * 16 + g + hf * 8) * 2 + ng] = psum[mt][hf];
        }
        if (kt + 1 < NKT) cp_wait<1>(); else cp_wait<0>();   // V[kt] arrived
        __syncthreads();   // P + sSum + V visible

        // ---- l update + rescale O ----
#pragma unroll
        for (int mt = 0; mt < 2; ++mt)
#pragma unroll
            for (int hf = 0; hf < 2; ++hf) {
                int row = wm + mt * 16 + g + hf * 8;
                lAcc[mt][hf] = lAcc[mt][hf] * aF[mt][hf] + sSum[row * 2] + sSum[row * 2 + 1];
            }
#pragma unroll
        for (int mt = 0; mt < 2; ++mt)
#pragma unroll
            for (int nf = 0; nf < 8; ++nf) {
                oacc[mt][nf][0] *= aF[mt][0]; oacc[mt][nf][1] *= aF[mt][0];
                oacc[mt][nf][2] *= aF[mt][1]; oacc[mt][nf][3] *= aF[mt][1];
            }

        // ---- phase 2: O += P @ V, warp tile 32x64, 4 k16-steps ----
        {
            uint32_t pa0 = smem_u32(sP) + ((wm + lr) * PSTR + lk) * 2;
            int vkr = ((lane >> 3) & 1) * 8 + (lane & 7);
            int vnc = (lane >> 4) * 8;
            uint32_t va0 = sbase + (SMEM_V + vkr * PADDH + wn2 + vnc) * 2;
#pragma unroll
            for (int kk2 = 0; kk2 < 4; ++kk2) {
                uint32_t aP[2][4];
#pragma unroll
                for (int mt = 0; mt < 2; ++mt)
                    ldsm_x4(aP[mt], pa0 + mt * (16 * PSTR * 2) + kk2 * 32);
#pragma unroll
                for (int ng2 = 0; ng2 < 4; ++ng2) {
                    uint32_t bh[4];
                    ldsm_x4_t(bh, va0 + kk2 * (16 * PADDH * 2) + ng2 * 32);
#pragma unroll
                    for (int mt = 0; mt < 2; ++mt) {
                        mma_f16(oacc[mt][ng2 * 2],     aP[mt], bh[0], bh[1]);
                        mma_f16(oacc[mt][ng2 * 2 + 1], aP[mt], bh[2], bh[3]);
                    }
                }
            }
        }
    }

    // epilogue: normalize; vid rows -> fp16 preproj (token order); txt rows -> fp32 atomics
#pragma unroll
    for (int mt = 0; mt < 2; ++mt)
#pragma unroll
        for (int hf = 0; hf < 2; ++hf) {
            int ql = wm + mt * 16 + g + hf * 8;
            int qg = qrow0 + ql;
            if (qg >= SEQ) continue;
            float inv = 1.f / lAcc[mt][hf];
            if (qg < WS) {
                int token = token_of(w, qg);
                __half* dst = &g_preproj_h[(long)token * DM + h * 128];
#pragma unroll
                for (int nf = 0; nf < 8; ++nf) {
                    int col = wn2 + nf * 8 + 2 * tig;
                    *reinterpret_cast<__half2*>(&dst[col]) =
                        __floats2half2_rn(oacc[mt][nf][hf * 2] * inv,
                                          oacc[mt][nf][hf * 2 + 1] * inv);
                }
            } else {
                int tr = qg - WS;
                float* dst = &g_txtacc[(long)tr * DM + h * 128];
#pragma unroll
                for (int nf = 0; nf < 8; ++nf) {
                    int col = wn2 + nf * 8 + 2 * tig;
                    atomicAdd(&dst[col],     oacc[mt][nf][hf * 2] * inv);
                    atomicAdd(&dst[col + 1], oacc[mt][nf][hf * 2 + 1] * inv);
                }
            }
        }
}

// ---------------- launch ----------------
extern "C" void kernel_launch(void* const* d_in, const int* in_sizes, int n_in,
                              void* d_out, int out_size) {
    const float* vid       = (const float*)d_in[0];
    const float* txt       = (const float*)d_in[1];
    const float* w_qkv_vid = (const float*)d_in[2];
    const float* w_qkv_txt = (const float*)d_in[3];
    const float* w_out_vid = (const float*)d_in[4];
    const float* w_out_txt = (const float*)d_in[5];
    float* out = (float*)d_out;

    cudaFuncSetAttribute(attn3_kernel, cudaFuncAttributeMaxDynamicSharedMemorySize,
                         ATTN3_SMEM_BYTES);

    float *p_qkv_t, *p_txt;
    __half *p_pre_h, *p_vid_h, *p_wqkvT_h, *p_woutT_h;
    cudaGetSymbolAddress((void**)&p_qkv_t,   g_qkv_t);
    cudaGetSymbolAddress((void**)&p_txt,     g_txtacc);
    cudaGetSymbolAddress((void**)&p_pre_h,   g_preproj_h);
    cudaGetSymbolAddress((void**)&p_vid_h,   g_vid_h);
    cudaGetSymbolAddress((void**)&p_wqkvT_h, g_wqkvT_h);
    cudaGetSymbolAddress((void**)&p_woutT_h, g_woutT_h);

    zero_txt_kernel<<<(TXTL * DM + 255) / 256, 256>>>();
    init_invfreq_kernel<<<1, 64>>>();

    // fp16 conversions
    round_half_kernel<<<(N_VID * DM / 4 + 255) / 256, 256>>>(vid, p_vid_h, N_VID * DM / 4);
    transpose_round_h_kernel<<<dim3(1536 / 32, DM / 32), dim3(32, 8)>>>(w_qkv_vid, p_wqkvT_h, DM, 1536);
    transpose_round_h_kernel<<<dim3(DM / 32, DM / 32), dim3(32, 8)>>>(w_out_vid, p_woutT_h, DM, DM);

    // txt QKV (fp32), then broadcast into windows
    tf32_gemm_kernel<<<dim3(1536 / 128, 1), 256>>>(
        txt, w_qkv_txt, p_qkv_t, TXTL, 1536, DM, 1.f);

    // vid QKV projection with fused rope + window scatter
    h16_gemm_t<true><<<dim3(1536 / 128, (N_VID + 127) / 128), 256>>>(
        p_vid_h, p_wqkvT_h, (float*)nullptr, N_VID, 1536, DM);

    txt_broadcast_kernel<<<dim3(NWIN, TXTL), 256>>>();

    // attention (fp16)
    attn3_kernel<<<dim3(7, 4, NWIN), 256, ATTN3_SMEM_BYTES>>>();

    // output projections
    h16_gemm_t<false><<<dim3(DM / 128, (N_VID + 127) / 128), 256>>>(
        p_pre_h, p_woutT_h, out, N_VID, DM, DM);
    tf32_gemm_kernel<<<dim3(DM / 128, 1), 256>>>(
        p_txt, w_out_txt, out + (long)N_VID * DM, TXTL, DM, DM, 1.f / 50.f);
}

// round 9
// speedup vs baseline: 5.5424x; 1.0332x over previous
#include <cuda_runtime.h>
#include <cuda_fp16.h>
#include <math.h>
#include <stdint.h>

#define N_VID 36000
#define DM    512
#define NWIN  50
#define WS    720
#define SEQ   784
#define TXTL  64

// ---------------- scratch (static device allocations; no cudaMalloc) ----------------
__device__ float  g_qkv_t[TXTL * 1536];         // txt QKV (fp32)
__device__ __half g_Qw_h[NWIN * SEQ * DM];      // windowed Q (rope, fp16)
__device__ __half g_Kw_h[NWIN * SEQ * DM];
__device__ __half g_Vhi_h[NWIN * SEQ * DM];     // V (fp16)
__device__ __half g_preproj_h[N_VID * DM];      // attn out, token order (fp16)
__device__ float  g_txtacc[TXTL * DM];          // txt attn out (fp32)
__device__ __half g_vid_h[N_VID * DM];          // fp16 vid
__device__ __half g_wqkvT_h[1536 * DM];         // w_qkv_vid^T [N][K] fp16
__device__ __half g_woutT_h[DM * DM];           // w_out_vid^T [N][K] fp16
__device__ float  g_invfreq[64];                // rope inverse frequencies per d-pair

__device__ __forceinline__ int token_of(int w, int p) {
    int it = w & 1;
    int ih = (w >> 1) % 5;
    int iw = w / 10;
    int tl = p / 144;
    int rem = p % 144;
    int hl = rem >> 4;
    int wl = rem & 15;
    return ((it * 5 + tl) * 45 + (ih * 9 + hl)) * 80 + (iw * 16 + wl);
}

__device__ __forceinline__ float to_tf32(float x) {
    float r;
    asm("cvt.rna.tf32.f32 %0, %1;" : "=f"(r) : "f"(x));
    return r;
}

// tf32 mma (kept for small txt GEMMs)
__device__ __forceinline__ void mma_tf32(float* c, unsigned a0, unsigned a1,
                                         unsigned a2, unsigned a3,
                                         unsigned b0, unsigned b1) {
    asm volatile(
        "mma.sync.aligned.m16n8k8.row.col.f32.tf32.tf32.f32 "
        "{%0,%1,%2,%3}, {%4,%5,%6,%7}, {%8,%9}, {%0,%1,%2,%3};"
        : "+f"(c[0]), "+f"(c[1]), "+f"(c[2]), "+f"(c[3])
        : "r"(a0), "r"(a1), "r"(a2), "r"(a3), "r"(b0), "r"(b1));
}

// fp16 mma, fp32 accum
__device__ __forceinline__ void mma_f16(float* c, const uint32_t* a,
                                        uint32_t b0, uint32_t b1) {
    asm volatile(
        "mma.sync.aligned.m16n8k16.row.col.f32.f16.f16.f32 "
        "{%0,%1,%2,%3}, {%4,%5,%6,%7}, {%8,%9}, {%0,%1,%2,%3};"
        : "+f"(c[0]), "+f"(c[1]), "+f"(c[2]), "+f"(c[3])
        : "r"(a[0]), "r"(a[1]), "r"(a[2]), "r"(a[3]), "r"(b0), "r"(b1));
}

__device__ __forceinline__ void ldsm_x4(uint32_t* r, uint32_t addr) {
    asm volatile("ldmatrix.sync.aligned.m8n8.x4.shared.b16 {%0,%1,%2,%3}, [%4];"
                 : "=r"(r[0]), "=r"(r[1]), "=r"(r[2]), "=r"(r[3]) : "r"(addr));
}
__device__ __forceinline__ void ldsm_x4_t(uint32_t* r, uint32_t addr) {
    asm volatile("ldmatrix.sync.aligned.m8n8.x4.trans.shared.b16 {%0,%1,%2,%3}, [%4];"
                 : "=r"(r[0]), "=r"(r[1]), "=r"(r[2]), "=r"(r[3]) : "r"(addr));
}

// packed fp16x2 exp2 via MUFU (one op per two elements)
__device__ __forceinline__ uint32_t h2exp2_u(uint32_t x) {
    uint32_t r;
    asm("ex2.approx.f16x2 %0, %1;" : "=r"(r) : "r"(x));
    return r;
}

__device__ __forceinline__ uint32_t smem_u32(const void* p) {
    return (uint32_t)__cvta_generic_to_shared(p);
}

// cp.async helpers (16B; invalid -> zero-fill)
__device__ __forceinline__ void cp_async16(void* smem_dst, const void* gsrc, bool valid) {
    unsigned saddr = (unsigned)__cvta_generic_to_shared(smem_dst);
    int sz = valid ? 16 : 0;
    asm volatile("cp.async.cg.shared.global [%0], [%1], 16, %2;\n"
                 :: "r"(saddr), "l"(gsrc), "r"(sz));
}
__device__ __forceinline__ void cp_commit() {
    asm volatile("cp.async.commit_group;\n" ::);
}
template <int N>
__device__ __forceinline__ void cp_wait() {
    asm volatile("cp.async.wait_group %0;\n" :: "n"(N));
}

// ---------------- rope inverse-frequency table ----------------
__global__ void init_invfreq_kernel() {
    int i = threadIdx.x;   // 64
    int d0 = 2 * i;
    int dl, da;
    if (d0 < 32)      { dl = d0;      da = 32; }
    else if (d0 < 80) { dl = d0 - 32; da = 48; }
    else              { dl = d0 - 80; da = 48; }
    g_invfreq[i] = powf(10000.0f, -((float)dl) / (float)da);
}

// ---------------- round fp32 -> fp16, elementwise ----------------
__global__ void round_half_kernel(const float* __restrict__ src, __half* __restrict__ dst, int n4) {
    int i = blockIdx.x * 256 + threadIdx.x;
    if (i < n4) {
        float4 v = reinterpret_cast<const float4*>(src)[i];
        reinterpret_cast<__half2*>(dst)[2 * i]     = __floats2half2_rn(v.x, v.y);
        reinterpret_cast<__half2*>(dst)[2 * i + 1] = __floats2half2_rn(v.z, v.w);
    }
}

// ---------------- transpose + round weights: w[K][N] fp32 -> wt[N][K] fp16 ----------------
__global__ void transpose_round_h_kernel(const float* __restrict__ w, __half* __restrict__ wt,
                                         int K, int N) {
    __shared__ float t[32][33];
    int nb = blockIdx.x * 32, kb = blockIdx.y * 32;
    int tx = threadIdx.x, ty = threadIdx.y;   // 32 x 8
#pragma unroll
    for (int j = 0; j < 4; ++j)
        t[ty + j * 8][tx] = w[(long)(kb + ty + j * 8) * N + nb + tx];
    __syncthreads();
#pragma unroll
    for (int j = 0; j < 4; ++j)
        wt[(long)(nb + ty + j * 8) * K + kb + tx] = __float2half_rn(t[tx][ty + j * 8]);
}

// ============= fp16 tensor-core GEMM: C[M,N] = A[M,K] @ Bt[N,K]^T =============
// 128x128 CTA tile, BK=32, 256 threads, 8 warps 64x32, m16n8k16, ldmatrix, cp.async 2-stage.
// FUSED=true: QKV projection — epilogue applies 3D RoPE and scatters into windowed arrays.
#define GH_STRIDE 40   // halves per row (32 + 8 pad)
template <bool FUSED>
__global__ void __launch_bounds__(256) h16_gemm_t(
    const __half* __restrict__ A, const __half* __restrict__ Bt, float* __restrict__ C,
    int M, int N, int K)
{
    __shared__ __half sA[2][128 * GH_STRIDE];
    __shared__ __half sB[2][128 * GH_STRIDE];

    const int tid  = threadIdx.x;
    const int warp = tid >> 5, lane = tid & 31;
    const int g = lane >> 2, tig = lane & 3;
    const int lr = lane & 15, lk = (lane >> 4) * 8;
    const int wm = (warp & 1) * 64;
    const int wn = (warp >> 1) * 32;
    const int rowBase = blockIdx.y * 128;
    const int colBase = blockIdx.x * 128;
    const int nIter = K / 32;

    float c[4][4][4];
#pragma unroll
    for (int mt = 0; mt < 4; ++mt)
#pragma unroll
        for (int nt = 0; nt < 4; ++nt)
#pragma unroll
            for (int i = 0; i < 4; ++i) c[mt][nt][i] = 0.f;

#pragma unroll
    for (int i = 0; i < 2; ++i) {
        int idx = tid + i * 256;
        int r = idx >> 2, o = idx & 3;
        int grow = rowBase + r;
        cp_async16(&sA[0][r * GH_STRIDE + o * 8], &A[(long)grow * K + o * 8], grow < M);
        cp_async16(&sB[0][r * GH_STRIDE + o * 8], &Bt[(long)(colBase + r) * K + o * 8], true);
    }
    cp_commit();

    for (int it = 0; it < nIter; ++it) {
        int b = it & 1;
        if (it + 1 < nIter) {
            int k0 = (it + 1) * 32;
            int bn = (it + 1) & 1;
#pragma unroll
            for (int i = 0; i < 2; ++i) {
                int idx = tid + i * 256;
                int r = idx >> 2, o = idx & 3;
                int grow = rowBase + r;
                cp_async16(&sA[bn][r * GH_STRIDE + o * 8], &A[(long)grow * K + k0 + o * 8], grow < M);
                cp_async16(&sB[bn][r * GH_STRIDE + o * 8], &Bt[(long)(colBase + r) * K + k0 + o * 8], true);
            }
            cp_commit();
            cp_wait<1>();
        } else {
            cp_wait<0>();
        }
        __syncthreads();

        uint32_t aBase = smem_u32(&sA[b][0]) + ((wm + lr) * GH_STRIDE + lk) * 2;
        uint32_t bBase = smem_u32(&sB[b][0]) + ((wn + lr) * GH_STRIDE + lk) * 2;
#pragma unroll
        for (int s = 0; s < 2; ++s) {
            uint32_t af[4][4];
#pragma unroll
            for (int mt = 0; mt < 4; ++mt)
                ldsm_x4(af[mt], aBase + mt * (16 * GH_STRIDE * 2) + s * 32);
#pragma unroll
            for (int np = 0; np < 2; ++np) {
                uint32_t bf[4];
                ldsm_x4(bf, bBase + np * (16 * GH_STRIDE * 2) + s * 32);
#pragma unroll
                for (int mt = 0; mt < 4; ++mt) {
                    mma_f16(c[mt][np * 2],     af[mt], bf[0], bf[2]);
                    mma_f16(c[mt][np * 2 + 1], af[mt], bf[1], bf[3]);
                }
            }
        }
        __syncthreads();
    }

    if (!FUSED) {
#pragma unroll
        for (int mt = 0; mt < 4; ++mt) {
#pragma unroll
            for (int nt = 0; nt < 4; ++nt) {
                int row0 = rowBase + wm + mt * 16 + g;
                int col = colBase + wn + nt * 8 + 2 * tig;
                if (row0 < M) {
                    float2 o = make_float2(c[mt][nt][0], c[mt][nt][1]);
                    *reinterpret_cast<float2*>(&C[(long)row0 * N + col]) = o;
                }
                int row1 = row0 + 8;
                if (row1 < M) {
                    float2 o = make_float2(c[mt][nt][2], c[mt][nt][3]);
                    *reinterpret_cast<float2*>(&C[(long)row1 * N + col]) = o;
                }
            }
        }
    } else {
        // fused QKV epilogue: rope + window scatter, fp16 out
#pragma unroll
        for (int mt = 0; mt < 4; ++mt) {
#pragma unroll
            for (int hr = 0; hr < 2; ++hr) {
                int token = rowBase + wm + mt * 16 + g + hr * 8;
                if (token >= M) continue;
                int t = token / 3600, rem = token % 3600;
                int hh = rem / 80, ww2 = rem % 80;
                int it2 = t / 5, tl = t % 5;
                int ih = hh / 9, hl = hh % 9;
                int iw = ww2 >> 4, wl = ww2 & 15;
                int wwin = iw * 10 + ih * 2 + it2;
                int p = tl * 144 + hl * 16 + wl;
                long rowout = ((long)(wwin * SEQ + p)) * 4;
#pragma unroll
                for (int nt = 0; nt < 4; ++nt) {
                    int col = colBase + wn + nt * 8 + 2 * tig;
                    int section = col >> 9;
                    int head = (col >> 7) & 3;
                    int d = col & 127;
                    float x0 = c[mt][nt][hr * 2], x1 = c[mt][nt][hr * 2 + 1];
                    long ob = (rowout + head) * 128 + d;
                    if (section == 2) {
                        *reinterpret_cast<__half2*>(&g_Vhi_h[ob]) = __floats2half2_rn(x0, x1);
                    } else {
                        float pos;
                        if (d < 32)      pos = (float)t;
                        else if (d < 80) pos = (float)hh;
                        else             pos = (float)ww2;
                        float ang = pos * g_invfreq[d >> 1];
                        float s = __sinf(ang), cc = __cosf(ang);
                        __half2 o = __floats2half2_rn(x0 * cc - x1 * s, x1 * cc + x0 * s);
                        if (section == 0)
                            *reinterpret_cast<__half2*>(&g_Qw_h[ob]) = o;
                        else
                            *reinterpret_cast<__half2*>(&g_Kw_h[ob]) = o;
                    }
                }
            }
        }
    }
}

// ---------------- old tf32 GEMM — small txt GEMMs only ----------------
#define SA_STRIDE 36
#define SB_STRIDE 136
__global__ void __launch_bounds__(256) tf32_gemm_kernel(
    const float* __restrict__ A, const float* __restrict__ B, float* __restrict__ C,
    int M, int N, int K, float alpha)
{
    __shared__ float sA[128 * SA_STRIDE];
    __shared__ float sB[32 * SB_STRIDE];

    const int tid  = threadIdx.x;
    const int warp = tid >> 5, lane = tid & 31;
    const int g = lane >> 2, tig = lane & 3;
    const int wm = (warp & 1) * 64;
    const int wn = (warp >> 1) * 32;
    const int rowBase = blockIdx.y * 128;
    const int colBase = blockIdx.x * 128;

    float c[4][4][4];
#pragma unroll
    for (int mt = 0; mt < 4; ++mt)
#pragma unroll
        for (int nt = 0; nt < 4; ++nt)
#pragma unroll
            for (int i = 0; i < 4; ++i) c[mt][nt][i] = 0.f;

    float4 pa[4], pb[4];
#pragma unroll
    for (int i = 0; i < 4; ++i) {
        int idx = tid + i * 256;
        int r = idx >> 3, c4 = idx & 7;
        int grow = rowBase + r;
        pa[i] = (grow < M) ? *reinterpret_cast<const float4*>(&A[(long)grow * K + c4 * 4])
                           : make_float4(0.f, 0.f, 0.f, 0.f);
        int rb = idx >> 5, cb4 = idx & 31;
        pb[i] = *reinterpret_cast<const float4*>(&B[(long)rb * N + colBase + cb4 * 4]);
    }

    const int nIter = K / 32;
    for (int it = 0; it < nIter; ++it) {
#pragma unroll
        for (int i = 0; i < 4; ++i) {
            int idx = tid + i * 256;
            int r = idx >> 3, c4 = idx & 7;
            float* d = &sA[r * SA_STRIDE + c4 * 4];
            d[0] = to_tf32(pa[i].x); d[1] = to_tf32(pa[i].y);
            d[2] = to_tf32(pa[i].z); d[3] = to_tf32(pa[i].w);
            int rb = idx >> 5, cb4 = idx & 31;
            float* db = &sB[rb * SB_STRIDE + cb4 * 4];
            db[0] = to_tf32(pb[i].x); db[1] = to_tf32(pb[i].y);
            db[2] = to_tf32(pb[i].z); db[3] = to_tf32(pb[i].w);
        }
        __syncthreads();

        if (it + 1 < nIter) {
            int k0 = (it + 1) * 32;
#pragma unroll
            for (int i = 0; i < 4; ++i) {
                int idx = tid + i * 256;
                int r = idx >> 3, c4 = idx & 7;
                int grow = rowBase + r;
                pa[i] = (grow < M) ? *reinterpret_cast<const float4*>(&A[(long)grow * K + k0 + c4 * 4])
                                   : make_float4(0.f, 0.f, 0.f, 0.f);
                int rb = idx >> 5, cb4 = idx & 31;
                pb[i] = *reinterpret_cast<const float4*>(&B[(long)(k0 + rb) * N + colBase + cb4 * 4]);
            }
        }

#pragma unroll
        for (int kk = 0; kk < 4; ++kk) {
            unsigned int af[4][4], bf[4][2];
#pragma unroll
            for (int mt = 0; mt < 4; ++mt) {
                int r0 = wm + mt * 16 + g;
                af[mt][0] = __float_as_uint(sA[r0 * SA_STRIDE + kk * 8 + tig]);
                af[mt][1] = __float_as_uint(sA[(r0 + 8) * SA_STRIDE + kk * 8 + tig]);
                af[mt][2] = __float_as_uint(sA[r0 * SA_STRIDE + kk * 8 + tig + 4]);
                af[mt][3] = __float_as_uint(sA[(r0 + 8) * SA_STRIDE + kk * 8 + tig + 4]);
            }
#pragma unroll
            for (int nt = 0; nt < 4; ++nt) {
                int cn = wn + nt * 8 + g;
                bf[nt][0] = __float_as_uint(sB[(kk * 8 + tig) * SB_STRIDE + cn]);
                bf[nt][1] = __float_as_uint(sB[(kk * 8 + tig + 4) * SB_STRIDE + cn]);
            }
#pragma unroll
            for (int mt = 0; mt < 4; ++mt)
#pragma unroll
                for (int nt = 0; nt < 4; ++nt)
                    mma_tf32(c[mt][nt], af[mt][0], af[mt][1], af[mt][2], af[mt][3],
                             bf[nt][0], bf[nt][1]);
        }
        __syncthreads();
    }

#pragma unroll
    for (int mt = 0; mt < 4; ++mt) {
#pragma unroll
        for (int nt = 0; nt < 4; ++nt) {
            int row0 = rowBase + wm + mt * 16 + g;
            int col = colBase + wn + nt * 8 + 2 * tig;
            if (row0 < M) {
                float2 o = make_float2(c[mt][nt][0] * alpha, c[mt][nt][1] * alpha);
                *reinterpret_cast<float2*>(&C[(long)row0 * N + col]) = o;
            }
            int row1 = row0 + 8;
            if (row1 < M) {
                float2 o = make_float2(c[mt][nt][2] * alpha, c[mt][nt][3] * alpha);
                *reinterpret_cast<float2*>(&C[(long)row1 * N + col]) = o;
            }
        }
    }
}

// ---------------- zero the txt accumulator ----------------
__global__ void zero_txt_kernel() {
    int i = blockIdx.x * 256 + threadIdx.x;
    if (i < TXTL * DM) g_txtacc[i] = 0.f;
}

// ---------------- broadcast txt qkv rows into all windows (no rope) ----------------
__global__ void __launch_bounds__(256) txt_broadcast_kernel() {
    int w = blockIdx.x, tr = blockIdx.y;
    int tid = threadIdx.x;
    int h = tid >> 6, pr = tid & 63;
    int d0 = pr * 2;
    const float* base = &g_qkv_t[(long)tr * 1536 + h * 128];
    float q0 = base[d0],        q1 = base[d0 + 1];
    float k0 = base[512 + d0],  k1 = base[512 + d0 + 1];
    float v0 = base[1024 + d0], v1 = base[1024 + d0 + 1];
    long ob = ((long)(w * SEQ + WS + tr) * 4 + h) * 128 + d0;
    *reinterpret_cast<__half2*>(&g_Qw_h[ob])  = __floats2half2_rn(q0, q1);
    *reinterpret_cast<__half2*>(&g_Kw_h[ob])  = __floats2half2_rn(k0, k1);
    *reinterpret_cast<__half2*>(&g_Vhi_h[ob]) = __floats2half2_rn(v0, v1);
}

// ---------------- fp16 flash attention: QT=128, KT=64, f16x2 exp2, l-via-MMA ----------------
#define QT2   128
#define KT2   64
#define PADDH 136   // halves stride for Q/K/V rows (128+8); 272B
#define PSTR  72    // halves stride for P rows (64+8); 144B
#define NKT   13
// smem halves: sQ 128*136=17408 @0 | sK 2 bufs of 9216 @17408 | sV 64*136=8704 @35840
// => 44544 halves = 89088 B; floats: sPart @89088 (1024B) => total 90112 B
#define SMEM_K0   17408
#define SMEM_KBUF 9216
#define SMEM_V    35840
#define ATTN3_SMEM_BYTES 90112

__global__ void __launch_bounds__(256) attn3_kernel() {
    extern __shared__ char smraw[];
    __half* sh = (__half*)smraw;
    float* sPart = (float*)(smraw + 89088);
    const uint32_t sbase = smem_u32(sh);

    const float NEGINF = __int_as_float(0xff800000);
    const float scale = 0.08838834764831843f;              // 1/sqrt(128)
    const float SL = 0.12751089f;                          // scale * log2(e)
    const uint32_t ONES2 = 0x3C003C00u;                    // half2(1.0, 1.0)

    int qt = blockIdx.x, h = blockIdx.y, w = blockIdx.z;
    int tid = threadIdx.x;
    const int warp = tid >> 5, lane = tid & 31;
    const int g = lane >> 2, tig = lane & 3;
    const int lr = lane & 15, lk = (lane >> 4) * 8;
    const int wm = (warp & 3) * 32;
    const int ng = warp >> 2;
    const int wn1 = ng * 32;
    const int wn2 = ng * 64;

    const long gbase = ((long)(w * SEQ) * 4 + h) * 128;
    const int qrow0 = qt * QT2;

    // prologue: Q + K0, one commit group
#pragma unroll
    for (int i = 0; i < 8; ++i) {
        int idx = tid + i * 256;
        int r = idx >> 4, o = idx & 15;
        cp_async16(&sh[r * PADDH + o * 8],
                   &g_Qw_h[gbase + (long)(qrow0 + r) * 512 + o * 8], qrow0 + r < SEQ);
    }
#pragma unroll
    for (int i = 0; i < 4; ++i) {
        int idx = tid + i * 256;
        int r = idx >> 4, o = idx & 15;
        cp_async16(&sh[SMEM_K0 + r * PADDH + o * 8],
                   &g_Kw_h[gbase + (long)r * 512 + o * 8], r < SEQ);
    }
    cp_commit();

    float oacc[2][8][4];
#pragma unroll
    for (int mt = 0; mt < 2; ++mt)
#pragma unroll
        for (int nf = 0; nf < 8; ++nf)
#pragma unroll
            for (int i = 0; i < 4; ++i) oacc[mt][nf][i] = 0.f;

    float lex[2][4];                        // row-sum accumulators (ones-column MMA)
#pragma unroll
    for (int mt = 0; mt < 2; ++mt)
#pragma unroll
        for (int i = 0; i < 4; ++i) lex[mt][i] = 0.f;

    float mOld[2][2];
#pragma unroll
    for (int mt = 0; mt < 2; ++mt)
#pragma unroll
        for (int hf = 0; hf < 2; ++hf) mOld[mt][hf] = NEGINF;

    for (int kt = 0; kt < NKT; ++kt) {
        const int b = kt & 1;
        __half* sKb = sh + SMEM_K0 + b * SMEM_KBUF;
        __half* sP  = sKb;   // overlay after K consumed

        __syncthreads();   // phase2(kt-1) done: sV free; prior K buf free

        // issue V[kt]
        {
            int kb = kt * KT2;
#pragma unroll
            for (int i = 0; i < 4; ++i) {
                int idx = tid + i * 256;
                int r = idx >> 4, o = idx & 15;
                cp_async16(&sh[SMEM_V + r * PADDH + o * 8],
                           &g_Vhi_h[gbase + (long)(kb + r) * 512 + o * 8], kb + r < SEQ);
            }
            cp_commit();
        }
        // issue K[kt+1]
        if (kt + 1 < NKT) {
            int kb = (kt + 1) * KT2;
            __half* sKn = sh + SMEM_K0 + ((kt + 1) & 1) * SMEM_KBUF;
#pragma unroll
            for (int i = 0; i < 4; ++i) {
                int idx = tid + i * 256;
                int r = idx >> 4, o = idx & 15;
                cp_async16(&sKn[r * PADDH + o * 8],
                           &g_Kw_h[gbase + (long)(kb + r) * 512 + o * 8], kb + r < SEQ);
            }
            cp_commit();
            cp_wait<2>();   // K[kt] complete
        } else {
            cp_wait<1>();
        }
        __syncthreads();

        // ---- phase 1: S = Q @ K^T (warp tile 32x32, 8 k16-steps) ----
        float sacc[2][4][4];
#pragma unroll
        for (int mt = 0; mt < 2; ++mt)
#pragma unroll
            for (int nf = 0; nf < 4; ++nf)
#pragma unroll
                for (int i = 0; i < 4; ++i) sacc[mt][nf][i] = 0.f;

        {
            uint32_t qa0 = sbase + ((wm + lr) * PADDH + lk) * 2;
            uint32_t ka0 = smem_u32(sKb) + ((wn1 + lr) * PADDH + lk) * 2;
#pragma unroll
            for (int kk = 0; kk < 8; ++kk) {
                uint32_t aQ[2][4];
#pragma unroll
                for (int mt = 0; mt < 2; ++mt)
                    ldsm_x4(aQ[mt], qa0 + mt * (16 * PADDH * 2) + kk * 32);
#pragma unroll
                for (int np = 0; np < 2; ++np) {
                    uint32_t bK[4];
                    ldsm_x4(bK, ka0 + np * (16 * PADDH * 2) + kk * 32);
#pragma unroll
                    for (int mt = 0; mt < 2; ++mt) {
                        mma_f16(sacc[mt][np * 2],     aQ[mt], bK[0], bK[2]);
                        mma_f16(sacc[mt][np * 2 + 1], aQ[mt], bK[1], bK[3]);
                    }
                }
            }
        }

        // ---- mask (raw scores; scale folded into exp arg) + partial row max ----
        bool cval[4][2];
#pragma unroll
        for (int nf = 0; nf < 4; ++nf) {
            int c0 = kt * KT2 + wn1 + nf * 8 + 2 * tig;
            cval[nf][0] = (c0 < SEQ);
            cval[nf][1] = (c0 + 1 < SEQ);
        }
        float mp[2][2];
#pragma unroll
        for (int mt = 0; mt < 2; ++mt)
#pragma unroll
            for (int hf = 0; hf < 2; ++hf) {
                float m = NEGINF;
#pragma unroll
                for (int nf = 0; nf < 4; ++nf)
#pragma unroll
                    for (int pr = 0; pr < 2; ++pr) {
                        float s = cval[nf][pr] ? sacc[mt][nf][hf * 2 + pr] : NEGINF;
                        sacc[mt][nf][hf * 2 + pr] = s;
                        m = fmaxf(m, s);
                    }
                m = fmaxf(m, __shfl_xor_sync(0xffffffffu, m, 1));
                m = fmaxf(m, __shfl_xor_sync(0xffffffffu, m, 2));
                mp[mt][hf] = m;
            }
        if (tig == 0) {
#pragma unroll
            for (int mt = 0; mt < 2; ++mt)
#pragma unroll
                for (int hf = 0; hf < 2; ++hf)
                    sPart[(wm + mt * 16 + g + hf * 8) * 2 + ng] = mp[mt][hf];
        }
        __syncthreads();   // sPart visible; K buf dead -> P overlay safe

        // ---- exp2.f16x2 + P(half) write ----
        float aF[2][2];
#pragma unroll
        for (int mt = 0; mt < 2; ++mt)
#pragma unroll
            for (int hf = 0; hf < 2; ++hf) {
                int row = wm + mt * 16 + g + hf * 8;
                float mn = fmaxf(mOld[mt][hf], fmaxf(sPart[row * 2], sPart[row * 2 + 1]));
                aF[mt][hf] = __expf((mOld[mt][hf] - mn) * scale);
                mOld[mt][hf] = mn;
            }
#pragma unroll
        for (int mt = 0; mt < 2; ++mt)
#pragma unroll
            for (int hf = 0; hf < 2; ++hf) {
                int row = wm + mt * 16 + g + hf * 8;
                float mnSL = mOld[mt][hf] * SL;
#pragma unroll
                for (int nf = 0; nf < 4; ++nf) {
                    float a0 = fmaf(sacc[mt][nf][hf * 2],     SL, -mnSL);
                    float a1 = fmaf(sacc[mt][nf][hf * 2 + 1], SL, -mnSL);
                    __half2 ha = __floats2half2_rn(a0, a1);
                    uint32_t p2 = h2exp2_u(*reinterpret_cast<uint32_t*>(&ha));
                    int col = wn1 + nf * 8 + 2 * tig;
                    *reinterpret_cast<uint32_t*>(&sP[row * PSTR + col]) = p2;
                }
            }
        if (kt + 1 < NKT) cp_wait<1>(); else cp_wait<0>();   // V[kt] arrived
        __syncthreads();   // P + V visible

        // ---- rescale O and l ----
#pragma unroll
        for (int mt = 0; mt < 2; ++mt) {
#pragma unroll
            for (int nf = 0; nf < 8; ++nf) {
                oacc[mt][nf][0] *= aF[mt][0]; oacc[mt][nf][1] *= aF[mt][0];
                oacc[mt][nf][2] *= aF[mt][1]; oacc[mt][nf][3] *= aF[mt][1];
            }
            lex[mt][0] *= aF[mt][0]; lex[mt][1] *= aF[mt][0];
            lex[mt][2] *= aF[mt][1]; lex[mt][3] *= aF[mt][1];
        }

        // ---- phase 2: O += P @ V (+ l += P @ ones), warp tile 32x64, 4 k16-steps ----
        {
            uint32_t pa0 = smem_u32(sP) + ((wm + lr) * PSTR + lk) * 2;
            int vkr = ((lane >> 3) & 1) * 8 + (lane & 7);
            int vnc = (lane >> 4) * 8;
            uint32_t va0 = sbase + (SMEM_V + vkr * PADDH + wn2 + vnc) * 2;
#pragma unroll
            for (int kk2 = 0; kk2 < 4; ++kk2) {
                uint32_t aP[2][4];
#pragma unroll
                for (int mt = 0; mt < 2; ++mt) {
                    ldsm_x4(aP[mt], pa0 + mt * (16 * PSTR * 2) + kk2 * 32);
                    mma_f16(lex[mt], aP[mt], ONES2, ONES2);   // row sums
                }
#pragma unroll
                for (int ng2 = 0; ng2 < 4; ++ng2) {
                    uint32_t bh[4];
                    ldsm_x4_t(bh, va0 + kk2 * (16 * PADDH * 2) + ng2 * 32);
#pragma unroll
                    for (int mt = 0; mt < 2; ++mt) {
                        mma_f16(oacc[mt][ng2 * 2],     aP[mt], bh[0], bh[1]);
                        mma_f16(oacc[mt][ng2 * 2 + 1], aP[mt], bh[2], bh[3]);
                    }
                }
            }
        }
    }

    // epilogue: normalize; vid rows -> fp16 preproj (token order); txt rows -> fp32 atomics
#pragma unroll
    for (int mt = 0; mt < 2; ++mt)
#pragma unroll
        for (int hf = 0; hf < 2; ++hf) {
            int ql = wm + mt * 16 + g + hf * 8;
            int qg = qrow0 + ql;
            if (qg >= SEQ) continue;
            float inv = 1.f / lex[mt][hf * 2];
            if (qg < WS) {
                int token = token_of(w, qg);
                __half* dst = &g_preproj_h[(long)token * DM + h * 128];
#pragma unroll
                for (int nf = 0; nf < 8; ++nf) {
                    int col = wn2 + nf * 8 + 2 * tig;
                    *reinterpret_cast<__half2*>(&dst[col]) =
                        __floats2half2_rn(oacc[mt][nf][hf * 2] * inv,
                                          oacc[mt][nf][hf * 2 + 1] * inv);
                }
            } else {
                int tr = qg - WS;
                float* dst = &g_txtacc[(long)tr * DM + h * 128];
#pragma unroll
                for (int nf = 0; nf < 8; ++nf) {
                    int col = wn2 + nf * 8 + 2 * tig;
                    atomicAdd(&dst[col],     oacc[mt][nf][hf * 2] * inv);
                    atomicAdd(&dst[col + 1], oacc[mt][nf][hf * 2 + 1] * inv);
                }
            }
        }
}

// ---------------- launch ----------------
extern "C" void kernel_launch(void* const* d_in, const int* in_sizes, int n_in,
                              void* d_out, int out_size) {
    const float* vid       = (const float*)d_in[0];
    const float* txt       = (const float*)d_in[1];
    const float* w_qkv_vid = (const float*)d_in[2];
    const float* w_qkv_txt = (const float*)d_in[3];
    const float* w_out_vid = (const float*)d_in[4];
    const float* w_out_txt = (const float*)d_in[5];
    float* out = (float*)d_out;

    cudaFuncSetAttribute(attn3_kernel, cudaFuncAttributeMaxDynamicSharedMemorySize,
                         ATTN3_SMEM_BYTES);

    float *p_qkv_t, *p_txt;
    __half *p_pre_h, *p_vid_h, *p_wqkvT_h, *p_woutT_h;
    cudaGetSymbolAddress((void**)&p_qkv_t,   g_qkv_t);
    cudaGetSymbolAddress((void**)&p_txt,     g_txtacc);
    cudaGetSymbolAddress((void**)&p_pre_h,   g_preproj_h);
    cudaGetSymbolAddress((void**)&p_vid_h,   g_vid_h);
    cudaGetSymbolAddress((void**)&p_wqkvT_h, g_wqkvT_h);
    cudaGetSymbolAddress((void**)&p_woutT_h, g_woutT_h);

    zero_txt_kernel<<<(TXTL * DM + 255) / 256, 256>>>();
    init_invfreq_kernel<<<1, 64>>>();

    // fp16 conversions
    round_half_kernel<<<(N_VID * DM / 4 + 255) / 256, 256>>>(vid, p_vid_h, N_VID * DM / 4);
    transpose_round_h_kernel<<<dim3(1536 / 32, DM / 32), dim3(32, 8)>>>(w_qkv_vid, p_wqkvT_h, DM, 1536);
    transpose_round_h_kernel<<<dim3(DM / 32, DM / 32), dim3(32, 8)>>>(w_out_vid, p_woutT_h, DM, DM);

    // txt QKV (fp32), then broadcast into windows
    tf32_gemm_kernel<<<dim3(1536 / 128, 1), 256>>>(
        txt, w_qkv_txt, p_qkv_t, TXTL, 1536, DM, 1.f);

    // vid QKV projection with fused rope + window scatter
    h16_gemm_t<true><<<dim3(1536 / 128, (N_VID + 127) / 128), 256>>>(
        p_vid_h, p_wqkvT_h, (float*)nullptr, N_VID, 1536, DM);

    txt_broadcast_kernel<<<dim3(NWIN, TXTL), 256>>>();

    // attention (fp16, f16x2 exp2)
    attn3_kernel<<<dim3(7, 4, NWIN), 256, ATTN3_SMEM_BYTES>>>();

    // output projections
    h16_gemm_t<false><<<dim3(DM / 128, (N_VID + 127) / 128), 256>>>(
        p_pre_h, p_woutT_h, out, N_VID, DM, DM);
    tf32_gemm_kernel<<<dim3(DM / 128, 1), 256>>>(
        p_txt, w_out_txt, out + (long)N_VID * DM, TXTL, DM, DM, 1.f / 50.f);
}

// round 13
// speedup vs baseline: 5.5754x; 1.0060x over previous
#include <cuda_runtime.h>
#include <cuda_fp16.h>
#include <math.h>
#include <stdint.h>

#define N_VID 36000
#define DM    512
#define NWIN  50
#define WS    720
#define SEQ   784
#define TXTL  64

// ---------------- scratch (static device allocations; no cudaMalloc) ----------------
__device__ float  g_qkv_t[TXTL * 1536];         // txt QKV (fp32)
__device__ __half g_Qw_h[NWIN * SEQ * DM];      // windowed Q (rope, fp16)
__device__ __half g_Kw_h[NWIN * SEQ * DM];
__device__ __half g_Vhi_h[NWIN * SEQ * DM];     // V (fp16)
__device__ __half g_preproj_h[N_VID * DM];      // attn out, token order (fp16)
__device__ float  g_txtacc[TXTL * DM];          // txt attn out (fp32)
__device__ __half g_vid_h[N_VID * DM];          // fp16 vid
__device__ __half g_wqkvT_h[1536 * DM];         // w_qkv_vid^T [N][K] fp16
__device__ __half g_woutT_h[DM * DM];           // w_out_vid^T [N][K] fp16
__device__ float  g_invfreq[64];                // rope inverse frequencies per d-pair

__device__ __forceinline__ int token_of(int w, int p) {
    int it = w & 1;
    int ih = (w >> 1) % 5;
    int iw = w / 10;
    int tl = p / 144;
    int rem = p % 144;
    int hl = rem >> 4;
    int wl = rem & 15;
    return ((it * 5 + tl) * 45 + (ih * 9 + hl)) * 80 + (iw * 16 + wl);
}

__device__ __forceinline__ float to_tf32(float x) {
    float r;
    asm("cvt.rna.tf32.f32 %0, %1;" : "=f"(r) : "f"(x));
    return r;
}

// tf32 mma (kept for small txt GEMMs)
__device__ __forceinline__ void mma_tf32(float* c, unsigned a0, unsigned a1,
                                         unsigned a2, unsigned a3,
                                         unsigned b0, unsigned b1) {
    asm volatile(
        "mma.sync.aligned.m16n8k8.row.col.f32.tf32.tf32.f32 "
        "{%0,%1,%2,%3}, {%4,%5,%6,%7}, {%8,%9}, {%0,%1,%2,%3};"
        : "+f"(c[0]), "+f"(c[1]), "+f"(c[2]), "+f"(c[3])
        : "r"(a0), "r"(a1), "r"(a2), "r"(a3), "r"(b0), "r"(b1));
}

// fp16 mma, fp32 accum
__device__ __forceinline__ void mma_f16(float* c, const uint32_t* a,
                                        uint32_t b0, uint32_t b1) {
    asm volatile(
        "mma.sync.aligned.m16n8k16.row.col.f32.f16.f16.f32 "
        "{%0,%1,%2,%3}, {%4,%5,%6,%7}, {%8,%9}, {%0,%1,%2,%3};"
        : "+f"(c[0]), "+f"(c[1]), "+f"(c[2]), "+f"(c[3])
        : "r"(a[0]), "r"(a[1]), "r"(a[2]), "r"(a[3]), "r"(b0), "r"(b1));
}

__device__ __forceinline__ void ldsm_x4(uint32_t* r, uint32_t addr) {
    asm volatile("ldmatrix.sync.aligned.m8n8.x4.shared.b16 {%0,%1,%2,%3}, [%4];"
                 : "=r"(r[0]), "=r"(r[1]), "=r"(r[2]), "=r"(r[3]) : "r"(addr));
}
__device__ __forceinline__ void ldsm_x4_t(uint32_t* r, uint32_t addr) {
    asm volatile("ldmatrix.sync.aligned.m8n8.x4.trans.shared.b16 {%0,%1,%2,%3}, [%4];"
                 : "=r"(r[0]), "=r"(r[1]), "=r"(r[2]), "=r"(r[3]) : "r"(addr));
}

// packed fp16x2 exp2 via MUFU
__device__ __forceinline__ uint32_t h2exp2_u(uint32_t x) {
    uint32_t r;
    asm("ex2.approx.f16x2 %0, %1;" : "=r"(r) : "r"(x));
    return r;
}

__device__ __forceinline__ uint32_t smem_u32(const void* p) {
    return (uint32_t)__cvta_generic_to_shared(p);
}

// cp.async helpers (16B; invalid -> zero-fill)
__device__ __forceinline__ void cp_async16(void* smem_dst, const void* gsrc, bool valid) {
    unsigned saddr = (unsigned)__cvta_generic_to_shared(smem_dst);
    int sz = valid ? 16 : 0;
    asm volatile("cp.async.cg.shared.global [%0], [%1], 16, %2;\n"
                 :: "r"(saddr), "l"(gsrc), "r"(sz));
}
__device__ __forceinline__ void cp_commit() {
    asm volatile("cp.async.commit_group;\n" ::);
}
template <int N>
__device__ __forceinline__ void cp_wait() {
    asm volatile("cp.async.wait_group %0;\n" :: "n"(N));
}

// ---------------- rope inverse-frequency table ----------------
__global__ void init_invfreq_kernel() {
    int i = threadIdx.x;   // 64
    int d0 = 2 * i;
    int dl, da;
    if (d0 < 32)      { dl = d0;      da = 32; }
    else if (d0 < 80) { dl = d0 - 32; da = 48; }
    else              { dl = d0 - 80; da = 48; }
    g_invfreq[i] = powf(10000.0f, -((float)dl) / (float)da);
}

// ---------------- round fp32 -> fp16, elementwise ----------------
__global__ void round_half_kernel(const float* __restrict__ src, __half* __restrict__ dst, int n4) {
    int i = blockIdx.x * 256 + threadIdx.x;
    if (i < n4) {
        float4 v = reinterpret_cast<const float4*>(src)[i];
        reinterpret_cast<__half2*>(dst)[2 * i]     = __floats2half2_rn(v.x, v.y);
        reinterpret_cast<__half2*>(dst)[2 * i + 1] = __floats2half2_rn(v.z, v.w);
    }
}

// ---------------- transpose + round weights: w[K][N] fp32 -> wt[N][K] fp16 ----------------
__global__ void transpose_round_h_kernel(const float* __restrict__ w, __half* __restrict__ wt,
                                         int K, int N) {
    __shared__ float t[32][33];
    int nb = blockIdx.x * 32, kb = blockIdx.y * 32;
    int tx = threadIdx.x, ty = threadIdx.y;   // 32 x 8
#pragma unroll
    for (int j = 0; j < 4; ++j)
        t[ty + j * 8][tx] = w[(long)(kb + ty + j * 8) * N + nb + tx];
    __syncthreads();
#pragma unroll
    for (int j = 0; j < 4; ++j)
        wt[(long)(nb + ty + j * 8) * K + kb + tx] = __float2half_rn(t[tx][ty + j * 8]);
}

// ============= fp16 tensor-core GEMM: C[M,N] = A[M,K] @ Bt[N,K]^T =============
// 128x128 CTA tile, BK=32, 256 threads, 8 warps 64x32, m16n8k16, ldmatrix, cp.async 2-stage.
// Epilogue stages C tile through fp32 smem (overlaying pipeline bufs) for coalesced writes.
// FUSED=true: QKV projection — write pass applies 3D RoPE + window scatter (256B runs).
#define GH_STRIDE 40   // halves per row (32 + 8 pad)
#define CS_STRIDE 132
#define GEMM_SMEM_BYTES (128 * CS_STRIDE * 4)   // 67584 (pipeline bufs use first 40960)

template <bool FUSED>
__global__ void __launch_bounds__(256) h16_gemm_t(
    const __half* __restrict__ A, const __half* __restrict__ Bt, float* __restrict__ C,
    int M, int N, int K)
{
    extern __shared__ char smraw[];
    __half* smh = (__half*)smraw;                 // sA: 2 bufs x 5120 halves; sB follows
    float*  cs  = (float*)smraw;                  // 128 x 132 fp32 staging (reuses all)

    const int tid  = threadIdx.x;
    const int warp = tid >> 5, lane = tid & 31;
    const int g = lane >> 2, tig = lane & 3;
    const int lr = lane & 15, lk = (lane >> 4) * 8;
    const int wm = (warp & 1) * 64;
    const int wn = (warp >> 1) * 32;
    const int rowBase = blockIdx.y * 128;
    const int colBase = blockIdx.x * 128;
    const int nIter = K / 32;

    float c[4][4][4];
#pragma unroll
    for (int mt = 0; mt < 4; ++mt)
#pragma unroll
        for (int nt = 0; nt < 4; ++nt)
#pragma unroll
            for (int i = 0; i < 4; ++i) c[mt][nt][i] = 0.f;

#pragma unroll
    for (int i = 0; i < 2; ++i) {
        int idx = tid + i * 256;
        int r = idx >> 2, o = idx & 3;
        int grow = rowBase + r;
        cp_async16(&smh[r * GH_STRIDE + o * 8], &A[(long)grow * K + o * 8], grow < M);
        cp_async16(&smh[10240 + r * GH_STRIDE + o * 8], &Bt[(long)(colBase + r) * K + o * 8], true);
    }
    cp_commit();

    for (int it = 0; it < nIter; ++it) {
        int b = it & 1;
        if (it + 1 < nIter) {
            int k0 = (it + 1) * 32;
            int bn = (it + 1) & 1;
#pragma unroll
            for (int i = 0; i < 2; ++i) {
                int idx = tid + i * 256;
                int r = idx >> 2, o = idx & 3;
                int grow = rowBase + r;
                cp_async16(&smh[bn * 5120 + r * GH_STRIDE + o * 8],
                           &A[(long)grow * K + k0 + o * 8], grow < M);
                cp_async16(&smh[10240 + bn * 5120 + r * GH_STRIDE + o * 8],
                           &Bt[(long)(colBase + r) * K + k0 + o * 8], true);
            }
            cp_commit();
            cp_wait<1>();
        } else {
            cp_wait<0>();
        }
        __syncthreads();

        uint32_t aBase = smem_u32(smh) + (b * 5120 + (wm + lr) * GH_STRIDE + lk) * 2;
        uint32_t bBase = smem_u32(smh) + (10240 + b * 5120 + (wn + lr) * GH_STRIDE + lk) * 2;
#pragma unroll
        for (int s = 0; s < 2; ++s) {
            uint32_t af[4][4];
#pragma unroll
            for (int mt = 0; mt < 4; ++mt)
                ldsm_x4(af[mt], aBase + mt * (16 * GH_STRIDE * 2) + s * 32);
#pragma unroll
            for (int np = 0; np < 2; ++np) {
                uint32_t bf[4];
                ldsm_x4(bf, bBase + np * (16 * GH_STRIDE * 2) + s * 32);
#pragma unroll
                for (int mt = 0; mt < 4; ++mt) {
                    mma_f16(c[mt][np * 2],     af[mt], bf[0], bf[2]);
                    mma_f16(c[mt][np * 2 + 1], af[mt], bf[1], bf[3]);
                }
            }
        }
        __syncthreads();
    }

    // stage C tile to fp32 smem (pipeline bufs are dead; last loop ended with sync)
#pragma unroll
    for (int mt = 0; mt < 4; ++mt)
#pragma unroll
        for (int nt = 0; nt < 4; ++nt) {
            int col = wn + nt * 8 + 2 * tig;
            int r0 = wm + mt * 16 + g;
            *reinterpret_cast<float2*>(&cs[r0 * CS_STRIDE + col]) =
                make_float2(c[mt][nt][0], c[mt][nt][1]);
            *reinterpret_cast<float2*>(&cs[(r0 + 8) * CS_STRIDE + col]) =
                make_float2(c[mt][nt][2], c[mt][nt][3]);
        }
    __syncthreads();

    // coalesced write pass: 16 threads/row x 8 cols, 16 rows/iter
    const int wr = tid >> 4;             // 0..15 row-in-group
    const int c8 = (tid & 15) * 8;       // col chunk
    if (!FUSED) {
#pragma unroll
        for (int j = 0; j < 8; ++j) {
            int r = wr + j * 16;
            int row = rowBase + r;
            if (row >= M) break;
            float4 v0 = *reinterpret_cast<float4*>(&cs[r * CS_STRIDE + c8]);
            float4 v1 = *reinterpret_cast<float4*>(&cs[r * CS_STRIDE + c8 + 4]);
            float4* dst = reinterpret_cast<float4*>(&C[(long)row * N + colBase + c8]);
            dst[0] = v0; dst[1] = v1;
        }
    } else {
        const int section = blockIdx.x >> 2;   // 0=Q,1=K,2=V
        const int head = blockIdx.x & 3;
        float f0 = g_invfreq[(c8 >> 1) + 0], f1 = g_invfreq[(c8 >> 1) + 1];
        float f2 = g_invfreq[(c8 >> 1) + 2], f3 = g_invfreq[(c8 >> 1) + 3];
#pragma unroll
        for (int j = 0; j < 8; ++j) {
            int r = wr + j * 16;
            int token = rowBase + r;
            if (token >= M) break;
            int t = token / 3600, rem = token % 3600;
            int hh = rem / 80, ww2 = rem % 80;
            int it2 = t / 5, tl = t % 5;
            int ih = hh / 9, hl = hh % 9;
            int iw = ww2 >> 4, wl = ww2 & 15;
            int wwin = iw * 10 + ih * 2 + it2;
            int p = tl * 144 + hl * 16 + wl;
            long ob = ((long)(wwin * SEQ + p) * 4 + head) * 128 + c8;
            float4 v0 = *reinterpret_cast<float4*>(&cs[r * CS_STRIDE + c8]);
            float4 v1 = *reinterpret_cast<float4*>(&cs[r * CS_STRIDE + c8 + 4]);
            __half2 o[4];
            if (section == 2) {
                o[0] = __floats2half2_rn(v0.x, v0.y);
                o[1] = __floats2half2_rn(v0.z, v0.w);
                o[2] = __floats2half2_rn(v1.x, v1.y);
                o[3] = __floats2half2_rn(v1.z, v1.w);
                *reinterpret_cast<uint2*>(&g_Vhi_h[ob]) = *reinterpret_cast<uint2*>(&o[0]);
                *reinterpret_cast<uint2*>(&g_Vhi_h[ob + 4]) = *reinterpret_cast<uint2*>(&o[2]);
            } else {
                float pos;
                if (c8 < 32)      pos = (float)t;
                else if (c8 < 80) pos = (float)hh;
                else              pos = (float)ww2;
                float s0 = __sinf(pos * f0), c0 = __cosf(pos * f0);
                float s1 = __sinf(pos * f1), c1 = __cosf(pos * f1);
                float s2 = __sinf(pos * f2), c2 = __cosf(pos * f2);
                float s3 = __sinf(pos * f3), c3 = __cosf(pos * f3);
                o[0] = __floats2half2_rn(v0.x * c0 - v0.y * s0, v0.y * c0 + v0.x * s0);
                o[1] = __floats2half2_rn(v0.z * c1 - v0.w * s1, v0.w * c1 + v0.z * s1);
                o[2] = __floats2half2_rn(v1.x * c2 - v1.y * s2, v1.y * c2 + v1.x * s2);
                o[3] = __floats2half2_rn(v1.z * c3 - v1.w * s3, v1.w * c3 + v1.z * s3);
                __half* base = (section == 0) ? g_Qw_h : g_Kw_h;
                *reinterpret_cast<uint2*>(&base[ob]) = *reinterpret_cast<uint2*>(&o[0]);
                *reinterpret_cast<uint2*>(&base[ob + 4]) = *reinterpret_cast<uint2*>(&o[2]);
            }
        }
    }
}

// ---------------- old tf32 GEMM — small txt GEMMs only ----------------
#define SA_STRIDE 36
#define SB_STRIDE 136
__global__ void __launch_bounds__(256) tf32_gemm_kernel(
    const float* __restrict__ A, const float* __restrict__ B, float* __restrict__ C,
    int M, int N, int K, float alpha)
{
    __shared__ float sA[128 * SA_STRIDE];
    __shared__ float sB[32 * SB_STRIDE];

    const int tid  = threadIdx.x;
    const int warp = tid >> 5, lane = tid & 31;
    const int g = lane >> 2, tig = lane & 3;
    const int wm = (warp & 1) * 64;
    const int wn = (warp >> 1) * 32;
    const int rowBase = blockIdx.y * 128;
    const int colBase = blockIdx.x * 128;

    float c[4][4][4];
#pragma unroll
    for (int mt = 0; mt < 4; ++mt)
#pragma unroll
        for (int nt = 0; nt < 4; ++nt)
#pragma unroll
            for (int i = 0; i < 4; ++i) c[mt][nt][i] = 0.f;

    float4 pa[4], pb[4];
#pragma unroll
    for (int i = 0; i < 4; ++i) {
        int idx = tid + i * 256;
        int r = idx >> 3, c4 = idx & 7;
        int grow = rowBase + r;
        pa[i] = (grow < M) ? *reinterpret_cast<const float4*>(&A[(long)grow * K + c4 * 4])
                           : make_float4(0.f, 0.f, 0.f, 0.f);
        int rb = idx >> 5, cb4 = idx & 31;
        pb[i] = *reinterpret_cast<const float4*>(&B[(long)rb * N + colBase + cb4 * 4]);
    }

    const int nIter = K / 32;
    for (int it = 0; it < nIter; ++it) {
#pragma unroll
        for (int i = 0; i < 4; ++i) {
            int idx = tid + i * 256;
            int r = idx >> 3, c4 = idx & 7;
            float* d = &sA[r * SA_STRIDE + c4 * 4];
            d[0] = to_tf32(pa[i].x); d[1] = to_tf32(pa[i].y);
            d[2] = to_tf32(pa[i].z); d[3] = to_tf32(pa[i].w);
            int rb = idx >> 5, cb4 = idx & 31;
            float* db = &sB[rb * SB_STRIDE + cb4 * 4];
            db[0] = to_tf32(pb[i].x); db[1] = to_tf32(pb[i].y);
            db[2] = to_tf32(pb[i].z); db[3] = to_tf32(pb[i].w);
        }
        __syncthreads();

        if (it + 1 < nIter) {
            int k0 = (it + 1) * 32;
#pragma unroll
            for (int i = 0; i < 4; ++i) {
                int idx = tid + i * 256;
                int r = idx >> 3, c4 = idx & 7;
                int grow = rowBase + r;
                pa[i] = (grow < M) ? *reinterpret_cast<const float4*>(&A[(long)grow * K + k0 + c4 * 4])
                                   : make_float4(0.f, 0.f, 0.f, 0.f);
                int rb = idx >> 5, cb4 = idx & 31;
                pb[i] = *reinterpret_cast<const float4*>(&B[(long)(k0 + rb) * N + colBase + cb4 * 4]);
            }
        }

#pragma unroll
        for (int kk = 0; kk < 4; ++kk) {
            unsigned int af[4][4], bf[4][2];
#pragma unroll
            for (int mt = 0; mt < 4; ++mt) {
                int r0 = wm + mt * 16 + g;
                af[mt][0] = __float_as_uint(sA[r0 * SA_STRIDE + kk * 8 + tig]);
                af[mt][1] = __float_as_uint(sA[(r0 + 8) * SA_STRIDE + kk * 8 + tig]);
                af[mt][2] = __float_as_uint(sA[r0 * SA_STRIDE + kk * 8 + tig + 4]);
                af[mt][3] = __float_as_uint(sA[(r0 + 8) * SA_STRIDE + kk * 8 + tig + 4]);
            }
#pragma unroll
            for (int nt = 0; nt < 4; ++nt) {
                int cn = wn + nt * 8 + g;
                bf[nt][0] = __float_as_uint(sB[(kk * 8 + tig) * SB_STRIDE + cn]);
                bf[nt][1] = __float_as_uint(sB[(kk * 8 + tig + 4) * SB_STRIDE + cn]);
            }
#pragma unroll
            for (int mt = 0; mt < 4; ++mt)
#pragma unroll
                for (int nt = 0; nt < 4; ++nt)
                    mma_tf32(c[mt][nt], af[mt][0], af[mt][1], af[mt][2], af[mt][3],
                             bf[nt][0], bf[nt][1]);
        }
        __syncthreads();
    }

#pragma unroll
    for (int mt = 0; mt < 4; ++mt) {
#pragma unroll
        for (int nt = 0; nt < 4; ++nt) {
            int row0 = rowBase + wm + mt * 16 + g;
            int col = colBase + wn + nt * 8 + 2 * tig;
            if (row0 < M) {
                float2 o = make_float2(c[mt][nt][0] * alpha, c[mt][nt][1] * alpha);
                *reinterpret_cast<float2*>(&C[(long)row0 * N + col]) = o;
            }
            int row1 = row0 + 8;
            if (row1 < M) {
                float2 o = make_float2(c[mt][nt][2] * alpha, c[mt][nt][3] * alpha);
                *reinterpret_cast<float2*>(&C[(long)row1 * N + col]) = o;
            }
        }
    }
}

// ---------------- zero the txt accumulator ----------------
__global__ void zero_txt_kernel() {
    int i = blockIdx.x * 256 + threadIdx.x;
    if (i < TXTL * DM) g_txtacc[i] = 0.f;
}

// ---------------- broadcast txt qkv rows into all windows (no rope) ----------------
__global__ void __launch_bounds__(256) txt_broadcast_kernel() {
    int w = blockIdx.x, tr = blockIdx.y;
    int tid = threadIdx.x;
    int h = tid >> 6, pr = tid & 63;
    int d0 = pr * 2;
    const float* base = &g_qkv_t[(long)tr * 1536 + h * 128];
    float q0 = base[d0],        q1 = base[d0 + 1];
    float k0 = base[512 + d0],  k1 = base[512 + d0 + 1];
    float v0 = base[1024 + d0], v1 = base[1024 + d0 + 1];
    long ob = ((long)(w * SEQ + WS + tr) * 4 + h) * 128 + d0;
    *reinterpret_cast<__half2*>(&g_Qw_h[ob])  = __floats2half2_rn(q0, q1);
    *reinterpret_cast<__half2*>(&g_Kw_h[ob])  = __floats2half2_rn(k0, k1);
    *reinterpret_cast<__half2*>(&g_Vhi_h[ob]) = __floats2half2_rn(v0, v1);
}

// ---------------- fp16 flash attention: QT=128, KT=64, f16x2 exp2, l-via-MMA ----------------
#define QT2   128
#define KT2   64
#define PADDH 136   // halves stride for Q/K/V rows (128+8); 272B
#define PSTR  72    // halves stride for P rows (64+8); 144B
#define NKT   13
#define SMEM_K0   17408
#define SMEM_KBUF 9216
#define SMEM_V    35840
#define ATTN3_SMEM_BYTES 90112

__global__ void __launch_bounds__(256) attn3_kernel() {
    extern __shared__ char smraw[];
    __half* sh = (__half*)smraw;
    float* sPart = (float*)(smraw + 89088);
    const uint32_t sbase = smem_u32(sh);

    const float NEGINF = __int_as_float(0xff800000);
    const float scale = 0.08838834764831843f;              // 1/sqrt(128)
    const float SL = 0.12751089f;                          // scale * log2(e)
    const uint32_t ONES2 = 0x3C003C00u;                    // half2(1.0, 1.0)

    int qt = blockIdx.x, h = blockIdx.y, w = blockIdx.z;
    int tid = threadIdx.x;
    const int warp = tid >> 5, lane = tid & 31;
    const int g = lane >> 2, tig = lane & 3;
    const int lr = lane & 15, lk = (lane >> 4) * 8;
    const int wm = (warp & 3) * 32;
    const int ng = warp >> 2;
    const int wn1 = ng * 32;
    const int wn2 = ng * 64;

    const long gbase = ((long)(w * SEQ) * 4 + h) * 128;
    const int qrow0 = qt * QT2;

    // prologue: Q + K0, one commit group
#pragma unroll
    for (int i = 0; i < 8; ++i) {
        int idx = tid + i * 256;
        int r = idx >> 4, o = idx & 15;
        cp_async16(&sh[r * PADDH + o * 8],
                   &g_Qw_h[gbase + (long)(qrow0 + r) * 512 + o * 8], qrow0 + r < SEQ);
    }
#pragma unroll
    for (int i = 0; i < 4; ++i) {
        int idx = tid + i * 256;
        int r = idx >> 4, o = idx & 15;
        cp_async16(&sh[SMEM_K0 + r * PADDH + o * 8],
                   &g_Kw_h[gbase + (long)r * 512 + o * 8], r < SEQ);
    }
    cp_commit();

    float oacc[2][8][4];
#pragma unroll
    for (int mt = 0; mt < 2; ++mt)
#pragma unroll
        for (int nf = 0; nf < 8; ++nf)
#pragma unroll
            for (int i = 0; i < 4; ++i) oacc[mt][nf][i] = 0.f;

    float lex[2][4];
#pragma unroll
    for (int mt = 0; mt < 2; ++mt)
#pragma unroll
        for (int i = 0; i < 4; ++i) lex[mt][i] = 0.f;

    float mOld[2][2];
#pragma unroll
    for (int mt = 0; mt < 2; ++mt)
#pragma unroll
        for (int hf = 0; hf < 2; ++hf) mOld[mt][hf] = NEGINF;

    for (int kt = 0; kt < NKT; ++kt) {
        const int b = kt & 1;
        __half* sKb = sh + SMEM_K0 + b * SMEM_KBUF;
        __half* sP  = sKb;

        __syncthreads();

        {
            int kb = kt * KT2;
#pragma unroll
            for (int i = 0; i < 4; ++i) {
                int idx = tid + i * 256;
                int r = idx >> 4, o = idx & 15;
                cp_async16(&sh[SMEM_V + r * PADDH + o * 8],
                           &g_Vhi_h[gbase + (long)(kb + r) * 512 + o * 8], kb + r < SEQ);
            }
            cp_commit();
        }
        if (kt + 1 < NKT) {
            int kb = (kt + 1) * KT2;
            __half* sKn = sh + SMEM_K0 + ((kt + 1) & 1) * SMEM_KBUF;
#pragma unroll
            for (int i = 0; i < 4; ++i) {
                int idx = tid + i * 256;
                int r = idx >> 4, o = idx & 15;
                cp_async16(&sKn[r * PADDH + o * 8],
                           &g_Kw_h[gbase + (long)(kb + r) * 512 + o * 8], kb + r < SEQ);
            }
            cp_commit();
            cp_wait<2>();
        } else {
            cp_wait<1>();
        }
        __syncthreads();

        // ---- phase 1: S = Q @ K^T ----
        float sacc[2][4][4];
#pragma unroll
        for (int mt = 0; mt < 2; ++mt)
#pragma unroll
            for (int nf = 0; nf < 4; ++nf)
#pragma unroll
                for (int i = 0; i < 4; ++i) sacc[mt][nf][i] = 0.f;

        {
            uint32_t qa0 = sbase + ((wm + lr) * PADDH + lk) * 2;
            uint32_t ka0 = smem_u32(sKb) + ((wn1 + lr) * PADDH + lk) * 2;
#pragma unroll
            for (int kk = 0; kk < 8; ++kk) {
                uint32_t aQ[2][4];
#pragma unroll
                for (int mt = 0; mt < 2; ++mt)
                    ldsm_x4(aQ[mt], qa0 + mt * (16 * PADDH * 2) + kk * 32);
#pragma unroll
                for (int np = 0; np < 2; ++np) {
                    uint32_t bK[4];
                    ldsm_x4(bK, ka0 + np * (16 * PADDH * 2) + kk * 32);
#pragma unroll
                    for (int mt = 0; mt < 2; ++mt) {
                        mma_f16(sacc[mt][np * 2],     aQ[mt], bK[0], bK[2]);
                        mma_f16(sacc[mt][np * 2 + 1], aQ[mt], bK[1], bK[3]);
                    }
                }
            }
        }

        // ---- mask + partial row max ----
        bool cval[4][2];
#pragma unroll
        for (int nf = 0; nf < 4; ++nf) {
            int c0 = kt * KT2 + wn1 + nf * 8 + 2 * tig;
            cval[nf][0] = (c0 < SEQ);
            cval[nf][1] = (c0 + 1 < SEQ);
        }
        float mp[2][2];
#pragma unroll
        for (int mt = 0; mt < 2; ++mt)
#pragma unroll
            for (int hf = 0; hf < 2; ++hf) {
                float m = NEGINF;
#pragma unroll
                for (int nf = 0; nf < 4; ++nf)
#pragma unroll
                    for (int pr = 0; pr < 2; ++pr) {
                        float s = cval[nf][pr] ? sacc[mt][nf][hf * 2 + pr] : NEGINF;
                        sacc[mt][nf][hf * 2 + pr] = s;
                        m = fmaxf(m, s);
                    }
                m = fmaxf(m, __shfl_xor_sync(0xffffffffu, m, 1));
                m = fmaxf(m, __shfl_xor_sync(0xffffffffu, m, 2));
                mp[mt][hf] = m;
            }
        if (tig == 0) {
#pragma unroll
            for (int mt = 0; mt < 2; ++mt)
#pragma unroll
                for (int hf = 0; hf < 2; ++hf)
                    sPart[(wm + mt * 16 + g + hf * 8) * 2 + ng] = mp[mt][hf];
        }
        __syncthreads();

        // ---- exp2.f16x2 + P(half) write ----
        float aF[2][2];
#pragma unroll
        for (int mt = 0; mt < 2; ++mt)
#pragma unroll
            for (int hf = 0; hf < 2; ++hf) {
                int row = wm + mt * 16 + g + hf * 8;
                float mn = fmaxf(mOld[mt][hf], fmaxf(sPart[row * 2], sPart[row * 2 + 1]));
                aF[mt][hf] = __expf((mOld[mt][hf] - mn) * scale);
                mOld[mt][hf] = mn;
            }
#pragma unroll
        for (int mt = 0; mt < 2; ++mt)
#pragma unroll
            for (int hf = 0; hf < 2; ++hf) {
                int row = wm + mt * 16 + g + hf * 8;
                float mnSL = mOld[mt][hf] * SL;
#pragma unroll
                for (int nf = 0; nf < 4; ++nf) {
                    float a0 = fmaf(sacc[mt][nf][hf * 2],     SL, -mnSL);
                    float a1 = fmaf(sacc[mt][nf][hf * 2 + 1], SL, -mnSL);
                    __half2 ha = __floats2half2_rn(a0, a1);
                    uint32_t p2 = h2exp2_u(*reinterpret_cast<uint32_t*>(&ha));
                    int col = wn1 + nf * 8 + 2 * tig;
                    *reinterpret_cast<uint32_t*>(&sP[row * PSTR + col]) = p2;
                }
            }
        if (kt + 1 < NKT) cp_wait<1>(); else cp_wait<0>();
        __syncthreads();

        // ---- rescale O and l ----
#pragma unroll
        for (int mt = 0; mt < 2; ++mt) {
#pragma unroll
            for (int nf = 0; nf < 8; ++nf) {
                oacc[mt][nf][0] *= aF[mt][0]; oacc[mt][nf][1] *= aF[mt][0];
                oacc[mt][nf][2] *= aF[mt][1]; oacc[mt][nf][3] *= aF[mt][1];
            }
            lex[mt][0] *= aF[mt][0]; lex[mt][1] *= aF[mt][0];
            lex[mt][2] *= aF[mt][1]; lex[mt][3] *= aF[mt][1];
        }

        // ---- phase 2: O += P @ V (+ l += P @ ones) ----
        {
            uint32_t pa0 = smem_u32(sP) + ((wm + lr) * PSTR + lk) * 2;
            int vkr = ((lane >> 3) & 1) * 8 + (lane & 7);
            int vnc = (lane >> 4) * 8;
            uint32_t va0 = sbase + (SMEM_V + vkr * PADDH + wn2 + vnc) * 2;
#pragma unroll
            for (int kk2 = 0; kk2 < 4; ++kk2) {
                uint32_t aP[2][4];
#pragma unroll
                for (int mt = 0; mt < 2; ++mt) {
                    ldsm_x4(aP[mt], pa0 + mt * (16 * PSTR * 2) + kk2 * 32);
                    mma_f16(lex[mt], aP[mt], ONES2, ONES2);
                }
#pragma unroll
                for (int ng2 = 0; ng2 < 4; ++ng2) {
                    uint32_t bh[4];
                    ldsm_x4_t(bh, va0 + kk2 * (16 * PADDH * 2) + ng2 * 32);
#pragma unroll
                    for (int mt = 0; mt < 2; ++mt) {
                        mma_f16(oacc[mt][ng2 * 2],     aP[mt], bh[0], bh[1]);
                        mma_f16(oacc[mt][ng2 * 2 + 1], aP[mt], bh[2], bh[3]);
                    }
                }
            }
        }
    }

    // epilogue: txt rows via atomics; vid rows staged into sQ (dead) for coalesced scatter
#pragma unroll
    for (int mt = 0; mt < 2; ++mt)
#pragma unroll
        for (int hf = 0; hf < 2; ++hf) {
            int ql = wm + mt * 16 + g + hf * 8;
            int qg = qrow0 + ql;
            if (qg >= SEQ) continue;
            float inv = 1.f / lex[mt][hf * 2];
            if (qg >= WS) {
                int tr = qg - WS;
                float* dst = &g_txtacc[(long)tr * DM + h * 128];
#pragma unroll
                for (int nf = 0; nf < 8; ++nf) {
                    int col = wn2 + nf * 8 + 2 * tig;
                    atomicAdd(&dst[col],     oacc[mt][nf][hf * 2] * inv);
                    atomicAdd(&dst[col + 1], oacc[mt][nf][hf * 2 + 1] * inv);
                }
            } else {
#pragma unroll
                for (int nf = 0; nf < 8; ++nf) {
                    int col = wn2 + nf * 8 + 2 * tig;
                    *reinterpret_cast<__half2*>(&sh[ql * PADDH + col]) =
                        __floats2half2_rn(oacc[mt][nf][hf * 2] * inv,
                                          oacc[mt][nf][hf * 2 + 1] * inv);
                }
            }
        }
    __syncthreads();

    // coalesced scatter: 16 threads/row x 16B (uint4 = 8 halves), vid rows only
    {
        int wr = tid >> 4, c8 = (tid & 15) * 8;
#pragma unroll
        for (int j = 0; j < 8; ++j) {
            int ql = wr + j * 16;
            int qg = qrow0 + ql;
            if (qg >= WS) break;
            int token = token_of(w, qg);
            uint4 v = *reinterpret_cast<uint4*>(&sh[ql * PADDH + c8]);
            *reinterpret_cast<uint4*>(&g_preproj_h[(long)token * DM + h * 128 + c8]) = v;
        }
    }
}

// ---------------- launch ----------------
extern "C" void kernel_launch(void* const* d_in, const int* in_sizes, int n_in,
                              void* d_out, int out_size) {
    const float* vid       = (const float*)d_in[0];
    const float* txt       = (const float*)d_in[1];
    const float* w_qkv_vid = (const float*)d_in[2];
    const float* w_qkv_txt = (const float*)d_in[3];
    const float* w_out_vid = (const float*)d_in[4];
    const float* w_out_txt = (const float*)d_in[5];
    float* out = (float*)d_out;

    cudaFuncSetAttribute(attn3_kernel, cudaFuncAttributeMaxDynamicSharedMemorySize,
                         ATTN3_SMEM_BYTES);
    cudaFuncSetAttribute(h16_gemm_t<true>, cudaFuncAttributeMaxDynamicSharedMemorySize,
                         GEMM_SMEM_BYTES);
    cudaFuncSetAttribute(h16_gemm_t<false>, cudaFuncAttributeMaxDynamicSharedMemorySize,
                         GEMM_SMEM_BYTES);

    float *p_qkv_t, *p_txt;
    __half *p_pre_h, *p_vid_h, *p_wqkvT_h, *p_woutT_h;
    cudaGetSymbolAddress((void**)&p_qkv_t,   g_qkv_t);
    cudaGetSymbolAddress((void**)&p_txt,     g_txtacc);
    cudaGetSymbolAddress((void**)&p_pre_h,   g_preproj_h);
    cudaGetSymbolAddress((void**)&p_vid_h,   g_vid_h);
    cudaGetSymbolAddress((void**)&p_wqkvT_h, g_wqkvT_h);
    cudaGetSymbolAddress((void**)&p_woutT_h, g_woutT_h);

    zero_txt_kernel<<<(TXTL * DM + 255) / 256, 256>>>();
    init_invfreq_kernel<<<1, 64>>>();

    // fp16 conversions
    round_half_kernel<<<(N_VID * DM / 4 + 255) / 256, 256>>>(vid, p_vid_h, N_VID * DM / 4);
    transpose_round_h_kernel<<<dim3(1536 / 32, DM / 32), dim3(32, 8)>>>(w_qkv_vid, p_wqkvT_h, DM, 1536);
    transpose_round_h_kernel<<<dim3(DM / 32, DM / 32), dim3(32, 8)>>>(w_out_vid, p_woutT_h, DM, DM);

    // txt QKV (fp32), then broadcast into windows
    tf32_gemm_kernel<<<dim3(1536 / 128, 1), 256>>>(
        txt, w_qkv_txt, p_qkv_t, TXTL, 1536, DM, 1.f);

    // vid QKV projection with fused rope + window scatter (coalesced)
    h16_gemm_t<true><<<dim3(1536 / 128, (N_VID + 127) / 128), 256, GEMM_SMEM_BYTES>>>(
        p_vid_h, p_wqkvT_h, (float*)nullptr, N_VID, 1536, DM);

    txt_broadcast_kernel<<<dim3(NWIN, TXTL), 256>>>();

    // attention (fp16)
    attn3_kernel<<<dim3(7, 4, NWIN), 256, ATTN3_SMEM_BYTES>>>();

    // output projections
    h16_gemm_t<false><<<dim3(DM / 128, (N_VID + 127) / 128), 256, GEMM_SMEM_BYTES>>>(
        p_pre_h, p_woutT_h, out, N_VID, DM, DM);
    tf32_gemm_kernel<<<dim3(DM / 128, 1), 256>>>(
        p_txt, w_out_txt, out + (long)N_VID * DM, TXTL, DM, DM, 1.f / 50.f);
}